// round 1
// baseline (speedup 1.0000x reference)
#include <cuda_runtime.h>
#include <math.h>

// Problem constants
#define BSZ   2
#define SEQ   2048
#define DIM   2048
#define NH    16
#define DRr   64
#define DNn   64
#define DQK   128
#define DVv   128
#define QLR   1536
#define KVLR  1024
#define ROWS  (BSZ*SEQ)          // 4096
#define KVAW  (KVLR + DRr)       // 1088
#define KV2W  (NH*(DNn+DVv))     // 3072
#define QW    (NH*DQK)           // 2048
#define OW    (NH*DVv)           // 2048

// -------- scratch (static device globals; no runtime allocation) --------
__device__ float g_qa  [ (size_t)ROWS * QLR  ];  // x@wq_a.T, then rmsnorm in place
__device__ float g_q   [ (size_t)ROWS * QW   ];  // q (rope applied in place)
__device__ float g_kv  [ (size_t)ROWS * KVAW ];  // x@wkv_a.T
__device__ float g_ckvn[ (size_t)ROWS * KVLR ];  // rmsnorm(c_kv)
__device__ float g_kv2 [ (size_t)ROWS * KV2W ];  // ckvn@wkv_b.T  (k_nope | v per head)
__device__ float g_k   [ (size_t)ROWS * QW   ];  // concat(k_nope, rope(k_pe)) per head
__device__ float g_attn[ (size_t)ROWS * OW   ];  // attention output

// ============================================================
// GEMM: C[M,N] = A[M,K] @ W[N,K]^T   (fp32, 64x64 tile, BK=32)
// ============================================================
__global__ void gemm_tn(const float* __restrict__ A, const float* __restrict__ W,
                        float* __restrict__ C, int M, int N, int K)
{
    __shared__ float As[64][33];
    __shared__ float Ws[64][33];

    const int n0 = blockIdx.x * 64;
    const int m0 = blockIdx.y * 64;
    const int tid = threadIdx.x;          // 256
    const int ty = tid >> 4, tx = tid & 15;

    float acc[4][4];
#pragma unroll
    for (int i = 0; i < 4; i++)
#pragma unroll
        for (int j = 0; j < 4; j++) acc[i][j] = 0.f;

    for (int k0 = 0; k0 < K; k0 += 32) {
#pragma unroll
        for (int l = 0; l < 8; l++) {
            int i = tid + l * 256;
            int r = i >> 5, c = i & 31;
            As[r][c] = A[(size_t)(m0 + r) * K + k0 + c];
            Ws[r][c] = W[(size_t)(n0 + r) * K + k0 + c];
        }
        __syncthreads();
#pragma unroll
        for (int kk = 0; kk < 32; kk++) {
            float a[4], bv[4];
#pragma unroll
            for (int i = 0; i < 4; i++) a[i] = As[ty * 4 + i][kk];
#pragma unroll
            for (int j = 0; j < 4; j++) bv[j] = Ws[tx * 4 + j][kk];
#pragma unroll
            for (int i = 0; i < 4; i++)
#pragma unroll
                for (int j = 0; j < 4; j++) acc[i][j] += a[i] * bv[j];
        }
        __syncthreads();
    }
#pragma unroll
    for (int i = 0; i < 4; i++)
#pragma unroll
        for (int j = 0; j < 4; j++)
            C[(size_t)(m0 + ty * 4 + i) * N + n0 + tx * 4 + j] = acc[i][j];
}

// ============================================================
// RMSNorm: out[row] = in[row] * rsqrt(mean(in^2)+eps) * w
// ============================================================
__global__ void rmsnorm_kernel(const float* __restrict__ in, const float* __restrict__ w,
                               float* __restrict__ out, int K, int inStride, int outStride)
{
    const int row = blockIdx.x;
    const float* ip = in + (size_t)row * inStride;
    float* op = out + (size_t)row * outStride;

    float ss = 0.f;
    for (int i = threadIdx.x; i < K; i += blockDim.x) { float v = ip[i]; ss += v * v; }
#pragma unroll
    for (int o = 16; o; o >>= 1) ss += __shfl_xor_sync(0xffffffffu, ss, o);

    __shared__ float red[8];
    __shared__ float rs;
    int wid = threadIdx.x >> 5, lid = threadIdx.x & 31;
    if (lid == 0) red[wid] = ss;
    __syncthreads();
    if (threadIdx.x == 0) {
        float t = 0.f;
        for (int i = 0; i < 8; i++) t += red[i];
        rs = rsqrtf(t / (float)K + 1e-6f);
    }
    __syncthreads();
    float r = rs;
    for (int i = threadIdx.x; i < K; i += blockDim.x) op[i] = ip[i] * r * w[i];
}

// ============================================================
// RoPE on q_pe (cols 64..127 of each head), in place.
// ============================================================
__global__ void rope_q_kernel(float* __restrict__ q,
                              const float* __restrict__ fcos, const float* __restrict__ fsin)
{
    const int row = blockIdx.x;
    const int tid = threadIdx.x;        // 512 = 16 heads * 32 pairs
    const int h = tid >> 5, i = tid & 31;
    const int s = row & (SEQ - 1);
    size_t base = (size_t)row * QW + h * DQK + DNn + 2 * i;
    float x0 = q[base], x1 = q[base + 1];
    float c = fcos[s * 32 + i], sn = fsin[s * 32 + i];
    q[base]     = x0 * c - x1 * sn;
    q[base + 1] = x0 * sn + x1 * c;
}

// ============================================================
// Build K: per head, [k_nope(64) | rope(k_pe)(64, shared across heads)]
// ============================================================
__global__ void build_k_kernel(const float* __restrict__ fcos, const float* __restrict__ fsin)
{
    const int row = blockIdx.x;
    const int tid = threadIdx.x;        // 256
    __shared__ float pe[64];
    const int s = row & (SEQ - 1);
    if (tid < 32) {
        float x0 = g_kv[(size_t)row * KVAW + KVLR + 2 * tid];
        float x1 = g_kv[(size_t)row * KVAW + KVLR + 2 * tid + 1];
        float c = fcos[s * 32 + tid], sn = fsin[s * 32 + tid];
        pe[2 * tid]     = x0 * c - x1 * sn;
        pe[2 * tid + 1] = x0 * sn + x1 * c;
    }
    __syncthreads();
#pragma unroll
    for (int l = 0; l < 8; l++) {
        int i = tid + l * 256;          // 0..2047
        int h = i >> 7, d = i & 127;
        float v = (d < DNn) ? g_kv2[(size_t)row * KV2W + h * (DNn + DVv) + d] : pe[d - DNn];
        g_k[(size_t)row * QW + i] = v;
    }
}

// ============================================================
// Flash attention: BQ=64, BK=64, online softmax, causal.
// grid: (SEQ/64, NH, BSZ), block 256, dynamic smem.
// ============================================================
__global__ void flash_kernel()
{
    extern __shared__ float sm[];
    float* Qs   = sm;                    // 64 x 129
    float* Ks   = Qs + 64 * 129;         // 64 x 129
    float* Vs   = Ks + 64 * 129;         // 64 x 128
    float* Ps   = Vs + 64 * 128;         // 64 x 65
    float* mrow = Ps + 64 * 65;          // 64
    float* lrow = mrow + 64;             // 64

    const int q0 = blockIdx.x * 64;
    const int h  = blockIdx.y;
    const int b  = blockIdx.z;
    const int tid = threadIdx.x;         // 256
    const int ty = tid >> 4, tx = tid & 15;
    const int orow = tid >> 2;           // 0..63
    const int ocg  = tid & 3;            // 0..3
    const float scale = 0.088388347648318447f;  // 128^-0.5

    // load Q tile
#pragma unroll
    for (int l = 0; l < 32; l++) {
        int i = tid + l * 256;
        int r = i >> 7, c = i & 127;
        Qs[r * 129 + c] = g_q[((size_t)(b * SEQ + q0 + r)) * QW + h * DQK + c];
    }
    if (tid < 64) { mrow[tid] = -1e30f; lrow[tid] = 0.f; }

    float o[32];
#pragma unroll
    for (int j = 0; j < 32; j++) o[j] = 0.f;

    const int nkt = blockIdx.x + 1;      // causal tile limit
    for (int kt = 0; kt < nkt; kt++) {
        const int t0 = kt * 64;
        __syncthreads();   // previous consumers done (also covers Q load, init)
#pragma unroll
        for (int l = 0; l < 32; l++) {
            int i = tid + l * 256;
            int r = i >> 7, c = i & 127;
            size_t grow = (size_t)(b * SEQ + t0 + r);
            Ks[r * 129 + c] = g_k  [grow * QW   + h * DQK + c];
            Vs[r * 128 + c] = g_kv2[grow * KV2W + h * (DNn + DVv) + DNn + c];
        }
        __syncthreads();

        // scores: 4x4 register tile per thread
        float acc[4][4];
#pragma unroll
        for (int i = 0; i < 4; i++)
#pragma unroll
            for (int j = 0; j < 4; j++) acc[i][j] = 0.f;
#pragma unroll 8
        for (int kk = 0; kk < 128; kk++) {
            float a[4], bv[4];
#pragma unroll
            for (int i = 0; i < 4; i++) a[i] = Qs[(ty * 4 + i) * 129 + kk];
#pragma unroll
            for (int j = 0; j < 4; j++) bv[j] = Ks[(tx * 4 + j) * 129 + kk];
#pragma unroll
            for (int i = 0; i < 4; i++)
#pragma unroll
                for (int j = 0; j < 4; j++) acc[i][j] += a[i] * bv[j];
        }
#pragma unroll
        for (int i = 0; i < 4; i++) {
#pragma unroll
            for (int j = 0; j < 4; j++) {
                int qq = q0 + ty * 4 + i, tt = t0 + tx * 4 + j;
                float mv = (tt <= qq) ? 0.f : -1e9f;
                Ps[(ty * 4 + i) * 65 + tx * 4 + j] = acc[i][j] * scale + mv;
            }
        }
        __syncthreads();

        // online softmax: 4 threads per row, 16 cols each
        float lm = -1e30f;
        for (int c = ocg * 16; c < ocg * 16 + 16; c++) lm = fmaxf(lm, Ps[orow * 65 + c]);
        lm = fmaxf(lm, __shfl_xor_sync(0xffffffffu, lm, 1));
        lm = fmaxf(lm, __shfl_xor_sync(0xffffffffu, lm, 2));
        float mold = mrow[orow];
        float mnew = fmaxf(mold, lm);
        float alpha = __expf(mold - mnew);
        float ls = 0.f;
        for (int c = ocg * 16; c < ocg * 16 + 16; c++) {
            float p = __expf(Ps[orow * 65 + c] - mnew);
            Ps[orow * 65 + c] = p;
            ls += p;
        }
        ls += __shfl_xor_sync(0xffffffffu, ls, 1);
        ls += __shfl_xor_sync(0xffffffffu, ls, 2);
        if (ocg == 0) {
            lrow[orow] = lrow[orow] * alpha + ls;
            mrow[orow] = mnew;
        }
        __syncthreads();

        // O update: each thread owns (row=orow, cols ocg+4j)
#pragma unroll
        for (int j = 0; j < 32; j++) o[j] *= alpha;
        for (int t = 0; t < 64; t++) {
            float p = Ps[orow * 65 + t];
#pragma unroll
            for (int j = 0; j < 32; j++) o[j] += p * Vs[t * 128 + ocg + 4 * j];
        }
    }
    __syncthreads();
    float inv = 1.f / lrow[orow];
#pragma unroll
    for (int j = 0; j < 32; j++)
        g_attn[((size_t)(b * SEQ + q0 + orow)) * OW + h * DVv + ocg + 4 * j] = o[j] * inv;
}

// ============================================================
// launch
// ============================================================
extern "C" void kernel_launch(void* const* d_in, const int* in_sizes, int n_in,
                              void* d_out, int out_size)
{
    const float* x      = (const float*)d_in[0];
    const float* wq_a   = (const float*)d_in[1];
    const float* qnw    = (const float*)d_in[2];
    const float* wq_b   = (const float*)d_in[3];
    const float* wkv_a  = (const float*)d_in[4];
    const float* kvnw   = (const float*)d_in[5];
    const float* wkv_b  = (const float*)d_in[6];
    const float* wo     = (const float*)d_in[7];
    // d_in[8] mask (we reproduce the exact -1e9 causal additive analytically)
    const float* fcos   = (const float*)d_in[9];
    const float* fsin   = (const float*)d_in[10];
    // d_in[11] start_pos == 0

    float* out = (float*)d_out;

    float *p_qa, *p_q, *p_kv, *p_ckvn, *p_kv2;
    cudaGetSymbolAddress((void**)&p_qa,   g_qa);
    cudaGetSymbolAddress((void**)&p_q,    g_q);
    cudaGetSymbolAddress((void**)&p_kv,   g_kv);
    cudaGetSymbolAddress((void**)&p_ckvn, g_ckvn);
    cudaGetSymbolAddress((void**)&p_kv2,  g_kv2);
    float* p_attn;
    cudaGetSymbolAddress((void**)&p_attn, g_attn);

    const int smem_flash = (64 * 129 * 2 + 64 * 128 + 64 * 65 + 128) * sizeof(float);
    cudaFuncSetAttribute(flash_kernel, cudaFuncAttributeMaxDynamicSharedMemorySize, smem_flash);

    dim3 blk(256);

    // q path
    gemm_tn<<<dim3(QLR / 64, ROWS / 64), blk>>>(x, wq_a, p_qa, ROWS, QLR, DIM);
    rmsnorm_kernel<<<ROWS, 256>>>(p_qa, qnw, p_qa, QLR, QLR, QLR);
    gemm_tn<<<dim3(QW / 64, ROWS / 64), blk>>>(p_qa, wq_b, p_q, ROWS, QW, QLR);
    rope_q_kernel<<<ROWS, 512>>>(p_q, fcos, fsin);

    // kv path
    gemm_tn<<<dim3(KVAW / 64, ROWS / 64), blk>>>(x, wkv_a, p_kv, ROWS, KVAW, DIM);
    rmsnorm_kernel<<<ROWS, 256>>>(p_kv, kvnw, p_ckvn, KVLR, KVAW, KVLR);
    gemm_tn<<<dim3(KV2W / 64, ROWS / 64), blk>>>(p_ckvn, wkv_b, p_kv2, ROWS, KV2W, KVLR);
    build_k_kernel<<<ROWS, 256>>>(fcos, fsin);

    // attention
    flash_kernel<<<dim3(SEQ / 64, NH, BSZ), blk, smem_flash>>>();

    // output projection
    gemm_tn<<<dim3(DIM / 64, ROWS / 64), blk>>>(p_attn, wo, out, ROWS, DIM, OW);
}

// round 3
// speedup vs baseline: 1.4099x; 1.4099x over previous
#include <cuda_runtime.h>
#include <cuda_bf16.h>
#include <cstdint>
#include <math.h>

// Problem constants
#define BSZ   2
#define SEQ   2048
#define DIM   2048
#define NH    16
#define DRr   64
#define DNn   64
#define DQK   128
#define DVv   128
#define QLR   1536
#define KVLR  1024
#define ROWS  (BSZ*SEQ)          // 4096
#define KVAW  (KVLR + DRr)       // 1088
#define KV2W  (NH*(DNn+DVv))     // 3072
#define QW    (NH*DQK)           // 2048
#define OW    (NH*DVv)           // 2048

// -------- fp32 scratch --------
__device__ float g_qa  [ (size_t)ROWS * QLR  ];
__device__ float g_q   [ (size_t)ROWS * QW   ];
__device__ float g_kv  [ (size_t)ROWS * KVAW ];
__device__ float g_ckvn[ (size_t)ROWS * KVLR ];
__device__ float g_kv2 [ (size_t)ROWS * KV2W ];
__device__ float g_k   [ (size_t)ROWS * QW   ];
__device__ float g_attn[ (size_t)ROWS * OW   ];

// -------- bf16 split scratch --------
__device__ __nv_bfloat16 g_x_hi  [(size_t)ROWS*DIM],  g_x_lo  [(size_t)ROWS*DIM];
__device__ __nv_bfloat16 g_wqa_hi[(size_t)QLR*DIM],   g_wqa_lo[(size_t)QLR*DIM];
__device__ __nv_bfloat16 g_wqb_hi[(size_t)QW*QLR],    g_wqb_lo[(size_t)QW*QLR];
__device__ __nv_bfloat16 g_wkva_hi[(size_t)KVAW*DIM], g_wkva_lo[(size_t)KVAW*DIM];
__device__ __nv_bfloat16 g_wkvb_hi[(size_t)KV2W*KVLR],g_wkvb_lo[(size_t)KV2W*KVLR];
__device__ __nv_bfloat16 g_wo_hi [(size_t)DIM*OW],    g_wo_lo [(size_t)DIM*OW];
__device__ __nv_bfloat16 g_qan_hi[(size_t)ROWS*QLR],  g_qan_lo[(size_t)ROWS*QLR];
__device__ __nv_bfloat16 g_ckv_hi[(size_t)ROWS*KVLR], g_ckv_lo[(size_t)ROWS*KVLR];
__device__ __nv_bfloat16 g_at_hi [(size_t)ROWS*OW],   g_at_lo [(size_t)ROWS*OW];

// ============================================================
// helpers (sm_80-compatible instructions only — plain sm_103 target!)
// ============================================================
__device__ __forceinline__ uint32_t smem_u32(const void* p) {
    uint32_t a;
    asm("{ .reg .u64 t; cvta.to.shared.u64 t, %1; cvt.u32.u64 %0, t; }" : "=r"(a) : "l"(p));
    return a;
}

#define CP16(dst, src) \
    asm volatile("cp.async.cg.shared.global [%0], [%1], 16;" :: "r"(dst), "l"(src))
#define CP_COMMIT() asm volatile("cp.async.commit_group;" ::: "memory")
#define CP_WAIT(n)  asm volatile("cp.async.wait_group %0;" :: "n"(n) : "memory")

#define LDSM4(r0, r1, r2, r3, addr) \
    asm volatile("ldmatrix.sync.aligned.m8n8.x4.shared.b16 {%0,%1,%2,%3}, [%4];" \
        : "=r"(r0), "=r"(r1), "=r"(r2), "=r"(r3) : "r"(addr))

#define MMA_BF16(d, a, b0, b1) \
    asm volatile("mma.sync.aligned.m16n8k16.row.col.f32.bf16.bf16.f32 " \
        "{%0,%1,%2,%3},{%4,%5,%6,%7},{%8,%9},{%0,%1,%2,%3};" \
        : "+f"((d)[0]), "+f"((d)[1]), "+f"((d)[2]), "+f"((d)[3]) \
        : "r"((a)[0]), "r"((a)[1]), "r"((a)[2]), "r"((a)[3]), "r"(b0), "r"(b1))

// ============================================================
// Split fp32 -> (bf16 hi, bf16 lo)
// ============================================================
__global__ void split_kernel(const float* __restrict__ in,
                             __nv_bfloat16* __restrict__ hi,
                             __nv_bfloat16* __restrict__ lo, int n)
{
    int i = blockIdx.x * blockDim.x + threadIdx.x;
    if (i < n) {
        float v = in[i];
        __nv_bfloat16 h = __float2bfloat16(v);
        hi[i] = h;
        lo[i] = __float2bfloat16(v - __bfloat162float(h));
    }
}

// ============================================================
// Split-bf16 GEMM via mma.sync: C[M,N] = A[M,K] @ W[N,K]^T
// 128x128x32 tiles, cp.async double buffer, 8 warps (4m x 2n),
// warp tile 32x64. Row stride 80B => conflict-free ldmatrix.
// ============================================================
#define GBM 128
#define GBN 128
#define GBK 32
#define ROWB 80                       // bytes per smem row (32 bf16 data + pad)
#define MAT_BYTES (128 * ROWB)        // 10240
#define STAGE_BYTES (4 * MAT_BYTES)   // 40960
#define OFF_AHI 0
#define OFF_ALO (1 * MAT_BYTES)
#define OFF_WHI (2 * MAT_BYTES)
#define OFF_WLO (3 * MAT_BYTES)
#define GS_TOTAL (2 * STAGE_BYTES)    // 81920

__global__ void __launch_bounds__(256, 1)
gemm_mma(const __nv_bfloat16* __restrict__ Ahi, const __nv_bfloat16* __restrict__ Alo,
         const __nv_bfloat16* __restrict__ Whi, const __nv_bfloat16* __restrict__ Wlo,
         float* __restrict__ C, int N, int K)
{
    extern __shared__ char smx[];
    const uint32_t sb = smem_u32(smx);
    const int tid  = threadIdx.x;
    const int lane = tid & 31;
    const int warp = tid >> 5;
    const int wm = warp >> 1, wn = warp & 1;
    const int m0 = blockIdx.y * GBM;
    const int n0 = blockIdx.x * GBN;

    // ---- load mapping: thread t handles row = t&127, 16B-chunks {t>>7, (t>>7)+2}
    const int lrow = tid & 127;
    const int lc   = tid >> 7;                    // 0 or 1
    const size_t a_g = (size_t)(m0 + lrow) * K;
    int wr = n0 + lrow; if (wr >= N) wr = N - 1;
    const size_t w_g = (size_t)wr * K;
    const uint32_t s_row = (uint32_t)lrow * ROWB;

    // ---- ldmatrix lane offsets
    const uint32_t a_lm = (uint32_t)(wm * 32 + (lane & 15)) * ROWB + (uint32_t)(lane >> 4) * 16;
    const uint32_t b_lm = (uint32_t)(wn * 64 + (lane & 7) + ((lane >> 4) << 3)) * ROWB
                        + (uint32_t)((lane >> 3) & 1) * 16;

    float acc[2][8][4];
#pragma unroll
    for (int i = 0; i < 2; i++)
#pragma unroll
        for (int j = 0; j < 8; j++)
#pragma unroll
            for (int q = 0; q < 4; q++) acc[i][j][q] = 0.f;

    const int nch = K >> 5;

    // ---- prologue: load chunk 0 into buf 0
    {
        const uint32_t st = sb + s_row;
#pragma unroll
        for (int u = 0; u < 2; u++) {
            const int cc = lc + u * 2;
            CP16(st + OFF_AHI + cc * 16, Ahi + a_g + cc * 8);
            CP16(st + OFF_ALO + cc * 16, Alo + a_g + cc * 8);
            CP16(st + OFF_WHI + cc * 16, Whi + w_g + cc * 8);
            CP16(st + OFF_WLO + cc * 16, Wlo + w_g + cc * 8);
        }
        CP_COMMIT();
    }

    for (int c = 0; c < nch; c++) {
        const int buf = c & 1;
        if (c + 1 < nch) {
            const int k0 = (c + 1) << 5;
            const uint32_t st = sb + ((c + 1) & 1) * STAGE_BYTES + s_row;
#pragma unroll
            for (int u = 0; u < 2; u++) {
                const int cc = lc + u * 2;
                CP16(st + OFF_AHI + cc * 16, Ahi + a_g + k0 + cc * 8);
                CP16(st + OFF_ALO + cc * 16, Alo + a_g + k0 + cc * 8);
                CP16(st + OFF_WHI + cc * 16, Whi + w_g + k0 + cc * 8);
                CP16(st + OFF_WLO + cc * 16, Wlo + w_g + k0 + cc * 8);
            }
            CP_COMMIT();
            CP_WAIT(1);
        } else {
            CP_COMMIT();
            CP_WAIT(0);
        }
        __syncthreads();

        const uint32_t base = sb + buf * STAGE_BYTES;
#pragma unroll
        for (int kk = 0; kk < 2; kk++) {
            uint32_t ah[2][4], al[2][4], bh[4][4], bl[4][4];
#pragma unroll
            for (int i = 0; i < 2; i++) {
                const uint32_t ao = base + a_lm + i * (16 * ROWB) + kk * 32;
                LDSM4(ah[i][0], ah[i][1], ah[i][2], ah[i][3], ao + OFF_AHI);
                LDSM4(al[i][0], al[i][1], al[i][2], al[i][3], ao + OFF_ALO);
            }
#pragma unroll
            for (int g = 0; g < 4; g++) {
                const uint32_t bo = base + b_lm + g * (16 * ROWB) + kk * 32;
                LDSM4(bh[g][0], bh[g][1], bh[g][2], bh[g][3], bo + OFF_WHI);
                LDSM4(bl[g][0], bl[g][1], bl[g][2], bl[g][3], bo + OFF_WLO);
            }
#pragma unroll
            for (int i = 0; i < 2; i++) {
#pragma unroll
                for (int j = 0; j < 8; j++) {
                    const int g = j >> 1, h = (j & 1) * 2;
                    MMA_BF16(acc[i][j], ah[i], bh[g][h], bh[g][h + 1]);
                    MMA_BF16(acc[i][j], ah[i], bl[g][h], bl[g][h + 1]);
                    MMA_BF16(acc[i][j], al[i], bh[g][h], bh[g][h + 1]);
                }
            }
        }
        __syncthreads();
    }

    // ---- epilogue
#pragma unroll
    for (int i = 0; i < 2; i++) {
        const int row = m0 + wm * 32 + i * 16 + (lane >> 2);
#pragma unroll
        for (int j = 0; j < 8; j++) {
            const int col = n0 + wn * 64 + j * 8 + 2 * (lane & 3);
            if (col < N) {
                *(float2*)&C[(size_t)row * N + col]       = make_float2(acc[i][j][0], acc[i][j][1]);
                *(float2*)&C[(size_t)(row + 8) * N + col] = make_float2(acc[i][j][2], acc[i][j][3]);
            }
        }
    }
}

// ============================================================
// RMSNorm
// ============================================================
__global__ void rmsnorm_kernel(const float* __restrict__ in, const float* __restrict__ w,
                               float* __restrict__ out, int K, int inStride, int outStride)
{
    const int row = blockIdx.x;
    const float* ip = in + (size_t)row * inStride;
    float* op = out + (size_t)row * outStride;

    float ss = 0.f;
    for (int i = threadIdx.x; i < K; i += blockDim.x) { float v = ip[i]; ss += v * v; }
#pragma unroll
    for (int o = 16; o; o >>= 1) ss += __shfl_xor_sync(0xffffffffu, ss, o);

    __shared__ float red[8];
    __shared__ float rs;
    int wid = threadIdx.x >> 5, lid = threadIdx.x & 31;
    if (lid == 0) red[wid] = ss;
    __syncthreads();
    if (threadIdx.x == 0) {
        float t = 0.f;
        for (int i = 0; i < 8; i++) t += red[i];
        rs = rsqrtf(t / (float)K + 1e-6f);
    }
    __syncthreads();
    float r = rs;
    for (int i = threadIdx.x; i < K; i += blockDim.x) op[i] = ip[i] * r * w[i];
}

// ============================================================
// RoPE on q_pe
// ============================================================
__global__ void rope_q_kernel(float* __restrict__ q,
                              const float* __restrict__ fcos, const float* __restrict__ fsin)
{
    const int row = blockIdx.x;
    const int tid = threadIdx.x;        // 512
    const int h = tid >> 5, i = tid & 31;
    const int s = row & (SEQ - 1);
    size_t base = (size_t)row * QW + h * DQK + DNn + 2 * i;
    float x0 = q[base], x1 = q[base + 1];
    float c = fcos[s * 32 + i], sn = fsin[s * 32 + i];
    q[base]     = x0 * c - x1 * sn;
    q[base + 1] = x0 * sn + x1 * c;
}

// ============================================================
// Build K
// ============================================================
__global__ void build_k_kernel(const float* __restrict__ fcos, const float* __restrict__ fsin)
{
    const int row = blockIdx.x;
    const int tid = threadIdx.x;        // 256
    __shared__ float pe[64];
    const int s = row & (SEQ - 1);
    if (tid < 32) {
        float x0 = g_kv[(size_t)row * KVAW + KVLR + 2 * tid];
        float x1 = g_kv[(size_t)row * KVAW + KVLR + 2 * tid + 1];
        float c = fcos[s * 32 + tid], sn = fsin[s * 32 + tid];
        pe[2 * tid]     = x0 * c - x1 * sn;
        pe[2 * tid + 1] = x0 * sn + x1 * c;
    }
    __syncthreads();
#pragma unroll
    for (int l = 0; l < 8; l++) {
        int i = tid + l * 256;
        int h = i >> 7, d = i & 127;
        float v = (d < DNn) ? g_kv2[(size_t)row * KV2W + h * (DNn + DVv) + d] : pe[d - DNn];
        g_k[(size_t)row * QW + i] = v;
    }
}

// ============================================================
// Flash attention (fp32, unchanged from round 1 — passing version)
// ============================================================
__global__ void flash_kernel()
{
    extern __shared__ float sm[];
    float* Qs   = sm;                    // 64 x 129
    float* Ks   = Qs + 64 * 129;
    float* Vs   = Ks + 64 * 129;         // 64 x 128
    float* Ps   = Vs + 64 * 128;         // 64 x 65
    float* mrow = Ps + 64 * 65;
    float* lrow = mrow + 64;

    const int q0 = blockIdx.x * 64;
    const int h  = blockIdx.y;
    const int b  = blockIdx.z;
    const int tid = threadIdx.x;
    const int ty = tid >> 4, tx = tid & 15;
    const int orow = tid >> 2;
    const int ocg  = tid & 3;
    const float scale = 0.088388347648318447f;

#pragma unroll
    for (int l = 0; l < 32; l++) {
        int i = tid + l * 256;
        int r = i >> 7, c = i & 127;
        Qs[r * 129 + c] = g_q[((size_t)(b * SEQ + q0 + r)) * QW + h * DQK + c];
    }
    if (tid < 64) { mrow[tid] = -1e30f; lrow[tid] = 0.f; }

    float o[32];
#pragma unroll
    for (int j = 0; j < 32; j++) o[j] = 0.f;

    const int nkt = blockIdx.x + 1;
    for (int kt = 0; kt < nkt; kt++) {
        const int t0 = kt * 64;
        __syncthreads();
#pragma unroll
        for (int l = 0; l < 32; l++) {
            int i = tid + l * 256;
            int r = i >> 7, c = i & 127;
            size_t grow = (size_t)(b * SEQ + t0 + r);
            Ks[r * 129 + c] = g_k  [grow * QW   + h * DQK + c];
            Vs[r * 128 + c] = g_kv2[grow * KV2W + h * (DNn + DVv) + DNn + c];
        }
        __syncthreads();

        float acc[4][4];
#pragma unroll
        for (int i = 0; i < 4; i++)
#pragma unroll
            for (int j = 0; j < 4; j++) acc[i][j] = 0.f;
#pragma unroll 8
        for (int kk = 0; kk < 128; kk++) {
            float a[4], bv[4];
#pragma unroll
            for (int i = 0; i < 4; i++) a[i] = Qs[(ty * 4 + i) * 129 + kk];
#pragma unroll
            for (int j = 0; j < 4; j++) bv[j] = Ks[(tx * 4 + j) * 129 + kk];
#pragma unroll
            for (int i = 0; i < 4; i++)
#pragma unroll
                for (int j = 0; j < 4; j++) acc[i][j] += a[i] * bv[j];
        }
#pragma unroll
        for (int i = 0; i < 4; i++) {
#pragma unroll
            for (int j = 0; j < 4; j++) {
                int qq = q0 + ty * 4 + i, tt = t0 + tx * 4 + j;
                float mv = (tt <= qq) ? 0.f : -1e9f;
                Ps[(ty * 4 + i) * 65 + tx * 4 + j] = acc[i][j] * scale + mv;
            }
        }
        __syncthreads();

        float lm = -1e30f;
        for (int c = ocg * 16; c < ocg * 16 + 16; c++) lm = fmaxf(lm, Ps[orow * 65 + c]);
        lm = fmaxf(lm, __shfl_xor_sync(0xffffffffu, lm, 1));
        lm = fmaxf(lm, __shfl_xor_sync(0xffffffffu, lm, 2));
        float mold = mrow[orow];
        float mnew = fmaxf(mold, lm);
        float alpha = __expf(mold - mnew);
        float ls = 0.f;
        for (int c = ocg * 16; c < ocg * 16 + 16; c++) {
            float p = __expf(Ps[orow * 65 + c] - mnew);
            Ps[orow * 65 + c] = p;
            ls += p;
        }
        ls += __shfl_xor_sync(0xffffffffu, ls, 1);
        ls += __shfl_xor_sync(0xffffffffu, ls, 2);
        if (ocg == 0) {
            lrow[orow] = lrow[orow] * alpha + ls;
            mrow[orow] = mnew;
        }
        __syncthreads();

#pragma unroll
        for (int j = 0; j < 32; j++) o[j] *= alpha;
        for (int t = 0; t < 64; t++) {
            float p = Ps[orow * 65 + t];
#pragma unroll
            for (int j = 0; j < 32; j++) o[j] += p * Vs[t * 128 + ocg + 4 * j];
        }
    }
    __syncthreads();
    float inv = 1.f / lrow[orow];
#pragma unroll
    for (int j = 0; j < 32; j++)
        g_attn[((size_t)(b * SEQ + q0 + orow)) * OW + h * DVv + ocg + 4 * j] = o[j] * inv;
}

// ============================================================
// launch
// ============================================================
static inline void split(const float* in, __nv_bfloat16* hi, __nv_bfloat16* lo, size_t n)
{
    split_kernel<<<(int)((n + 255) / 256), 256>>>(in, hi, lo, (int)n);
}

extern "C" void kernel_launch(void* const* d_in, const int* in_sizes, int n_in,
                              void* d_out, int out_size)
{
    const float* x      = (const float*)d_in[0];
    const float* wq_a   = (const float*)d_in[1];
    const float* qnw    = (const float*)d_in[2];
    const float* wq_b   = (const float*)d_in[3];
    const float* wkv_a  = (const float*)d_in[4];
    const float* kvnw   = (const float*)d_in[5];
    const float* wkv_b  = (const float*)d_in[6];
    const float* wo     = (const float*)d_in[7];
    const float* fcos   = (const float*)d_in[9];
    const float* fsin   = (const float*)d_in[10];

    float* out = (float*)d_out;

    float *p_qa, *p_q, *p_kv, *p_ckvn, *p_kv2, *p_attn;
    cudaGetSymbolAddress((void**)&p_qa,   g_qa);
    cudaGetSymbolAddress((void**)&p_q,    g_q);
    cudaGetSymbolAddress((void**)&p_kv,   g_kv);
    cudaGetSymbolAddress((void**)&p_ckvn, g_ckvn);
    cudaGetSymbolAddress((void**)&p_kv2,  g_kv2);
    cudaGetSymbolAddress((void**)&p_attn, g_attn);

    __nv_bfloat16 *xh, *xl, *wqah, *wqal, *wqbh, *wqbl, *wkah, *wkal, *wkbh, *wkbl,
                  *woh, *wol, *qanh, *qanl, *ckh, *ckl, *ath, *atl;
    cudaGetSymbolAddress((void**)&xh,   g_x_hi);   cudaGetSymbolAddress((void**)&xl,   g_x_lo);
    cudaGetSymbolAddress((void**)&wqah, g_wqa_hi); cudaGetSymbolAddress((void**)&wqal, g_wqa_lo);
    cudaGetSymbolAddress((void**)&wqbh, g_wqb_hi); cudaGetSymbolAddress((void**)&wqbl, g_wqb_lo);
    cudaGetSymbolAddress((void**)&wkah, g_wkva_hi);cudaGetSymbolAddress((void**)&wkal, g_wkva_lo);
    cudaGetSymbolAddress((void**)&wkbh, g_wkvb_hi);cudaGetSymbolAddress((void**)&wkbl, g_wkvb_lo);
    cudaGetSymbolAddress((void**)&woh,  g_wo_hi);  cudaGetSymbolAddress((void**)&wol,  g_wo_lo);
    cudaGetSymbolAddress((void**)&qanh, g_qan_hi); cudaGetSymbolAddress((void**)&qanl, g_qan_lo);
    cudaGetSymbolAddress((void**)&ckh,  g_ckv_hi); cudaGetSymbolAddress((void**)&ckl,  g_ckv_lo);
    cudaGetSymbolAddress((void**)&ath,  g_at_hi);  cudaGetSymbolAddress((void**)&atl,  g_at_lo);

    const int smem_flash = (64 * 129 * 2 + 64 * 128 + 64 * 65 + 128) * sizeof(float);
    cudaFuncSetAttribute(flash_kernel, cudaFuncAttributeMaxDynamicSharedMemorySize, smem_flash);
    cudaFuncSetAttribute(gemm_mma, cudaFuncAttributeMaxDynamicSharedMemorySize, GS_TOTAL);

    // splits of inputs/weights
    split(x,     xh,   xl,   (size_t)ROWS * DIM);
    split(wq_a,  wqah, wqal, (size_t)QLR * DIM);
    split(wq_b,  wqbh, wqbl, (size_t)QW * QLR);
    split(wkv_a, wkah, wkal, (size_t)KVAW * DIM);
    split(wkv_b, wkbh, wkbl, (size_t)KV2W * KVLR);
    split(wo,    woh,  wol,  (size_t)DIM * OW);

    // q path
    gemm_mma<<<dim3(QLR / 128, ROWS / 128), 256, GS_TOTAL>>>(xh, xl, wqah, wqal, p_qa, QLR, DIM);
    rmsnorm_kernel<<<ROWS, 256>>>(p_qa, qnw, p_qa, QLR, QLR, QLR);
    split(p_qa, qanh, qanl, (size_t)ROWS * QLR);
    gemm_mma<<<dim3(QW / 128, ROWS / 128), 256, GS_TOTAL>>>(qanh, qanl, wqbh, wqbl, p_q, QW, QLR);
    rope_q_kernel<<<ROWS, 512>>>(p_q, fcos, fsin);

    // kv path
    gemm_mma<<<dim3((KVAW + 127) / 128, ROWS / 128), 256, GS_TOTAL>>>(xh, xl, wkah, wkal, p_kv, KVAW, DIM);
    rmsnorm_kernel<<<ROWS, 256>>>(p_kv, kvnw, p_ckvn, KVLR, KVAW, KVLR);
    split(p_ckvn, ckh, ckl, (size_t)ROWS * KVLR);
    gemm_mma<<<dim3(KV2W / 128, ROWS / 128), 256, GS_TOTAL>>>(ckh, ckl, wkbh, wkbl, p_kv2, KV2W, KVLR);
    build_k_kernel<<<ROWS, 256>>>(fcos, fsin);

    // attention
    flash_kernel<<<dim3(SEQ / 64, NH, BSZ), 256, smem_flash>>>();

    // output projection
    split(p_attn, ath, atl, (size_t)ROWS * OW);
    gemm_mma<<<dim3(DIM / 128, ROWS / 128), 256, GS_TOTAL>>>(ath, atl, woh, wol, out, DIM, OW);
}

// round 4
// speedup vs baseline: 2.2690x; 1.6093x over previous
#include <cuda_runtime.h>
#include <cuda_bf16.h>
#include <cstdint>
#include <math.h>

// Problem constants
#define BSZ   2
#define SEQ   2048
#define DIM   2048
#define NH    16
#define DRr   64
#define DNn   64
#define DQK   128
#define DVv   128
#define QLR   1536
#define KVLR  1024
#define ROWS  (BSZ*SEQ)          // 4096
#define KVAW  (KVLR + DRr)       // 1088
#define KV2W  (NH*(DNn+DVv))     // 3072
#define QW    (NH*DQK)           // 2048
#define OW    (NH*DVv)           // 2048

// -------- fp32 scratch --------
__device__ float g_qa  [ (size_t)ROWS * QLR  ];
__device__ float g_q   [ (size_t)ROWS * QW   ];
__device__ float g_kv  [ (size_t)ROWS * KVAW ];
__device__ float g_ckvn[ (size_t)ROWS * KVLR ];
__device__ float g_kv2 [ (size_t)ROWS * KV2W ];
__device__ float g_k   [ (size_t)ROWS * QW   ];
__device__ float g_attn[ (size_t)ROWS * OW   ];

// -------- bf16 split scratch --------
__device__ __nv_bfloat16 g_x_hi  [(size_t)ROWS*DIM],  g_x_lo  [(size_t)ROWS*DIM];
__device__ __nv_bfloat16 g_wqa_hi[(size_t)QLR*DIM],   g_wqa_lo[(size_t)QLR*DIM];
__device__ __nv_bfloat16 g_wqb_hi[(size_t)QW*QLR],    g_wqb_lo[(size_t)QW*QLR];
__device__ __nv_bfloat16 g_wkva_hi[(size_t)KVAW*DIM], g_wkva_lo[(size_t)KVAW*DIM];
__device__ __nv_bfloat16 g_wkvb_hi[(size_t)KV2W*KVLR],g_wkvb_lo[(size_t)KV2W*KVLR];
__device__ __nv_bfloat16 g_wo_hi [(size_t)DIM*OW],    g_wo_lo [(size_t)DIM*OW];
__device__ __nv_bfloat16 g_qan_hi[(size_t)ROWS*QLR],  g_qan_lo[(size_t)ROWS*QLR];
__device__ __nv_bfloat16 g_ckv_hi[(size_t)ROWS*KVLR], g_ckv_lo[(size_t)ROWS*KVLR];
__device__ __nv_bfloat16 g_at_hi [(size_t)ROWS*OW],   g_at_lo [(size_t)ROWS*OW];
// flash operands (split)
__device__ __nv_bfloat16 g_q_hi[(size_t)ROWS*QW],  g_q_lo[(size_t)ROWS*QW];
__device__ __nv_bfloat16 g_k_hi[(size_t)ROWS*QW],  g_k_lo[(size_t)ROWS*QW];
__device__ __nv_bfloat16 g_v_hi[(size_t)ROWS*OW],  g_v_lo[(size_t)ROWS*OW];

// ============================================================
// helpers (sm_80-compatible instructions only — plain sm_103 target!)
// ============================================================
__device__ __forceinline__ uint32_t smem_u32(const void* p) {
    uint32_t a;
    asm("{ .reg .u64 t; cvta.to.shared.u64 t, %1; cvt.u32.u64 %0, t; }" : "=r"(a) : "l"(p));
    return a;
}

#define CP16(dst, src) \
    asm volatile("cp.async.cg.shared.global [%0], [%1], 16;" :: "r"(dst), "l"(src))
#define CP_COMMIT() asm volatile("cp.async.commit_group;" ::: "memory")
#define CP_WAIT(n)  asm volatile("cp.async.wait_group %0;" :: "n"(n) : "memory")

#define LDSM4(r0, r1, r2, r3, addr) \
    asm volatile("ldmatrix.sync.aligned.m8n8.x4.shared.b16 {%0,%1,%2,%3}, [%4];" \
        : "=r"(r0), "=r"(r1), "=r"(r2), "=r"(r3) : "r"(addr))

#define LDSM4T(r0, r1, r2, r3, addr) \
    asm volatile("ldmatrix.sync.aligned.m8n8.x4.trans.shared.b16 {%0,%1,%2,%3}, [%4];" \
        : "=r"(r0), "=r"(r1), "=r"(r2), "=r"(r3) : "r"(addr))

#define MMA_BF16(d, a, b0, b1) \
    asm volatile("mma.sync.aligned.m16n8k16.row.col.f32.bf16.bf16.f32 " \
        "{%0,%1,%2,%3},{%4,%5,%6,%7},{%8,%9},{%0,%1,%2,%3};" \
        : "+f"((d)[0]), "+f"((d)[1]), "+f"((d)[2]), "+f"((d)[3]) \
        : "r"((a)[0]), "r"((a)[1]), "r"((a)[2]), "r"((a)[3]), "r"(b0), "r"(b1))

// ============================================================
// Split fp32 -> (bf16 hi, bf16 lo)
// ============================================================
__global__ void split_kernel(const float* __restrict__ in,
                             __nv_bfloat16* __restrict__ hi,
                             __nv_bfloat16* __restrict__ lo, int n)
{
    int i = blockIdx.x * blockDim.x + threadIdx.x;
    if (i < n) {
        float v = in[i];
        __nv_bfloat16 h = __float2bfloat16(v);
        hi[i] = h;
        lo[i] = __float2bfloat16(v - __bfloat162float(h));
    }
}

// split V out of g_kv2 (strided)
__global__ void split_v_kernel()
{
    int i = blockIdx.x * blockDim.x + threadIdx.x;   // over ROWS*OW
    int row = i >> 11;                               // /2048
    int c   = i & 2047;
    int h = c >> 7, d = c & 127;
    float v = g_kv2[(size_t)row * KV2W + h * (DNn + DVv) + DNn + d];
    __nv_bfloat16 hh = __float2bfloat16(v);
    g_v_hi[i] = hh;
    g_v_lo[i] = __float2bfloat16(v - __bfloat162float(hh));
}

// ============================================================
// Split-bf16 GEMM via mma.sync: C[M,N] = A[M,K] @ W[N,K]^T
// ============================================================
#define GBM 128
#define GBN 128
#define ROWB 80
#define MAT_BYTES (128 * ROWB)
#define STAGE_BYTES (4 * MAT_BYTES)
#define OFF_AHI 0
#define OFF_ALO (1 * MAT_BYTES)
#define OFF_WHI (2 * MAT_BYTES)
#define OFF_WLO (3 * MAT_BYTES)
#define GS_TOTAL (2 * STAGE_BYTES)

__global__ void __launch_bounds__(256, 1)
gemm_mma(const __nv_bfloat16* __restrict__ Ahi, const __nv_bfloat16* __restrict__ Alo,
         const __nv_bfloat16* __restrict__ Whi, const __nv_bfloat16* __restrict__ Wlo,
         float* __restrict__ C, int N, int K)
{
    extern __shared__ char smx[];
    const uint32_t sb = smem_u32(smx);
    const int tid  = threadIdx.x;
    const int lane = tid & 31;
    const int warp = tid >> 5;
    const int wm = warp >> 1, wn = warp & 1;
    const int m0 = blockIdx.y * GBM;
    const int n0 = blockIdx.x * GBN;

    const int lrow = tid & 127;
    const int lc   = tid >> 7;
    const size_t a_g = (size_t)(m0 + lrow) * K;
    int wr = n0 + lrow; if (wr >= N) wr = N - 1;
    const size_t w_g = (size_t)wr * K;
    const uint32_t s_row = (uint32_t)lrow * ROWB;

    const uint32_t a_lm = (uint32_t)(wm * 32 + (lane & 15)) * ROWB + (uint32_t)(lane >> 4) * 16;
    const uint32_t b_lm = (uint32_t)(wn * 64 + (lane & 7) + ((lane >> 4) << 3)) * ROWB
                        + (uint32_t)((lane >> 3) & 1) * 16;

    float acc[2][8][4];
#pragma unroll
    for (int i = 0; i < 2; i++)
#pragma unroll
        for (int j = 0; j < 8; j++)
#pragma unroll
            for (int q = 0; q < 4; q++) acc[i][j][q] = 0.f;

    const int nch = K >> 5;

    {
        const uint32_t st = sb + s_row;
#pragma unroll
        for (int u = 0; u < 2; u++) {
            const int cc = lc + u * 2;
            CP16(st + OFF_AHI + cc * 16, Ahi + a_g + cc * 8);
            CP16(st + OFF_ALO + cc * 16, Alo + a_g + cc * 8);
            CP16(st + OFF_WHI + cc * 16, Whi + w_g + cc * 8);
            CP16(st + OFF_WLO + cc * 16, Wlo + w_g + cc * 8);
        }
        CP_COMMIT();
    }

    for (int c = 0; c < nch; c++) {
        const int buf = c & 1;
        if (c + 1 < nch) {
            const int k0 = (c + 1) << 5;
            const uint32_t st = sb + ((c + 1) & 1) * STAGE_BYTES + s_row;
#pragma unroll
            for (int u = 0; u < 2; u++) {
                const int cc = lc + u * 2;
                CP16(st + OFF_AHI + cc * 16, Ahi + a_g + k0 + cc * 8);
                CP16(st + OFF_ALO + cc * 16, Alo + a_g + k0 + cc * 8);
                CP16(st + OFF_WHI + cc * 16, Whi + w_g + k0 + cc * 8);
                CP16(st + OFF_WLO + cc * 16, Wlo + w_g + k0 + cc * 8);
            }
            CP_COMMIT();
            CP_WAIT(1);
        } else {
            CP_COMMIT();
            CP_WAIT(0);
        }
        __syncthreads();

        const uint32_t base = sb + buf * STAGE_BYTES;
#pragma unroll
        for (int kk = 0; kk < 2; kk++) {
            uint32_t ah[2][4], al[2][4], bh[4][4], bl[4][4];
#pragma unroll
            for (int i = 0; i < 2; i++) {
                const uint32_t ao = base + a_lm + i * (16 * ROWB) + kk * 32;
                LDSM4(ah[i][0], ah[i][1], ah[i][2], ah[i][3], ao + OFF_AHI);
                LDSM4(al[i][0], al[i][1], al[i][2], al[i][3], ao + OFF_ALO);
            }
#pragma unroll
            for (int g = 0; g < 4; g++) {
                const uint32_t bo = base + b_lm + g * (16 * ROWB) + kk * 32;
                LDSM4(bh[g][0], bh[g][1], bh[g][2], bh[g][3], bo + OFF_WHI);
                LDSM4(bl[g][0], bl[g][1], bl[g][2], bl[g][3], bo + OFF_WLO);
            }
#pragma unroll
            for (int i = 0; i < 2; i++) {
#pragma unroll
                for (int j = 0; j < 8; j++) {
                    const int g = j >> 1, h = (j & 1) * 2;
                    MMA_BF16(acc[i][j], ah[i], bh[g][h], bh[g][h + 1]);
                    MMA_BF16(acc[i][j], ah[i], bl[g][h], bl[g][h + 1]);
                    MMA_BF16(acc[i][j], al[i], bh[g][h], bh[g][h + 1]);
                }
            }
        }
        __syncthreads();
    }

#pragma unroll
    for (int i = 0; i < 2; i++) {
        const int row = m0 + wm * 32 + i * 16 + (lane >> 2);
#pragma unroll
        for (int j = 0; j < 8; j++) {
            const int col = n0 + wn * 64 + j * 8 + 2 * (lane & 3);
            if (col < N) {
                *(float2*)&C[(size_t)row * N + col]       = make_float2(acc[i][j][0], acc[i][j][1]);
                *(float2*)&C[(size_t)(row + 8) * N + col] = make_float2(acc[i][j][2], acc[i][j][3]);
            }
        }
    }
}

// ============================================================
// RMSNorm
// ============================================================
__global__ void rmsnorm_kernel(const float* __restrict__ in, const float* __restrict__ w,
                               float* __restrict__ out, int K, int inStride, int outStride)
{
    const int row = blockIdx.x;
    const float* ip = in + (size_t)row * inStride;
    float* op = out + (size_t)row * outStride;

    float ss = 0.f;
    for (int i = threadIdx.x; i < K; i += blockDim.x) { float v = ip[i]; ss += v * v; }
#pragma unroll
    for (int o = 16; o; o >>= 1) ss += __shfl_xor_sync(0xffffffffu, ss, o);

    __shared__ float red[8];
    __shared__ float rs;
    int wid = threadIdx.x >> 5, lid = threadIdx.x & 31;
    if (lid == 0) red[wid] = ss;
    __syncthreads();
    if (threadIdx.x == 0) {
        float t = 0.f;
        for (int i = 0; i < 8; i++) t += red[i];
        rs = rsqrtf(t / (float)K + 1e-6f);
    }
    __syncthreads();
    float r = rs;
    for (int i = threadIdx.x; i < K; i += blockDim.x) op[i] = ip[i] * r * w[i];
}

// ============================================================
// RoPE on q_pe
// ============================================================
__global__ void rope_q_kernel(float* __restrict__ q,
                              const float* __restrict__ fcos, const float* __restrict__ fsin)
{
    const int row = blockIdx.x;
    const int tid = threadIdx.x;        // 512
    const int h = tid >> 5, i = tid & 31;
    const int s = row & (SEQ - 1);
    size_t base = (size_t)row * QW + h * DQK + DNn + 2 * i;
    float x0 = q[base], x1 = q[base + 1];
    float c = fcos[s * 32 + i], sn = fsin[s * 32 + i];
    q[base]     = x0 * c - x1 * sn;
    q[base + 1] = x0 * sn + x1 * c;
}

// ============================================================
// Build K
// ============================================================
__global__ void build_k_kernel(const float* __restrict__ fcos, const float* __restrict__ fsin)
{
    const int row = blockIdx.x;
    const int tid = threadIdx.x;        // 256
    __shared__ float pe[64];
    const int s = row & (SEQ - 1);
    if (tid < 32) {
        float x0 = g_kv[(size_t)row * KVAW + KVLR + 2 * tid];
        float x1 = g_kv[(size_t)row * KVAW + KVLR + 2 * tid + 1];
        float c = fcos[s * 32 + tid], sn = fsin[s * 32 + tid];
        pe[2 * tid]     = x0 * c - x1 * sn;
        pe[2 * tid + 1] = x0 * sn + x1 * c;
    }
    __syncthreads();
#pragma unroll
    for (int l = 0; l < 8; l++) {
        int i = tid + l * 256;
        int h = i >> 7, d = i & 127;
        float v = (d < DNn) ? g_kv2[(size_t)row * KV2W + h * (DNn + DVv) + d] : pe[d - DNn];
        g_k[(size_t)row * QW + i] = v;
    }
}

// ============================================================
// Flash attention — FA2-style, split-bf16 mma.sync
// BQ=128, BK=64, 8 warps (each owns 16 rows), block 256.
// grid: (SEQ/128, NH, BSZ)
// ============================================================
#define RB 272                       // 128 bf16 (256B) + 16B pad
#define FQ_HI 0
#define FQ_LO (128*RB)               // 34816
#define FK_HI (2*128*RB)             // 69632
#define FK_LO (FK_HI + 64*RB)
#define FV_HI (FK_LO + 64*RB)
#define FV_LO (FV_HI + 64*RB)
#define F_TOTAL (FV_LO + 64*RB)      // 139264

__global__ void __launch_bounds__(256, 1)
flash_mma(const __nv_bfloat16* __restrict__ qhi, const __nv_bfloat16* __restrict__ qlo,
          const __nv_bfloat16* __restrict__ khi, const __nv_bfloat16* __restrict__ klo,
          const __nv_bfloat16* __restrict__ vhi, const __nv_bfloat16* __restrict__ vlo)
{
    extern __shared__ char smx[];
    const uint32_t sb = smem_u32(smx);
    const int tid = threadIdx.x, lane = tid & 31, wid = tid >> 5;
    const int q0 = blockIdx.x * 128;
    const int h  = blockIdx.y;
    const int b  = blockIdx.z;
    const float scale = 0.088388347648318447f;

    // ---- load Q tile (128 x 128 bf16, hi+lo)
    {
        int r = tid >> 4;
        const int cc = tid & 15;
#pragma unroll
        for (int it = 0; it < 8; it++, r += 16) {
            size_t go = (size_t)(b * SEQ + q0 + r) * QW + h * DQK + cc * 8;
            uint32_t so = (uint32_t)r * RB + cc * 16;
            *(uint4*)(smx + FQ_HI + so) = *(const uint4*)(qhi + go);
            *(uint4*)(smx + FQ_LO + so) = *(const uint4*)(qlo + go);
        }
    }

    float oacc[16][4];
#pragma unroll
    for (int t = 0; t < 16; t++)
#pragma unroll
        for (int q = 0; q < 4; q++) oacc[t][q] = 0.f;
    float m0 = -1e30f, m1 = -1e30f, l0 = 0.f, l1 = 0.f;

    const uint32_t a_off  = (uint32_t)(wid * 16 + (lane & 15)) * RB + (uint32_t)(lane >> 4) * 16;
    const uint32_t bK_off = (uint32_t)((lane & 7) + ((lane >> 4) << 3)) * RB
                          + (uint32_t)((lane >> 3) & 1) * 16;
    const uint32_t bV_off = (uint32_t)((lane & 7) + (((lane >> 3) & 1) << 3)) * RB
                          + (uint32_t)(lane >> 4) * 16;

    const int row0 = q0 + wid * 16 + (lane >> 2);
    const int row1 = row0 + 8;

    const int nkt = (blockIdx.x + 1) * 2;
    for (int kt = 0; kt < nkt; kt++) {
        const int t0 = kt * 64;
        __syncthreads();
        {   // load K,V tiles (64 x 128 bf16 each, hi+lo)
            int r = tid >> 4;
            const int cc = tid & 15;
#pragma unroll
            for (int it = 0; it < 4; it++, r += 16) {
                size_t grow = (size_t)(b * SEQ + t0 + r);
                size_t gk = grow * QW + h * DQK + cc * 8;
                size_t gv = grow * OW + h * DVv + cc * 8;
                uint32_t so = (uint32_t)r * RB + cc * 16;
                *(uint4*)(smx + FK_HI + so) = *(const uint4*)(khi + gk);
                *(uint4*)(smx + FK_LO + so) = *(const uint4*)(klo + gk);
                *(uint4*)(smx + FV_HI + so) = *(const uint4*)(vhi + gv);
                *(uint4*)(smx + FV_LO + so) = *(const uint4*)(vlo + gv);
            }
        }
        __syncthreads();

        // ---- S = Q @ K^T  (warp tile 16 x 64)
        float sacc[8][4];
#pragma unroll
        for (int t = 0; t < 8; t++)
#pragma unroll
            for (int q = 0; q < 4; q++) sacc[t][q] = 0.f;

#pragma unroll
        for (int kk = 0; kk < 8; kk++) {
            uint32_t ah[4], al[4];
            LDSM4(ah[0], ah[1], ah[2], ah[3], sb + FQ_HI + a_off + kk * 32);
            LDSM4(al[0], al[1], al[2], al[3], sb + FQ_LO + a_off + kk * 32);
#pragma unroll
            for (int g = 0; g < 4; g++) {
                uint32_t bh[4], bl[4];
                const uint32_t bo = bK_off + g * (16 * RB) + kk * 32;
                LDSM4(bh[0], bh[1], bh[2], bh[3], sb + FK_HI + bo);
                LDSM4(bl[0], bl[1], bl[2], bl[3], sb + FK_LO + bo);
                MMA_BF16(sacc[2*g],   ah, bh[0], bh[1]);
                MMA_BF16(sacc[2*g+1], ah, bh[2], bh[3]);
                MMA_BF16(sacc[2*g],   ah, bl[0], bl[1]);
                MMA_BF16(sacc[2*g+1], ah, bl[2], bl[3]);
                MMA_BF16(sacc[2*g],   al, bh[0], bh[1]);
                MMA_BF16(sacc[2*g+1], al, bh[2], bh[3]);
            }
        }

        // ---- scale + causal mask
        const int cb = t0 + 2 * (lane & 3);
#pragma unroll
        for (int t = 0; t < 8; t++) {
            const int c0 = cb + 8 * t, c1 = c0 + 1;
            sacc[t][0] = sacc[t][0] * scale + ((c0 > row0) ? -1e9f : 0.f);
            sacc[t][1] = sacc[t][1] * scale + ((c1 > row0) ? -1e9f : 0.f);
            sacc[t][2] = sacc[t][2] * scale + ((c0 > row1) ? -1e9f : 0.f);
            sacc[t][3] = sacc[t][3] * scale + ((c1 > row1) ? -1e9f : 0.f);
        }

        // ---- online softmax (rows owned by 4-lane groups)
        float mx0 = -1e30f, mx1 = -1e30f;
#pragma unroll
        for (int t = 0; t < 8; t++) {
            mx0 = fmaxf(mx0, fmaxf(sacc[t][0], sacc[t][1]));
            mx1 = fmaxf(mx1, fmaxf(sacc[t][2], sacc[t][3]));
        }
        mx0 = fmaxf(mx0, __shfl_xor_sync(0xffffffffu, mx0, 1));
        mx0 = fmaxf(mx0, __shfl_xor_sync(0xffffffffu, mx0, 2));
        mx1 = fmaxf(mx1, __shfl_xor_sync(0xffffffffu, mx1, 1));
        mx1 = fmaxf(mx1, __shfl_xor_sync(0xffffffffu, mx1, 2));

        const float mn0 = fmaxf(m0, mx0), mn1 = fmaxf(m1, mx1);
        const float al0 = __expf(m0 - mn0), al1 = __expf(m1 - mn1);
        m0 = mn0; m1 = mn1;

        float ps0 = 0.f, ps1 = 0.f;
#pragma unroll
        for (int t = 0; t < 8; t++) {
            sacc[t][0] = __expf(sacc[t][0] - mn0);
            sacc[t][1] = __expf(sacc[t][1] - mn0);
            sacc[t][2] = __expf(sacc[t][2] - mn1);
            sacc[t][3] = __expf(sacc[t][3] - mn1);
            ps0 += sacc[t][0] + sacc[t][1];
            ps1 += sacc[t][2] + sacc[t][3];
        }
        ps0 += __shfl_xor_sync(0xffffffffu, ps0, 1);
        ps0 += __shfl_xor_sync(0xffffffffu, ps0, 2);
        ps1 += __shfl_xor_sync(0xffffffffu, ps1, 1);
        ps1 += __shfl_xor_sync(0xffffffffu, ps1, 2);
        l0 = l0 * al0 + ps0;
        l1 = l1 * al1 + ps1;

#pragma unroll
        for (int t = 0; t < 16; t++) {
            oacc[t][0] *= al0; oacc[t][1] *= al0;
            oacc[t][2] *= al1; oacc[t][3] *= al1;
        }

        // ---- O += P @ V  (P re-packed from sacc; 3-term split)
#pragma unroll
        for (int jj = 0; jj < 4; jj++) {
            const int t2 = 2 * jj, t3 = 2 * jj + 1;
            uint32_t phi[4], plo[4];
            {
                __nv_bfloat162 h0 = __float22bfloat162_rn(make_float2(sacc[t2][0], sacc[t2][1]));
                __nv_bfloat162 h1 = __float22bfloat162_rn(make_float2(sacc[t2][2], sacc[t2][3]));
                __nv_bfloat162 h2 = __float22bfloat162_rn(make_float2(sacc[t3][0], sacc[t3][1]));
                __nv_bfloat162 h3 = __float22bfloat162_rn(make_float2(sacc[t3][2], sacc[t3][3]));
                float2 b0 = __bfloat1622float2(h0), b1 = __bfloat1622float2(h1);
                float2 b2 = __bfloat1622float2(h2), b3 = __bfloat1622float2(h3);
                __nv_bfloat162 g0 = __float22bfloat162_rn(make_float2(sacc[t2][0]-b0.x, sacc[t2][1]-b0.y));
                __nv_bfloat162 g1 = __float22bfloat162_rn(make_float2(sacc[t2][2]-b1.x, sacc[t2][3]-b1.y));
                __nv_bfloat162 g2 = __float22bfloat162_rn(make_float2(sacc[t3][0]-b2.x, sacc[t3][1]-b2.y));
                __nv_bfloat162 g3 = __float22bfloat162_rn(make_float2(sacc[t3][2]-b3.x, sacc[t3][3]-b3.y));
                phi[0] = *(uint32_t*)&h0; phi[1] = *(uint32_t*)&h1;
                phi[2] = *(uint32_t*)&h2; phi[3] = *(uint32_t*)&h3;
                plo[0] = *(uint32_t*)&g0; plo[1] = *(uint32_t*)&g1;
                plo[2] = *(uint32_t*)&g2; plo[3] = *(uint32_t*)&g3;
            }
#pragma unroll
            for (int g = 0; g < 8; g++) {
                uint32_t bh[4], bl[4];
                const uint32_t bo = bV_off + jj * (16 * RB) + g * 32;
                LDSM4T(bh[0], bh[1], bh[2], bh[3], sb + FV_HI + bo);
                LDSM4T(bl[0], bl[1], bl[2], bl[3], sb + FV_LO + bo);
                MMA_BF16(oacc[2*g],   phi, bh[0], bh[1]);
                MMA_BF16(oacc[2*g+1], phi, bh[2], bh[3]);
                MMA_BF16(oacc[2*g],   phi, bl[0], bl[1]);
                MMA_BF16(oacc[2*g+1], phi, bl[2], bl[3]);
                MMA_BF16(oacc[2*g],   plo, bh[0], bh[1]);
                MMA_BF16(oacc[2*g+1], plo, bh[2], bh[3]);
            }
        }
    }

    // ---- epilogue
    const float inv0 = 1.f / l0, inv1 = 1.f / l1;
    const size_t o0 = (size_t)(b * SEQ + row0) * OW + h * DVv;
    const size_t o1 = (size_t)(b * SEQ + row1) * OW + h * DVv;
#pragma unroll
    for (int t = 0; t < 16; t++) {
        const int d0 = 8 * t + 2 * (lane & 3);
        *(float2*)&g_attn[o0 + d0] = make_float2(oacc[t][0] * inv0, oacc[t][1] * inv0);
        *(float2*)&g_attn[o1 + d0] = make_float2(oacc[t][2] * inv1, oacc[t][3] * inv1);
    }
}

// ============================================================
// launch
// ============================================================
static inline void split(const float* in, __nv_bfloat16* hi, __nv_bfloat16* lo, size_t n)
{
    split_kernel<<<(int)((n + 255) / 256), 256>>>(in, hi, lo, (int)n);
}

extern "C" void kernel_launch(void* const* d_in, const int* in_sizes, int n_in,
                              void* d_out, int out_size)
{
    const float* x      = (const float*)d_in[0];
    const float* wq_a   = (const float*)d_in[1];
    const float* qnw    = (const float*)d_in[2];
    const float* wq_b   = (const float*)d_in[3];
    const float* wkv_a  = (const float*)d_in[4];
    const float* kvnw   = (const float*)d_in[5];
    const float* wkv_b  = (const float*)d_in[6];
    const float* wo     = (const float*)d_in[7];
    const float* fcos   = (const float*)d_in[9];
    const float* fsin   = (const float*)d_in[10];

    float* out = (float*)d_out;

    float *p_qa, *p_q, *p_kv, *p_ckvn, *p_kv2, *p_attn, *p_k;
    cudaGetSymbolAddress((void**)&p_qa,   g_qa);
    cudaGetSymbolAddress((void**)&p_q,    g_q);
    cudaGetSymbolAddress((void**)&p_kv,   g_kv);
    cudaGetSymbolAddress((void**)&p_ckvn, g_ckvn);
    cudaGetSymbolAddress((void**)&p_kv2,  g_kv2);
    cudaGetSymbolAddress((void**)&p_attn, g_attn);
    cudaGetSymbolAddress((void**)&p_k,    g_k);

    __nv_bfloat16 *xh, *xl, *wqah, *wqal, *wqbh, *wqbl, *wkah, *wkal, *wkbh, *wkbl,
                  *woh, *wol, *qanh, *qanl, *ckh, *ckl, *ath, *atl,
                  *qh, *ql, *kh, *kl, *vh, *vl;
    cudaGetSymbolAddress((void**)&xh,   g_x_hi);   cudaGetSymbolAddress((void**)&xl,   g_x_lo);
    cudaGetSymbolAddress((void**)&wqah, g_wqa_hi); cudaGetSymbolAddress((void**)&wqal, g_wqa_lo);
    cudaGetSymbolAddress((void**)&wqbh, g_wqb_hi); cudaGetSymbolAddress((void**)&wqbl, g_wqb_lo);
    cudaGetSymbolAddress((void**)&wkah, g_wkva_hi);cudaGetSymbolAddress((void**)&wkal, g_wkva_lo);
    cudaGetSymbolAddress((void**)&wkbh, g_wkvb_hi);cudaGetSymbolAddress((void**)&wkbl, g_wkvb_lo);
    cudaGetSymbolAddress((void**)&woh,  g_wo_hi);  cudaGetSymbolAddress((void**)&wol,  g_wo_lo);
    cudaGetSymbolAddress((void**)&qanh, g_qan_hi); cudaGetSymbolAddress((void**)&qanl, g_qan_lo);
    cudaGetSymbolAddress((void**)&ckh,  g_ckv_hi); cudaGetSymbolAddress((void**)&ckl,  g_ckv_lo);
    cudaGetSymbolAddress((void**)&ath,  g_at_hi);  cudaGetSymbolAddress((void**)&atl,  g_at_lo);
    cudaGetSymbolAddress((void**)&qh,   g_q_hi);   cudaGetSymbolAddress((void**)&ql,   g_q_lo);
    cudaGetSymbolAddress((void**)&kh,   g_k_hi);   cudaGetSymbolAddress((void**)&kl,   g_k_lo);
    cudaGetSymbolAddress((void**)&vh,   g_v_hi);   cudaGetSymbolAddress((void**)&vl,   g_v_lo);

    cudaFuncSetAttribute(gemm_mma,  cudaFuncAttributeMaxDynamicSharedMemorySize, GS_TOTAL);
    cudaFuncSetAttribute(flash_mma, cudaFuncAttributeMaxDynamicSharedMemorySize, F_TOTAL);

    // splits of inputs/weights
    split(x,     xh,   xl,   (size_t)ROWS * DIM);
    split(wq_a,  wqah, wqal, (size_t)QLR * DIM);
    split(wq_b,  wqbh, wqbl, (size_t)QW * QLR);
    split(wkv_a, wkah, wkal, (size_t)KVAW * DIM);
    split(wkv_b, wkbh, wkbl, (size_t)KV2W * KVLR);
    split(wo,    woh,  wol,  (size_t)DIM * OW);

    // q path
    gemm_mma<<<dim3(QLR / 128, ROWS / 128), 256, GS_TOTAL>>>(xh, xl, wqah, wqal, p_qa, QLR, DIM);
    rmsnorm_kernel<<<ROWS, 256>>>(p_qa, qnw, p_qa, QLR, QLR, QLR);
    split(p_qa, qanh, qanl, (size_t)ROWS * QLR);
    gemm_mma<<<dim3(QW / 128, ROWS / 128), 256, GS_TOTAL>>>(qanh, qanl, wqbh, wqbl, p_q, QW, QLR);
    rope_q_kernel<<<ROWS, 512>>>(p_q, fcos, fsin);
    split(p_q, qh, ql, (size_t)ROWS * QW);

    // kv path
    gemm_mma<<<dim3((KVAW + 127) / 128, ROWS / 128), 256, GS_TOTAL>>>(xh, xl, wkah, wkal, p_kv, KVAW, DIM);
    rmsnorm_kernel<<<ROWS, 256>>>(p_kv, kvnw, p_ckvn, KVLR, KVAW, KVLR);
    split(p_ckvn, ckh, ckl, (size_t)ROWS * KVLR);
    gemm_mma<<<dim3(KV2W / 128, ROWS / 128), 256, GS_TOTAL>>>(ckh, ckl, wkbh, wkbl, p_kv2, KV2W, KVLR);
    build_k_kernel<<<ROWS, 256>>>(fcos, fsin);
    split(p_k, kh, kl, (size_t)ROWS * QW);
    split_v_kernel<<<(ROWS * OW) / 256, 256>>>();

    // attention (tensor-core flash)
    flash_mma<<<dim3(SEQ / 128, NH, BSZ), 256, F_TOTAL>>>(qh, ql, kh, kl, vh, vl);

    // output projection
    split(p_attn, ath, atl, (size_t)ROWS * OW);
    gemm_mma<<<dim3(DIM / 128, ROWS / 128), 256, GS_TOTAL>>>(ath, atl, woh, wol, out, DIM, OW);
}

// round 5
// speedup vs baseline: 3.1062x; 1.3690x over previous
#include <cuda_runtime.h>
#include <cuda_fp16.h>
#include <cstdint>
#include <math.h>

// Problem constants
#define BSZ   2
#define SEQ   2048
#define DIM   2048
#define NH    16
#define DRr   64
#define DNn   64
#define DQK   128
#define DVv   128
#define QLR   1536
#define KVLR  1024
#define ROWS  (BSZ*SEQ)          // 4096
#define KVAW  (KVLR + DRr)       // 1088
#define KV2W  (NH*(DNn+DVv))     // 3072
#define QW    (NH*DQK)           // 2048
#define OW    (NH*DVv)           // 2048

// -------- fp32 scratch --------
__device__ float g_qa  [ (size_t)ROWS * QLR  ];
__device__ float g_q   [ (size_t)ROWS * QW   ];
__device__ float g_kv  [ (size_t)ROWS * KVAW ];
__device__ float g_kv2 [ (size_t)ROWS * KV2W ];

// -------- fp16 operands --------
__device__ __half g_xh   [(size_t)ROWS*DIM];
__device__ __half g_wqa_hi[(size_t)QLR*DIM],   g_wqa_lo[(size_t)QLR*DIM];
__device__ __half g_wqb_hi[(size_t)QW*QLR],    g_wqb_lo[(size_t)QW*QLR];
__device__ __half g_wkva_hi[(size_t)KVAW*DIM], g_wkva_lo[(size_t)KVAW*DIM];
__device__ __half g_wkvb_hi[(size_t)KV2W*KVLR],g_wkvb_lo[(size_t)KV2W*KVLR];
__device__ __half g_wo_hi [(size_t)DIM*OW],    g_wo_lo [(size_t)DIM*OW];
__device__ __half g_qanh [(size_t)ROWS*QLR];
__device__ __half g_ckvnh[(size_t)ROWS*KVLR];
__device__ __half g_ath  [(size_t)ROWS*OW];
__device__ __half g_qh   [(size_t)ROWS*QW];
__device__ __half g_khi  [(size_t)ROWS*QW],  g_klo[(size_t)ROWS*QW];
__device__ __half g_vhi  [(size_t)ROWS*OW],  g_vlo[(size_t)ROWS*OW];

// ============================================================
// helpers (sm_80-compatible instructions only — plain sm_103 target!)
// ============================================================
__device__ __forceinline__ uint32_t smem_u32(const void* p) {
    uint32_t a;
    asm("{ .reg .u64 t; cvta.to.shared.u64 t, %1; cvt.u32.u64 %0, t; }" : "=r"(a) : "l"(p));
    return a;
}

#define CP16(dst, src) \
    asm volatile("cp.async.cg.shared.global [%0], [%1], 16;" :: "r"(dst), "l"(src))
#define CP_COMMIT() asm volatile("cp.async.commit_group;" ::: "memory")
#define CP_WAIT(n)  asm volatile("cp.async.wait_group %0;" :: "n"(n) : "memory")

#define LDSM4(r0, r1, r2, r3, addr) \
    asm volatile("ldmatrix.sync.aligned.m8n8.x4.shared.b16 {%0,%1,%2,%3}, [%4];" \
        : "=r"(r0), "=r"(r1), "=r"(r2), "=r"(r3) : "r"(addr))

#define LDSM4T(r0, r1, r2, r3, addr) \
    asm volatile("ldmatrix.sync.aligned.m8n8.x4.trans.shared.b16 {%0,%1,%2,%3}, [%4];" \
        : "=r"(r0), "=r"(r1), "=r"(r2), "=r"(r3) : "r"(addr))

#define MMA_F16(d, a, b0, b1) \
    asm volatile("mma.sync.aligned.m16n8k16.row.col.f32.f16.f16.f32 " \
        "{%0,%1,%2,%3},{%4,%5,%6,%7},{%8,%9},{%0,%1,%2,%3};" \
        : "+f"((d)[0]), "+f"((d)[1]), "+f"((d)[2]), "+f"((d)[3]) \
        : "r"((a)[0]), "r"((a)[1]), "r"((a)[2]), "r"((a)[3]), "r"(b0), "r"(b1))

// ============================================================
// elementwise kernels
// ============================================================
__global__ void split_h_kernel(const float* __restrict__ in,
                               __half* __restrict__ hi, __half* __restrict__ lo, int n)
{
    int i = blockIdx.x * blockDim.x + threadIdx.x;
    if (i < n) {
        float v = in[i];
        __half h = __float2half_rn(v);
        hi[i] = h;
        lo[i] = __float2half_rn(v - __half2float(h));
    }
}

__global__ void conv_h_kernel(const float* __restrict__ in, __half* __restrict__ out, int n)
{
    int i = blockIdx.x * blockDim.x + threadIdx.x;
    if (i < n) out[i] = __float2half_rn(in[i]);
}

// RMSNorm: fp32 in (strided) -> fp16 out
__global__ void rmsnorm_h_kernel(const float* __restrict__ in, const float* __restrict__ w,
                                 __half* __restrict__ out, int K, int inStride)
{
    const int row = blockIdx.x;
    const float* ip = in + (size_t)row * inStride;
    __half* op = out + (size_t)row * K;

    float ss = 0.f;
    for (int i = threadIdx.x; i < K; i += blockDim.x) { float v = ip[i]; ss += v * v; }
#pragma unroll
    for (int o = 16; o; o >>= 1) ss += __shfl_xor_sync(0xffffffffu, ss, o);

    __shared__ float red[8];
    __shared__ float rs;
    int wid = threadIdx.x >> 5, lid = threadIdx.x & 31;
    if (lid == 0) red[wid] = ss;
    __syncthreads();
    if (threadIdx.x == 0) {
        float t = 0.f;
        for (int i = 0; i < 8; i++) t += red[i];
        rs = rsqrtf(t / (float)K + 1e-6f);
    }
    __syncthreads();
    float r = rs;
    for (int i = threadIdx.x; i < K; i += blockDim.x)
        op[i] = __float2half_rn(ip[i] * r * w[i]);
}

// RoPE on q_pe + convert full q row to fp16
__global__ void rope_q_conv_kernel(const float* __restrict__ fcos, const float* __restrict__ fsin)
{
    const int row = blockIdx.x;
    const int p = threadIdx.x;          // 1024 pairs per row
    const int h = p >> 6, j = p & 63;
    const int s = row & (SEQ - 1);
    size_t base = (size_t)row * QW + h * DQK + 2 * j;
    float x0 = g_q[base], x1 = g_q[base + 1];
    if (j >= 32) {
        const int i = j - 32;
        float c = fcos[s * 32 + i], sn = fsin[s * 32 + i];
        float y0 = x0 * c - x1 * sn;
        float y1 = x0 * sn + x1 * c;
        x0 = y0; x1 = y1;
    }
    g_qh[base]     = __float2half_rn(x0);
    g_qh[base + 1] = __float2half_rn(x1);
}

// Build K (split hi/lo fp16): per head [k_nope(64) | rope(k_pe)(64)]
__global__ void build_k_split_kernel(const float* __restrict__ fcos, const float* __restrict__ fsin)
{
    const int row = blockIdx.x;
    const int tid = threadIdx.x;        // 256
    __shared__ float pe[64];
    const int s = row & (SEQ - 1);
    if (tid < 32) {
        float x0 = g_kv[(size_t)row * KVAW + KVLR + 2 * tid];
        float x1 = g_kv[(size_t)row * KVAW + KVLR + 2 * tid + 1];
        float c = fcos[s * 32 + tid], sn = fsin[s * 32 + tid];
        pe[2 * tid]     = x0 * c - x1 * sn;
        pe[2 * tid + 1] = x0 * sn + x1 * c;
    }
    __syncthreads();
#pragma unroll
    for (int l = 0; l < 8; l++) {
        int i = tid + l * 256;
        int h = i >> 7, d = i & 127;
        float v = (d < DNn) ? g_kv2[(size_t)row * KV2W + h * (DNn + DVv) + d] : pe[d - DNn];
        __half hh = __float2half_rn(v);
        g_khi[(size_t)row * QW + i] = hh;
        g_klo[(size_t)row * QW + i] = __float2half_rn(v - __half2float(hh));
    }
}

// split V out of g_kv2 (strided) into fp16 hi/lo
__global__ void split_v_kernel()
{
    int i = blockIdx.x * blockDim.x + threadIdx.x;   // over ROWS*OW
    int row = i >> 11;
    int c   = i & 2047;
    int h = c >> 7, d = c & 127;
    float v = g_kv2[(size_t)row * KV2W + h * (DNn + DVv) + DNn + d];
    __half hh = __float2half_rn(v);
    g_vhi[i] = hh;
    g_vlo[i] = __float2half_rn(v - __half2float(hh));
}

// ============================================================
// 2-term fp16 GEMM via mma.sync: C[M,N] = A[M,K] @ (Whi+Wlo)[N,K]^T
// 128x128x32 tiles, cp.async double buffer, 8 warps (4m x 2n).
// ============================================================
#define GBM 128
#define GBN 128
#define ROWB 80
#define MAT_BYTES (128 * ROWB)         // 10240
#define OFF_A   0
#define OFF_WHI (1 * MAT_BYTES)
#define OFF_WLO (2 * MAT_BYTES)
#define STAGE_BYTES (3 * MAT_BYTES)    // 30720
#define GS_TOTAL (2 * STAGE_BYTES)     // 61440

__global__ void __launch_bounds__(256, 1)
gemm_mma(const __half* __restrict__ A,
         const __half* __restrict__ Whi, const __half* __restrict__ Wlo,
         float* __restrict__ C, int N, int K)
{
    extern __shared__ char smx[];
    const uint32_t sb = smem_u32(smx);
    const int tid  = threadIdx.x;
    const int lane = tid & 31;
    const int warp = tid >> 5;
    const int wm = warp >> 1, wn = warp & 1;
    const int m0 = blockIdx.y * GBM;
    const int n0 = blockIdx.x * GBN;

    const int lrow = tid & 127;
    const int lc   = tid >> 7;
    const size_t a_g = (size_t)(m0 + lrow) * K;
    int wr = n0 + lrow; if (wr >= N) wr = N - 1;
    const size_t w_g = (size_t)wr * K;
    const uint32_t s_row = (uint32_t)lrow * ROWB;

    const uint32_t a_lm = (uint32_t)(wm * 32 + (lane & 15)) * ROWB + (uint32_t)(lane >> 4) * 16;
    const uint32_t b_lm = (uint32_t)(wn * 64 + (lane & 7) + ((lane >> 4) << 3)) * ROWB
                        + (uint32_t)((lane >> 3) & 1) * 16;

    float acc[2][8][4];
#pragma unroll
    for (int i = 0; i < 2; i++)
#pragma unroll
        for (int j = 0; j < 8; j++)
#pragma unroll
            for (int q = 0; q < 4; q++) acc[i][j][q] = 0.f;

    const int nch = K >> 5;

    {
        const uint32_t st = sb + s_row;
#pragma unroll
        for (int u = 0; u < 2; u++) {
            const int cc = lc + u * 2;
            CP16(st + OFF_A   + cc * 16, A   + a_g + cc * 8);
            CP16(st + OFF_WHI + cc * 16, Whi + w_g + cc * 8);
            CP16(st + OFF_WLO + cc * 16, Wlo + w_g + cc * 8);
        }
        CP_COMMIT();
    }

    for (int c = 0; c < nch; c++) {
        const int buf = c & 1;
        if (c + 1 < nch) {
            const int k0 = (c + 1) << 5;
            const uint32_t st = sb + ((c + 1) & 1) * STAGE_BYTES + s_row;
#pragma unroll
            for (int u = 0; u < 2; u++) {
                const int cc = lc + u * 2;
                CP16(st + OFF_A   + cc * 16, A   + a_g + k0 + cc * 8);
                CP16(st + OFF_WHI + cc * 16, Whi + w_g + k0 + cc * 8);
                CP16(st + OFF_WLO + cc * 16, Wlo + w_g + k0 + cc * 8);
            }
            CP_COMMIT();
            CP_WAIT(1);
        } else {
            CP_COMMIT();
            CP_WAIT(0);
        }
        __syncthreads();

        const uint32_t base = sb + buf * STAGE_BYTES;
#pragma unroll
        for (int kk = 0; kk < 2; kk++) {
            uint32_t a[2][4], bh[4][4], bl[4][4];
#pragma unroll
            for (int i = 0; i < 2; i++) {
                const uint32_t ao = base + OFF_A + a_lm + i * (16 * ROWB) + kk * 32;
                LDSM4(a[i][0], a[i][1], a[i][2], a[i][3], ao);
            }
#pragma unroll
            for (int g = 0; g < 4; g++) {
                const uint32_t bo = base + b_lm + g * (16 * ROWB) + kk * 32;
                LDSM4(bh[g][0], bh[g][1], bh[g][2], bh[g][3], bo + OFF_WHI);
                LDSM4(bl[g][0], bl[g][1], bl[g][2], bl[g][3], bo + OFF_WLO);
            }
#pragma unroll
            for (int i = 0; i < 2; i++) {
#pragma unroll
                for (int j = 0; j < 8; j++) {
                    const int g = j >> 1, h = (j & 1) * 2;
                    MMA_F16(acc[i][j], a[i], bh[g][h], bh[g][h + 1]);
                    MMA_F16(acc[i][j], a[i], bl[g][h], bl[g][h + 1]);
                }
            }
        }
        __syncthreads();
    }

#pragma unroll
    for (int i = 0; i < 2; i++) {
        const int row = m0 + wm * 32 + i * 16 + (lane >> 2);
#pragma unroll
        for (int j = 0; j < 8; j++) {
            const int col = n0 + wn * 64 + j * 8 + 2 * (lane & 3);
            if (col < N) {
                *(float2*)&C[(size_t)row * N + col]       = make_float2(acc[i][j][0], acc[i][j][1]);
                *(float2*)&C[(size_t)(row + 8) * N + col] = make_float2(acc[i][j][2], acc[i][j][3]);
            }
        }
    }
}

// ============================================================
// Flash attention — FA2-style, fp16 2-term mma.sync
// BQ=128, BK=64, 8 warps (each owns 16 rows), block 256.
// Q single fp16; K,V split hi/lo. P single fp16.
// ============================================================
#define RB 272
#define FQ    0
#define FK_HI (128*RB)               // 34816
#define FK_LO (FK_HI + 64*RB)
#define FV_HI (FK_LO + 64*RB)
#define FV_LO (FV_HI + 64*RB)
#define F_TOTAL (FV_LO + 64*RB)      // 104448

__global__ void __launch_bounds__(256, 1)
flash_mma(const __half* __restrict__ q16,
          const __half* __restrict__ khi, const __half* __restrict__ klo,
          const __half* __restrict__ vhi, const __half* __restrict__ vlo)
{
    extern __shared__ char smx[];
    const uint32_t sb = smem_u32(smx);
    const int tid = threadIdx.x, lane = tid & 31, wid = tid >> 5;
    const int q0 = blockIdx.x * 128;
    const int h  = blockIdx.y;
    const int b  = blockIdx.z;
    const float scale = 0.088388347648318447f;  // 128^-0.5

    // ---- load Q tile (128 x 128 fp16)
    {
        int r = tid >> 4;
        const int cc = tid & 15;
#pragma unroll
        for (int it = 0; it < 8; it++, r += 16) {
            size_t go = (size_t)(b * SEQ + q0 + r) * QW + h * DQK + cc * 8;
            uint32_t so = (uint32_t)r * RB + cc * 16;
            *(uint4*)(smx + FQ + so) = *(const uint4*)(q16 + go);
        }
    }

    float oacc[16][4];
#pragma unroll
    for (int t = 0; t < 16; t++)
#pragma unroll
        for (int qq = 0; qq < 4; qq++) oacc[t][qq] = 0.f;
    float m0 = -1e30f, m1 = -1e30f, l0 = 0.f, l1 = 0.f;

    const uint32_t a_off  = (uint32_t)(wid * 16 + (lane & 15)) * RB + (uint32_t)(lane >> 4) * 16;
    const uint32_t bK_off = (uint32_t)((lane & 7) + ((lane >> 4) << 3)) * RB
                          + (uint32_t)((lane >> 3) & 1) * 16;
    const uint32_t bV_off = (uint32_t)((lane & 7) + (((lane >> 3) & 1) << 3)) * RB
                          + (uint32_t)(lane >> 4) * 16;

    const int row0 = q0 + wid * 16 + (lane >> 2);
    const int row1 = row0 + 8;

    const int nkt = (blockIdx.x + 1) * 2;
    for (int kt = 0; kt < nkt; kt++) {
        const int t0 = kt * 64;
        __syncthreads();
        {   // load K,V tiles (64 x 128 fp16, hi+lo)
            int r = tid >> 4;
            const int cc = tid & 15;
#pragma unroll
            for (int it = 0; it < 4; it++, r += 16) {
                size_t grow = (size_t)(b * SEQ + t0 + r);
                size_t gk = grow * QW + h * DQK + cc * 8;
                size_t gv = grow * OW + h * DVv + cc * 8;
                uint32_t so = (uint32_t)r * RB + cc * 16;
                *(uint4*)(smx + FK_HI + so) = *(const uint4*)(khi + gk);
                *(uint4*)(smx + FK_LO + so) = *(const uint4*)(klo + gk);
                *(uint4*)(smx + FV_HI + so) = *(const uint4*)(vhi + gv);
                *(uint4*)(smx + FV_LO + so) = *(const uint4*)(vlo + gv);
            }
        }
        __syncthreads();

        // ---- S = Q @ K^T  (warp tile 16 x 64)
        float sacc[8][4];
#pragma unroll
        for (int t = 0; t < 8; t++)
#pragma unroll
            for (int qq = 0; qq < 4; qq++) sacc[t][qq] = 0.f;

#pragma unroll
        for (int kk = 0; kk < 8; kk++) {
            uint32_t aq[4];
            LDSM4(aq[0], aq[1], aq[2], aq[3], sb + FQ + a_off + kk * 32);
#pragma unroll
            for (int g = 0; g < 4; g++) {
                uint32_t bh[4], bl[4];
                const uint32_t bo = bK_off + g * (16 * RB) + kk * 32;
                LDSM4(bh[0], bh[1], bh[2], bh[3], sb + FK_HI + bo);
                LDSM4(bl[0], bl[1], bl[2], bl[3], sb + FK_LO + bo);
                MMA_F16(sacc[2*g],   aq, bh[0], bh[1]);
                MMA_F16(sacc[2*g+1], aq, bh[2], bh[3]);
                MMA_F16(sacc[2*g],   aq, bl[0], bl[1]);
                MMA_F16(sacc[2*g+1], aq, bl[2], bl[3]);
            }
        }

        // ---- scale + causal mask
        const int cb = t0 + 2 * (lane & 3);
#pragma unroll
        for (int t = 0; t < 8; t++) {
            const int c0 = cb + 8 * t, c1 = c0 + 1;
            sacc[t][0] = sacc[t][0] * scale + ((c0 > row0) ? -1e9f : 0.f);
            sacc[t][1] = sacc[t][1] * scale + ((c1 > row0) ? -1e9f : 0.f);
            sacc[t][2] = sacc[t][2] * scale + ((c0 > row1) ? -1e9f : 0.f);
            sacc[t][3] = sacc[t][3] * scale + ((c1 > row1) ? -1e9f : 0.f);
        }

        // ---- online softmax
        float mx0 = -1e30f, mx1 = -1e30f;
#pragma unroll
        for (int t = 0; t < 8; t++) {
            mx0 = fmaxf(mx0, fmaxf(sacc[t][0], sacc[t][1]));
            mx1 = fmaxf(mx1, fmaxf(sacc[t][2], sacc[t][3]));
        }
        mx0 = fmaxf(mx0, __shfl_xor_sync(0xffffffffu, mx0, 1));
        mx0 = fmaxf(mx0, __shfl_xor_sync(0xffffffffu, mx0, 2));
        mx1 = fmaxf(mx1, __shfl_xor_sync(0xffffffffu, mx1, 1));
        mx1 = fmaxf(mx1, __shfl_xor_sync(0xffffffffu, mx1, 2));

        const float mn0 = fmaxf(m0, mx0), mn1 = fmaxf(m1, mx1);
        const float al0 = __expf(m0 - mn0), al1 = __expf(m1 - mn1);
        m0 = mn0; m1 = mn1;

        float ps0 = 0.f, ps1 = 0.f;
#pragma unroll
        for (int t = 0; t < 8; t++) {
            sacc[t][0] = __expf(sacc[t][0] - mn0);
            sacc[t][1] = __expf(sacc[t][1] - mn0);
            sacc[t][2] = __expf(sacc[t][2] - mn1);
            sacc[t][3] = __expf(sacc[t][3] - mn1);
            ps0 += sacc[t][0] + sacc[t][1];
            ps1 += sacc[t][2] + sacc[t][3];
        }
        ps0 += __shfl_xor_sync(0xffffffffu, ps0, 1);
        ps0 += __shfl_xor_sync(0xffffffffu, ps0, 2);
        ps1 += __shfl_xor_sync(0xffffffffu, ps1, 1);
        ps1 += __shfl_xor_sync(0xffffffffu, ps1, 2);
        l0 = l0 * al0 + ps0;
        l1 = l1 * al1 + ps1;

#pragma unroll
        for (int t = 0; t < 16; t++) {
            oacc[t][0] *= al0; oacc[t][1] *= al0;
            oacc[t][2] *= al1; oacc[t][3] *= al1;
        }

        // ---- O += P @ V  (P single fp16; V 2-term split)
#pragma unroll
        for (int jj = 0; jj < 4; jj++) {
            const int t2 = 2 * jj, t3 = 2 * jj + 1;
            uint32_t phi[4];
            {
                __half2 h0 = __floats2half2_rn(sacc[t2][0], sacc[t2][1]);
                __half2 h1 = __floats2half2_rn(sacc[t2][2], sacc[t2][3]);
                __half2 h2 = __floats2half2_rn(sacc[t3][0], sacc[t3][1]);
                __half2 h3 = __floats2half2_rn(sacc[t3][2], sacc[t3][3]);
                phi[0] = *(uint32_t*)&h0; phi[1] = *(uint32_t*)&h1;
                phi[2] = *(uint32_t*)&h2; phi[3] = *(uint32_t*)&h3;
            }
#pragma unroll
            for (int g = 0; g < 8; g++) {
                uint32_t bh[4], bl[4];
                const uint32_t bo = bV_off + jj * (16 * RB) + g * 32;
                LDSM4T(bh[0], bh[1], bh[2], bh[3], sb + FV_HI + bo);
                LDSM4T(bl[0], bl[1], bl[2], bl[3], sb + FV_LO + bo);
                MMA_F16(oacc[2*g],   phi, bh[0], bh[1]);
                MMA_F16(oacc[2*g+1], phi, bh[2], bh[3]);
                MMA_F16(oacc[2*g],   phi, bl[0], bl[1]);
                MMA_F16(oacc[2*g+1], phi, bl[2], bl[3]);
            }
        }
    }

    // ---- epilogue: write fp16 attn directly (A operand of final GEMM)
    const float inv0 = 1.f / l0, inv1 = 1.f / l1;
    const size_t o0 = (size_t)(b * SEQ + row0) * OW + h * DVv;
    const size_t o1 = (size_t)(b * SEQ + row1) * OW + h * DVv;
#pragma unroll
    for (int t = 0; t < 16; t++) {
        const int d0 = 8 * t + 2 * (lane & 3);
        __half2 v0 = __floats2half2_rn(oacc[t][0] * inv0, oacc[t][1] * inv0);
        __half2 v1 = __floats2half2_rn(oacc[t][2] * inv1, oacc[t][3] * inv1);
        *(__half2*)&g_ath[o0 + d0] = v0;
        *(__half2*)&g_ath[o1 + d0] = v1;
    }
}

// ============================================================
// launch
// ============================================================
static inline void splitw(const float* in, __half* hi, __half* lo, size_t n)
{
    split_h_kernel<<<(int)((n + 255) / 256), 256>>>(in, hi, lo, (int)n);
}

extern "C" void kernel_launch(void* const* d_in, const int* in_sizes, int n_in,
                              void* d_out, int out_size)
{
    const float* x      = (const float*)d_in[0];
    const float* wq_a   = (const float*)d_in[1];
    const float* qnw    = (const float*)d_in[2];
    const float* wq_b   = (const float*)d_in[3];
    const float* wkv_a  = (const float*)d_in[4];
    const float* kvnw   = (const float*)d_in[5];
    const float* wkv_b  = (const float*)d_in[6];
    const float* wo     = (const float*)d_in[7];
    const float* fcos   = (const float*)d_in[9];
    const float* fsin   = (const float*)d_in[10];

    float* out = (float*)d_out;

    float *p_qa, *p_q, *p_kv, *p_kv2;
    cudaGetSymbolAddress((void**)&p_qa,   g_qa);
    cudaGetSymbolAddress((void**)&p_q,    g_q);
    cudaGetSymbolAddress((void**)&p_kv,   g_kv);
    cudaGetSymbolAddress((void**)&p_kv2,  g_kv2);

    __half *xh, *wqah, *wqal, *wqbh, *wqbl, *wkah, *wkal, *wkbh, *wkbl, *woh, *wol,
           *qanh, *ckvnh, *ath, *qh, *khi, *klo, *vhi, *vlo;
    cudaGetSymbolAddress((void**)&xh,   g_xh);
    cudaGetSymbolAddress((void**)&wqah, g_wqa_hi); cudaGetSymbolAddress((void**)&wqal, g_wqa_lo);
    cudaGetSymbolAddress((void**)&wqbh, g_wqb_hi); cudaGetSymbolAddress((void**)&wqbl, g_wqb_lo);
    cudaGetSymbolAddress((void**)&wkah, g_wkva_hi);cudaGetSymbolAddress((void**)&wkal, g_wkva_lo);
    cudaGetSymbolAddress((void**)&wkbh, g_wkvb_hi);cudaGetSymbolAddress((void**)&wkbl, g_wkvb_lo);
    cudaGetSymbolAddress((void**)&woh,  g_wo_hi);  cudaGetSymbolAddress((void**)&wol,  g_wo_lo);
    cudaGetSymbolAddress((void**)&qanh, g_qanh);
    cudaGetSymbolAddress((void**)&ckvnh,g_ckvnh);
    cudaGetSymbolAddress((void**)&ath,  g_ath);
    cudaGetSymbolAddress((void**)&qh,   g_qh);
    cudaGetSymbolAddress((void**)&khi,  g_khi);    cudaGetSymbolAddress((void**)&klo,  g_klo);
    cudaGetSymbolAddress((void**)&vhi,  g_vhi);    cudaGetSymbolAddress((void**)&vlo,  g_vlo);

    cudaFuncSetAttribute(gemm_mma,  cudaFuncAttributeMaxDynamicSharedMemorySize, GS_TOTAL);
    cudaFuncSetAttribute(flash_mma, cudaFuncAttributeMaxDynamicSharedMemorySize, F_TOTAL);

    // operand prep
    conv_h_kernel<<<(ROWS * DIM) / 256, 256>>>(x, xh, ROWS * DIM);
    splitw(wq_a,  wqah, wqal, (size_t)QLR * DIM);
    splitw(wq_b,  wqbh, wqbl, (size_t)QW * QLR);
    splitw(wkv_a, wkah, wkal, (size_t)KVAW * DIM);
    splitw(wkv_b, wkbh, wkbl, (size_t)KV2W * KVLR);
    splitw(wo,    woh,  wol,  (size_t)DIM * OW);

    // q path
    gemm_mma<<<dim3(QLR / 128, ROWS / 128), 256, GS_TOTAL>>>(xh, wqah, wqal, p_qa, QLR, DIM);
    rmsnorm_h_kernel<<<ROWS, 256>>>(p_qa, qnw, qanh, QLR, QLR);
    gemm_mma<<<dim3(QW / 128, ROWS / 128), 256, GS_TOTAL>>>(qanh, wqbh, wqbl, p_q, QW, QLR);
    rope_q_conv_kernel<<<ROWS, 1024>>>(fcos, fsin);

    // kv path
    gemm_mma<<<dim3((KVAW + 127) / 128, ROWS / 128), 256, GS_TOTAL>>>(xh, wkah, wkal, p_kv, KVAW, DIM);
    rmsnorm_h_kernel<<<ROWS, 256>>>(p_kv, kvnw, ckvnh, KVLR, KVAW);
    gemm_mma<<<dim3(KV2W / 128, ROWS / 128), 256, GS_TOTAL>>>(ckvnh, wkbh, wkbl, p_kv2, KV2W, KVLR);
    build_k_split_kernel<<<ROWS, 256>>>(fcos, fsin);
    split_v_kernel<<<(ROWS * OW) / 256, 256>>>();

    // attention (tensor-core flash)
    flash_mma<<<dim3(SEQ / 128, NH, BSZ), 256, F_TOTAL>>>(qh, khi, klo, vhi, vlo);

    // output projection
    gemm_mma<<<dim3(DIM / 128, ROWS / 128), 256, GS_TOTAL>>>(ath, woh, wol, out, DIM, OW);
}

// round 6
// speedup vs baseline: 3.5671x; 1.1484x over previous
#include <cuda_runtime.h>
#include <cuda_fp16.h>
#include <cstdint>
#include <math.h>

// Problem constants
#define BSZ   2
#define SEQ   2048
#define DIM   2048
#define NH    16
#define DRr   64
#define DNn   64
#define DQK   128
#define DVv   128
#define QLR   1536
#define KVLR  1024
#define ROWS  (BSZ*SEQ)          // 4096
#define KVAW  (KVLR + DRr)       // 1088
#define KV2W  (NH*(DNn+DVv))     // 3072
#define QW    (NH*DQK)           // 2048
#define OW    (NH*DVv)           // 2048

// -------- fp32 scratch --------
__device__ float g_qa  [ (size_t)ROWS * QLR  ];
__device__ float g_q   [ (size_t)ROWS * QW   ];
__device__ float g_kv  [ (size_t)ROWS * KVAW ];
__device__ float g_kv2 [ (size_t)ROWS * KV2W ];

// -------- fp16 operands --------
__device__ __half g_xh   [(size_t)ROWS*DIM];
__device__ __half g_wqa_hi[(size_t)QLR*DIM],   g_wqa_lo[(size_t)QLR*DIM];
__device__ __half g_wqb_hi[(size_t)QW*QLR],    g_wqb_lo[(size_t)QW*QLR];
__device__ __half g_wkva_hi[(size_t)KVAW*DIM], g_wkva_lo[(size_t)KVAW*DIM];
__device__ __half g_wkvb_hi[(size_t)KV2W*KVLR],g_wkvb_lo[(size_t)KV2W*KVLR];
__device__ __half g_wo_hi [(size_t)DIM*OW],    g_wo_lo [(size_t)DIM*OW];
__device__ __half g_qanh [(size_t)ROWS*QLR];
__device__ __half g_ckvnh[(size_t)ROWS*KVLR];
__device__ __half g_ath  [(size_t)ROWS*OW];
__device__ __half g_qh   [(size_t)ROWS*QW];
__device__ __half g_khi  [(size_t)ROWS*QW],  g_klo[(size_t)ROWS*QW];
__device__ __half g_vhi  [(size_t)ROWS*OW];

// ============================================================
// helpers (sm_80-compatible instructions only — plain sm_103 target!)
// ============================================================
__device__ __forceinline__ uint32_t smem_u32(const void* p) {
    uint32_t a;
    asm("{ .reg .u64 t; cvta.to.shared.u64 t, %1; cvt.u32.u64 %0, t; }" : "=r"(a) : "l"(p));
    return a;
}

#define CP16(dst, src) \
    asm volatile("cp.async.cg.shared.global [%0], [%1], 16;" :: "r"(dst), "l"(src))
#define CP_COMMIT() asm volatile("cp.async.commit_group;" ::: "memory")
#define CP_WAIT(n)  asm volatile("cp.async.wait_group %0;" :: "n"(n) : "memory")

#define LDSM4(r0, r1, r2, r3, addr) \
    asm volatile("ldmatrix.sync.aligned.m8n8.x4.shared.b16 {%0,%1,%2,%3}, [%4];" \
        : "=r"(r0), "=r"(r1), "=r"(r2), "=r"(r3) : "r"(addr))

#define LDSM4T(r0, r1, r2, r3, addr) \
    asm volatile("ldmatrix.sync.aligned.m8n8.x4.trans.shared.b16 {%0,%1,%2,%3}, [%4];" \
        : "=r"(r0), "=r"(r1), "=r"(r2), "=r"(r3) : "r"(addr))

#define MMA_F16(d, a, b0, b1) \
    asm volatile("mma.sync.aligned.m16n8k16.row.col.f32.f16.f16.f32 " \
        "{%0,%1,%2,%3},{%4,%5,%6,%7},{%8,%9},{%0,%1,%2,%3};" \
        : "+f"((d)[0]), "+f"((d)[1]), "+f"((d)[2]), "+f"((d)[3]) \
        : "r"((a)[0]), "r"((a)[1]), "r"((a)[2]), "r"((a)[3]), "r"(b0), "r"(b1))

// ============================================================
// elementwise kernels
// ============================================================
__global__ void split_h_kernel(const float* __restrict__ in,
                               __half* __restrict__ hi, __half* __restrict__ lo, int n)
{
    int i = blockIdx.x * blockDim.x + threadIdx.x;
    if (i < n) {
        float v = in[i];
        __half h = __float2half_rn(v);
        hi[i] = h;
        lo[i] = __float2half_rn(v - __half2float(h));
    }
}

__global__ void conv_h_kernel(const float* __restrict__ in, __half* __restrict__ out, int n)
{
    int i = blockIdx.x * blockDim.x + threadIdx.x;
    if (i < n) out[i] = __float2half_rn(in[i]);
}

// RMSNorm: fp32 in (strided) -> fp16 out
__global__ void rmsnorm_h_kernel(const float* __restrict__ in, const float* __restrict__ w,
                                 __half* __restrict__ out, int K, int inStride)
{
    const int row = blockIdx.x;
    const float* ip = in + (size_t)row * inStride;
    __half* op = out + (size_t)row * K;

    float ss = 0.f;
    for (int i = threadIdx.x; i < K; i += blockDim.x) { float v = ip[i]; ss += v * v; }
#pragma unroll
    for (int o = 16; o; o >>= 1) ss += __shfl_xor_sync(0xffffffffu, ss, o);

    __shared__ float red[8];
    __shared__ float rs;
    int wid = threadIdx.x >> 5, lid = threadIdx.x & 31;
    if (lid == 0) red[wid] = ss;
    __syncthreads();
    if (threadIdx.x == 0) {
        float t = 0.f;
        for (int i = 0; i < 8; i++) t += red[i];
        rs = rsqrtf(t / (float)K + 1e-6f);
    }
    __syncthreads();
    float r = rs;
    for (int i = threadIdx.x; i < K; i += blockDim.x)
        op[i] = __float2half_rn(ip[i] * r * w[i]);
}

// RoPE on q_pe + convert full q row to fp16
__global__ void rope_q_conv_kernel(const float* __restrict__ fcos, const float* __restrict__ fsin)
{
    const int row = blockIdx.x;
    const int p = threadIdx.x;          // 1024 pairs per row
    const int h = p >> 6, j = p & 63;
    const int s = row & (SEQ - 1);
    size_t base = (size_t)row * QW + h * DQK + 2 * j;
    float x0 = g_q[base], x1 = g_q[base + 1];
    if (j >= 32) {
        const int i = j - 32;
        float c = fcos[s * 32 + i], sn = fsin[s * 32 + i];
        float y0 = x0 * c - x1 * sn;
        float y1 = x0 * sn + x1 * c;
        x0 = y0; x1 = y1;
    }
    g_qh[base]     = __float2half_rn(x0);
    g_qh[base + 1] = __float2half_rn(x1);
}

// Build K (split hi/lo fp16) + V (single fp16), one pass over g_kv2
__global__ void build_kv_kernel(const float* __restrict__ fcos, const float* __restrict__ fsin)
{
    const int row = blockIdx.x;
    const int tid = threadIdx.x;        // 256
    __shared__ float pe[64];
    const int s = row & (SEQ - 1);
    if (tid < 32) {
        float x0 = g_kv[(size_t)row * KVAW + KVLR + 2 * tid];
        float x1 = g_kv[(size_t)row * KVAW + KVLR + 2 * tid + 1];
        float c = fcos[s * 32 + tid], sn = fsin[s * 32 + tid];
        pe[2 * tid]     = x0 * c - x1 * sn;
        pe[2 * tid + 1] = x0 * sn + x1 * c;
    }
    __syncthreads();
#pragma unroll
    for (int l = 0; l < 8; l++) {
        int i = tid + l * 256;          // 0..2047
        int h = i >> 7, d = i & 127;
        // K
        float kv = (d < DNn) ? g_kv2[(size_t)row * KV2W + h * (DNn + DVv) + d] : pe[d - DNn];
        __half kh = __float2half_rn(kv);
        g_khi[(size_t)row * QW + i] = kh;
        g_klo[(size_t)row * QW + i] = __float2half_rn(kv - __half2float(kh));
        // V
        float vv = g_kv2[(size_t)row * KV2W + h * (DNn + DVv) + DNn + d];
        g_vhi[(size_t)row * OW + i] = __float2half_rn(vv);
    }
}

// ============================================================
// 2-term fp16 GEMM via mma.sync: C[M,N] = A[M,K] @ (Whi+Wlo)[N,K]^T
// 128x128x32 tiles, 3-stage cp.async pipeline, 8 warps (4m x 2n).
// ============================================================
#define GBM 128
#define GBN 128
#define ROWB 80
#define MAT_BYTES (128 * ROWB)         // 10240
#define OFF_A   0
#define OFF_WHI (1 * MAT_BYTES)
#define OFF_WLO (2 * MAT_BYTES)
#define STAGE_BYTES (3 * MAT_BYTES)    // 30720
#define NSTAGE 3
#define GS_TOTAL (NSTAGE * STAGE_BYTES) // 92160

__global__ void __launch_bounds__(256, 1)
gemm_mma(const __half* __restrict__ A,
         const __half* __restrict__ Whi, const __half* __restrict__ Wlo,
         float* __restrict__ C, int N, int K)
{
    extern __shared__ char smx[];
    const uint32_t sb = smem_u32(smx);
    const int tid  = threadIdx.x;
    const int lane = tid & 31;
    const int warp = tid >> 5;
    const int wm = warp >> 1, wn = warp & 1;
    const int m0 = blockIdx.y * GBM;
    const int n0 = blockIdx.x * GBN;

    const int lrow = tid & 127;
    const int lc   = tid >> 7;
    const size_t a_g = (size_t)(m0 + lrow) * K;
    int wr = n0 + lrow; if (wr >= N) wr = N - 1;
    const size_t w_g = (size_t)wr * K;
    const uint32_t s_row = (uint32_t)lrow * ROWB;

    const uint32_t a_lm = (uint32_t)(wm * 32 + (lane & 15)) * ROWB + (uint32_t)(lane >> 4) * 16;
    const uint32_t b_lm = (uint32_t)(wn * 64 + (lane & 7) + ((lane >> 4) << 3)) * ROWB
                        + (uint32_t)((lane >> 3) & 1) * 16;

    float acc[2][8][4];
#pragma unroll
    for (int i = 0; i < 2; i++)
#pragma unroll
        for (int j = 0; j < 8; j++)
#pragma unroll
            for (int q = 0; q < 4; q++) acc[i][j][q] = 0.f;

    const int nch = K >> 5;

    // prologue: chunks 0,1 into stages 0,1
#pragma unroll
    for (int p = 0; p < NSTAGE - 1; p++) {
        const int k0 = p << 5;
        const uint32_t st = sb + p * STAGE_BYTES + s_row;
#pragma unroll
        for (int u = 0; u < 2; u++) {
            const int cc = lc + u * 2;
            CP16(st + OFF_A   + cc * 16, A   + a_g + k0 + cc * 8);
            CP16(st + OFF_WHI + cc * 16, Whi + w_g + k0 + cc * 8);
            CP16(st + OFF_WLO + cc * 16, Wlo + w_g + k0 + cc * 8);
        }
        CP_COMMIT();
    }

    int stage = 0;
    for (int c = 0; c < nch; c++) {
        CP_WAIT(NSTAGE - 2);          // chunk c resident
        __syncthreads();              // everyone done with stage we're about to overwrite

        if (c + NSTAGE - 1 < nch) {
            const int k0 = (c + NSTAGE - 1) << 5;
            int ws = stage + NSTAGE - 1; if (ws >= NSTAGE) ws -= NSTAGE;
            const uint32_t st = sb + ws * STAGE_BYTES + s_row;
#pragma unroll
            for (int u = 0; u < 2; u++) {
                const int cc = lc + u * 2;
                CP16(st + OFF_A   + cc * 16, A   + a_g + k0 + cc * 8);
                CP16(st + OFF_WHI + cc * 16, Whi + w_g + k0 + cc * 8);
                CP16(st + OFF_WLO + cc * 16, Wlo + w_g + k0 + cc * 8);
            }
        }
        CP_COMMIT();

        const uint32_t base = sb + stage * STAGE_BYTES;
#pragma unroll
        for (int kk = 0; kk < 2; kk++) {
            uint32_t a[2][4], bh[4][4], bl[4][4];
#pragma unroll
            for (int i = 0; i < 2; i++) {
                const uint32_t ao = base + OFF_A + a_lm + i * (16 * ROWB) + kk * 32;
                LDSM4(a[i][0], a[i][1], a[i][2], a[i][3], ao);
            }
#pragma unroll
            for (int g = 0; g < 4; g++) {
                const uint32_t bo = base + b_lm + g * (16 * ROWB) + kk * 32;
                LDSM4(bh[g][0], bh[g][1], bh[g][2], bh[g][3], bo + OFF_WHI);
                LDSM4(bl[g][0], bl[g][1], bl[g][2], bl[g][3], bo + OFF_WLO);
            }
#pragma unroll
            for (int i = 0; i < 2; i++) {
#pragma unroll
                for (int j = 0; j < 8; j++) {
                    const int g = j >> 1, h = (j & 1) * 2;
                    MMA_F16(acc[i][j], a[i], bh[g][h], bh[g][h + 1]);
                    MMA_F16(acc[i][j], a[i], bl[g][h], bl[g][h + 1]);
                }
            }
        }
        if (++stage == NSTAGE) stage = 0;
    }

#pragma unroll
    for (int i = 0; i < 2; i++) {
        const int row = m0 + wm * 32 + i * 16 + (lane >> 2);
#pragma unroll
        for (int j = 0; j < 8; j++) {
            const int col = n0 + wn * 64 + j * 8 + 2 * (lane & 3);
            if (col < N) {
                *(float2*)&C[(size_t)row * N + col]       = make_float2(acc[i][j][0], acc[i][j][1]);
                *(float2*)&C[(size_t)(row + 8) * N + col] = make_float2(acc[i][j][2], acc[i][j][3]);
            }
        }
    }
}

// ============================================================
// Flash attention — FA2-style, fp16 mma.sync
// BQ=128, BK=64, 8 warps, block 256.
// Q fragments in registers; K hi/lo + V single in 3-stage cp.async ring.
// ============================================================
#define RB 272
#define SK_HI 0
#define SK_LO 17408
#define SV    34816
#define FSTG  52224                   // per stage: K_hi + K_lo + V
#define F_TOTAL (3 * FSTG)            // 156672

__global__ void __launch_bounds__(256, 1)
flash_mma(const __half* __restrict__ q16,
          const __half* __restrict__ khi, const __half* __restrict__ klo,
          const __half* __restrict__ vhi)
{
    extern __shared__ char smx[];
    const uint32_t sb = smem_u32(smx);
    const int tid = threadIdx.x, lane = tid & 31, wid = tid >> 5;
    const int q0 = blockIdx.x * 128;
    const int h  = blockIdx.y;
    const int b  = blockIdx.z;
    const float scale = 0.088388347648318447f;  // 128^-0.5

    const uint32_t a_off  = (uint32_t)(wid * 16 + (lane & 15)) * RB + (uint32_t)(lane >> 4) * 16;
    const uint32_t bK_off = (uint32_t)((lane & 7) + ((lane >> 4) << 3)) * RB
                          + (uint32_t)((lane >> 3) & 1) * 16;
    const uint32_t bV_off = (uint32_t)((lane & 7) + (((lane >> 3) & 1) << 3)) * RB
                          + (uint32_t)(lane >> 4) * 16;

    // ---- stage Q tile through smem (stage 0 buffer), hoist fragments to regs
    {
        int r = tid >> 4;
        const int cc = tid & 15;
#pragma unroll
        for (int it = 0; it < 8; it++, r += 16) {
            size_t go = (size_t)(b * SEQ + q0 + r) * QW + h * DQK + cc * 8;
            *(uint4*)(smx + (uint32_t)r * RB + cc * 16) = *(const uint4*)(q16 + go);
        }
    }
    __syncthreads();
    uint32_t aq[8][4];
#pragma unroll
    for (int kk = 0; kk < 8; kk++)
        LDSM4(aq[kk][0], aq[kk][1], aq[kk][2], aq[kk][3], sb + a_off + kk * 32);
    __syncthreads();

    float oacc[16][4];
#pragma unroll
    for (int t = 0; t < 16; t++)
#pragma unroll
        for (int qq = 0; qq < 4; qq++) oacc[t][qq] = 0.f;
    float m0 = -1e30f, m1 = -1e30f, l0 = 0.f, l1 = 0.f;

    const int row0 = q0 + wid * 16 + (lane >> 2);
    const int row1 = row0 + 8;

    const int nkt = (blockIdx.x + 1) * 2;
    const int ldr_r0 = tid >> 4;        // loader: 4 rows per thread, step 16
    const int ldr_c  = tid & 15;

    // prologue: tiles 0,1 into stages 0,1
#pragma unroll
    for (int p = 0; p < 2; p++) {
        const uint32_t stg = sb + p * FSTG;
        int r = ldr_r0;
#pragma unroll
        for (int it = 0; it < 4; it++, r += 16) {
            size_t grow = (size_t)(b * SEQ + p * 64 + r);
            size_t gk = grow * QW + h * DQK + ldr_c * 8;
            size_t gv = grow * OW + h * DVv + ldr_c * 8;
            uint32_t so = (uint32_t)r * RB + ldr_c * 16;
            CP16(stg + SK_HI + so, khi + gk);
            CP16(stg + SK_LO + so, klo + gk);
            CP16(stg + SV    + so, vhi + gv);
        }
        CP_COMMIT();
    }

    int stage = 0;
    for (int kt = 0; kt < nkt; kt++) {
        const int t0 = kt * 64;
        CP_WAIT(1);
        __syncthreads();

        if (kt + 2 < nkt) {
            int ws = stage + 2; if (ws >= 3) ws -= 3;
            const uint32_t stg = sb + ws * FSTG;
            int r = ldr_r0;
#pragma unroll
            for (int it = 0; it < 4; it++, r += 16) {
                size_t grow = (size_t)(b * SEQ + (kt + 2) * 64 + r);
                size_t gk = grow * QW + h * DQK + ldr_c * 8;
                size_t gv = grow * OW + h * DVv + ldr_c * 8;
                uint32_t so = (uint32_t)r * RB + ldr_c * 16;
                CP16(stg + SK_HI + so, khi + gk);
                CP16(stg + SK_LO + so, klo + gk);
                CP16(stg + SV    + so, vhi + gv);
            }
        }
        CP_COMMIT();

        const uint32_t stg = sb + stage * FSTG;

        // ---- S = Q @ K^T  (warp tile 16 x 64; K 2-term)
        float sacc[8][4];
#pragma unroll
        for (int t = 0; t < 8; t++)
#pragma unroll
            for (int qq = 0; qq < 4; qq++) sacc[t][qq] = 0.f;

#pragma unroll
        for (int kk = 0; kk < 8; kk++) {
#pragma unroll
            for (int g = 0; g < 4; g++) {
                uint32_t bh[4], bl[4];
                const uint32_t bo = bK_off + g * (16 * RB) + kk * 32;
                LDSM4(bh[0], bh[1], bh[2], bh[3], stg + SK_HI + bo);
                LDSM4(bl[0], bl[1], bl[2], bl[3], stg + SK_LO + bo);
                MMA_F16(sacc[2*g],   aq[kk], bh[0], bh[1]);
                MMA_F16(sacc[2*g+1], aq[kk], bh[2], bh[3]);
                MMA_F16(sacc[2*g],   aq[kk], bl[0], bl[1]);
                MMA_F16(sacc[2*g+1], aq[kk], bl[2], bl[3]);
            }
        }

        // ---- scale + causal mask
        const int cb = t0 + 2 * (lane & 3);
#pragma unroll
        for (int t = 0; t < 8; t++) {
            const int c0 = cb + 8 * t, c1 = c0 + 1;
            sacc[t][0] = sacc[t][0] * scale + ((c0 > row0) ? -1e9f : 0.f);
            sacc[t][1] = sacc[t][1] * scale + ((c1 > row0) ? -1e9f : 0.f);
            sacc[t][2] = sacc[t][2] * scale + ((c0 > row1) ? -1e9f : 0.f);
            sacc[t][3] = sacc[t][3] * scale + ((c1 > row1) ? -1e9f : 0.f);
        }

        // ---- online softmax
        float mx0 = -1e30f, mx1 = -1e30f;
#pragma unroll
        for (int t = 0; t < 8; t++) {
            mx0 = fmaxf(mx0, fmaxf(sacc[t][0], sacc[t][1]));
            mx1 = fmaxf(mx1, fmaxf(sacc[t][2], sacc[t][3]));
        }
        mx0 = fmaxf(mx0, __shfl_xor_sync(0xffffffffu, mx0, 1));
        mx0 = fmaxf(mx0, __shfl_xor_sync(0xffffffffu, mx0, 2));
        mx1 = fmaxf(mx1, __shfl_xor_sync(0xffffffffu, mx1, 1));
        mx1 = fmaxf(mx1, __shfl_xor_sync(0xffffffffu, mx1, 2));

        const float mn0 = fmaxf(m0, mx0), mn1 = fmaxf(m1, mx1);
        const float al0 = __expf(m0 - mn0), al1 = __expf(m1 - mn1);
        m0 = mn0; m1 = mn1;

        float ps0 = 0.f, ps1 = 0.f;
#pragma unroll
        for (int t = 0; t < 8; t++) {
            sacc[t][0] = __expf(sacc[t][0] - mn0);
            sacc[t][1] = __expf(sacc[t][1] - mn0);
            sacc[t][2] = __expf(sacc[t][2] - mn1);
            sacc[t][3] = __expf(sacc[t][3] - mn1);
            ps0 += sacc[t][0] + sacc[t][1];
            ps1 += sacc[t][2] + sacc[t][3];
        }
        ps0 += __shfl_xor_sync(0xffffffffu, ps0, 1);
        ps0 += __shfl_xor_sync(0xffffffffu, ps0, 2);
        ps1 += __shfl_xor_sync(0xffffffffu, ps1, 1);
        ps1 += __shfl_xor_sync(0xffffffffu, ps1, 2);
        l0 = l0 * al0 + ps0;
        l1 = l1 * al1 + ps1;

#pragma unroll
        for (int t = 0; t < 16; t++) {
            oacc[t][0] *= al0; oacc[t][1] *= al0;
            oacc[t][2] *= al1; oacc[t][3] *= al1;
        }

        // ---- O += P @ V  (P single fp16; V single fp16 — dominated by P rounding)
#pragma unroll
        for (int jj = 0; jj < 4; jj++) {
            const int t2 = 2 * jj, t3 = 2 * jj + 1;
            uint32_t phi[4];
            {
                __half2 h0 = __floats2half2_rn(sacc[t2][0], sacc[t2][1]);
                __half2 h1 = __floats2half2_rn(sacc[t2][2], sacc[t2][3]);
                __half2 h2 = __floats2half2_rn(sacc[t3][0], sacc[t3][1]);
                __half2 h3 = __floats2half2_rn(sacc[t3][2], sacc[t3][3]);
                phi[0] = *(uint32_t*)&h0; phi[1] = *(uint32_t*)&h1;
                phi[2] = *(uint32_t*)&h2; phi[3] = *(uint32_t*)&h3;
            }
#pragma unroll
            for (int g = 0; g < 8; g++) {
                uint32_t bv[4];
                const uint32_t bo = bV_off + jj * (16 * RB) + g * 32;
                LDSM4T(bv[0], bv[1], bv[2], bv[3], stg + SV + bo);
                MMA_F16(oacc[2*g],   phi, bv[0], bv[1]);
                MMA_F16(oacc[2*g+1], phi, bv[2], bv[3]);
            }
        }
        if (++stage == 3) stage = 0;
    }

    // ---- epilogue: write fp16 attn directly (A operand of final GEMM)
    const float inv0 = 1.f / l0, inv1 = 1.f / l1;
    const size_t o0 = (size_t)(b * SEQ + row0) * OW + h * DVv;
    const size_t o1 = (size_t)(b * SEQ + row1) * OW + h * DVv;
#pragma unroll
    for (int t = 0; t < 16; t++) {
        const int d0 = 8 * t + 2 * (lane & 3);
        __half2 v0 = __floats2half2_rn(oacc[t][0] * inv0, oacc[t][1] * inv0);
        __half2 v1 = __floats2half2_rn(oacc[t][2] * inv1, oacc[t][3] * inv1);
        *(__half2*)&g_ath[o0 + d0] = v0;
        *(__half2*)&g_ath[o1 + d0] = v1;
    }
}

// ============================================================
// launch
// ============================================================
static inline void splitw(const float* in, __half* hi, __half* lo, size_t n)
{
    split_h_kernel<<<(int)((n + 255) / 256), 256>>>(in, hi, lo, (int)n);
}

extern "C" void kernel_launch(void* const* d_in, const int* in_sizes, int n_in,
                              void* d_out, int out_size)
{
    const float* x      = (const float*)d_in[0];
    const float* wq_a   = (const float*)d_in[1];
    const float* qnw    = (const float*)d_in[2];
    const float* wq_b   = (const float*)d_in[3];
    const float* wkv_a  = (const float*)d_in[4];
    const float* kvnw   = (const float*)d_in[5];
    const float* wkv_b  = (const float*)d_in[6];
    const float* wo     = (const float*)d_in[7];
    const float* fcos   = (const float*)d_in[9];
    const float* fsin   = (const float*)d_in[10];

    float* out = (float*)d_out;

    float *p_qa, *p_q, *p_kv, *p_kv2;
    cudaGetSymbolAddress((void**)&p_qa,   g_qa);
    cudaGetSymbolAddress((void**)&p_q,    g_q);
    cudaGetSymbolAddress((void**)&p_kv,   g_kv);
    cudaGetSymbolAddress((void**)&p_kv2,  g_kv2);

    __half *xh, *wqah, *wqal, *wqbh, *wqbl, *wkah, *wkal, *wkbh, *wkbl, *woh, *wol,
           *qanh, *ckvnh, *ath, *qh, *khi, *klo, *vhi;
    cudaGetSymbolAddress((void**)&xh,   g_xh);
    cudaGetSymbolAddress((void**)&wqah, g_wqa_hi); cudaGetSymbolAddress((void**)&wqal, g_wqa_lo);
    cudaGetSymbolAddress((void**)&wqbh, g_wqb_hi); cudaGetSymbolAddress((void**)&wqbl, g_wqb_lo);
    cudaGetSymbolAddress((void**)&wkah, g_wkva_hi);cudaGetSymbolAddress((void**)&wkal, g_wkva_lo);
    cudaGetSymbolAddress((void**)&wkbh, g_wkvb_hi);cudaGetSymbolAddress((void**)&wkbl, g_wkvb_lo);
    cudaGetSymbolAddress((void**)&woh,  g_wo_hi);  cudaGetSymbolAddress((void**)&wol,  g_wo_lo);
    cudaGetSymbolAddress((void**)&qanh, g_qanh);
    cudaGetSymbolAddress((void**)&ckvnh,g_ckvnh);
    cudaGetSymbolAddress((void**)&ath,  g_ath);
    cudaGetSymbolAddress((void**)&qh,   g_qh);
    cudaGetSymbolAddress((void**)&khi,  g_khi);    cudaGetSymbolAddress((void**)&klo,  g_klo);
    cudaGetSymbolAddress((void**)&vhi,  g_vhi);

    cudaFuncSetAttribute(gemm_mma,  cudaFuncAttributeMaxDynamicSharedMemorySize, GS_TOTAL);
    cudaFuncSetAttribute(flash_mma, cudaFuncAttributeMaxDynamicSharedMemorySize, F_TOTAL);

    // operand prep
    conv_h_kernel<<<(ROWS * DIM) / 256, 256>>>(x, xh, ROWS * DIM);
    splitw(wq_a,  wqah, wqal, (size_t)QLR * DIM);
    splitw(wq_b,  wqbh, wqbl, (size_t)QW * QLR);
    splitw(wkv_a, wkah, wkal, (size_t)KVAW * DIM);
    splitw(wkv_b, wkbh, wkbl, (size_t)KV2W * KVLR);
    splitw(wo,    woh,  wol,  (size_t)DIM * OW);

    // q path
    gemm_mma<<<dim3(QLR / 128, ROWS / 128), 256, GS_TOTAL>>>(xh, wqah, wqal, p_qa, QLR, DIM);
    rmsnorm_h_kernel<<<ROWS, 256>>>(p_qa, qnw, qanh, QLR, QLR);
    gemm_mma<<<dim3(QW / 128, ROWS / 128), 256, GS_TOTAL>>>(qanh, wqbh, wqbl, p_q, QW, QLR);
    rope_q_conv_kernel<<<ROWS, 1024>>>(fcos, fsin);

    // kv path
    gemm_mma<<<dim3((KVAW + 127) / 128, ROWS / 128), 256, GS_TOTAL>>>(xh, wkah, wkal, p_kv, KVAW, DIM);
    rmsnorm_h_kernel<<<ROWS, 256>>>(p_kv, kvnw, ckvnh, KVLR, KVAW);
    gemm_mma<<<dim3(KV2W / 128, ROWS / 128), 256, GS_TOTAL>>>(ckvnh, wkbh, wkbl, p_kv2, KV2W, KVLR);
    build_kv_kernel<<<ROWS, 256>>>(fcos, fsin);

    // attention (tensor-core flash)
    flash_mma<<<dim3(SEQ / 128, NH, BSZ), 256, F_TOTAL>>>(qh, khi, klo, vhi);

    // output projection
    gemm_mma<<<dim3(DIM / 128, ROWS / 128), 256, GS_TOTAL>>>(ath, woh, wol, out, DIM, OW);
}

// round 7
// speedup vs baseline: 3.9536x; 1.1084x over previous
#include <cuda_runtime.h>
#include <cuda_fp16.h>
#include <cstdint>
#include <math.h>

// Problem constants
#define BSZ   2
#define SEQ   2048
#define DIM   2048
#define NH    16
#define DRr   64
#define DNn   64
#define DQK   128
#define DVv   128
#define QLR   1536
#define KVLR  1024
#define ROWS  (BSZ*SEQ)          // 4096
#define KVAW  (KVLR + DRr)       // 1088
#define KV2W  (NH*(DNn+DVv))     // 3072
#define QW    (NH*DQK)           // 2048
#define OW    (NH*DVv)           // 2048

// -------- fp32 scratch --------
__device__ float g_qa  [ (size_t)ROWS * QLR  ];
__device__ float g_q   [ (size_t)ROWS * QW   ];
__device__ float g_kv  [ (size_t)ROWS * KVAW ];
__device__ float g_kv2 [ (size_t)ROWS * KV2W ];

// -------- fp16 operands --------
__device__ __half g_xh   [(size_t)ROWS*DIM];
__device__ __half g_wqa_hi[(size_t)QLR*DIM],   g_wqa_lo[(size_t)QLR*DIM];
__device__ __half g_wqb_hi[(size_t)QW*QLR],    g_wqb_lo[(size_t)QW*QLR];
__device__ __half g_wkva_hi[(size_t)KVAW*DIM], g_wkva_lo[(size_t)KVAW*DIM];
__device__ __half g_wkvb_hi[(size_t)KV2W*KVLR],g_wkvb_lo[(size_t)KV2W*KVLR];
__device__ __half g_wo_hi [(size_t)DIM*OW],    g_wo_lo [(size_t)DIM*OW];
__device__ __half g_qanh [(size_t)ROWS*QLR];
__device__ __half g_ckvnh[(size_t)ROWS*KVLR];
__device__ __half g_ath  [(size_t)ROWS*OW];
__device__ __half g_qh   [(size_t)ROWS*QW];
__device__ __half g_khi  [(size_t)ROWS*QW],  g_klo[(size_t)ROWS*QW];
__device__ __half g_vhi  [(size_t)ROWS*OW];

// ============================================================
// helpers (sm_80-compatible instructions only — plain sm_103 target!)
// ============================================================
__device__ __forceinline__ uint32_t smem_u32(const void* p) {
    uint32_t a;
    asm("{ .reg .u64 t; cvta.to.shared.u64 t, %1; cvt.u32.u64 %0, t; }" : "=r"(a) : "l"(p));
    return a;
}

#define CP16(dst, src) \
    asm volatile("cp.async.cg.shared.global [%0], [%1], 16;" :: "r"(dst), "l"(src))
#define CP_COMMIT() asm volatile("cp.async.commit_group;" ::: "memory")
#define CP_WAIT(n)  asm volatile("cp.async.wait_group %0;" :: "n"(n) : "memory")

#define LDSM4(r0, r1, r2, r3, addr) \
    asm volatile("ldmatrix.sync.aligned.m8n8.x4.shared.b16 {%0,%1,%2,%3}, [%4];" \
        : "=r"(r0), "=r"(r1), "=r"(r2), "=r"(r3) : "r"(addr))

#define LDSM4T(r0, r1, r2, r3, addr) \
    asm volatile("ldmatrix.sync.aligned.m8n8.x4.trans.shared.b16 {%0,%1,%2,%3}, [%4];" \
        : "=r"(r0), "=r"(r1), "=r"(r2), "=r"(r3) : "r"(addr))

#define MMA_F16(d, a, b0, b1) \
    asm volatile("mma.sync.aligned.m16n8k16.row.col.f32.f16.f16.f32 " \
        "{%0,%1,%2,%3},{%4,%5,%6,%7},{%8,%9},{%0,%1,%2,%3};" \
        : "+f"((d)[0]), "+f"((d)[1]), "+f"((d)[2]), "+f"((d)[3]) \
        : "r"((a)[0]), "r"((a)[1]), "r"((a)[2]), "r"((a)[3]), "r"(b0), "r"(b1))

// ============================================================
// elementwise kernels (vectorized: 4 elems/thread)
// ============================================================
__global__ void split_h4_kernel(const float4* __restrict__ in,
                                uint2* __restrict__ hi, uint2* __restrict__ lo, int n4)
{
    int i = blockIdx.x * blockDim.x + threadIdx.x;
    if (i < n4) {
        float4 v = in[i];
        __half2 h0 = __floats2half2_rn(v.x, v.y);
        __half2 h1 = __floats2half2_rn(v.z, v.w);
        float2 f0 = __half22float2(h0), f1 = __half22float2(h1);
        __half2 e0 = __floats2half2_rn(v.x - f0.x, v.y - f0.y);
        __half2 e1 = __floats2half2_rn(v.z - f1.x, v.w - f1.y);
        hi[i] = make_uint2(*(uint32_t*)&h0, *(uint32_t*)&h1);
        lo[i] = make_uint2(*(uint32_t*)&e0, *(uint32_t*)&e1);
    }
}

__global__ void conv_h4_kernel(const float4* __restrict__ in, uint2* __restrict__ out, int n4)
{
    int i = blockIdx.x * blockDim.x + threadIdx.x;
    if (i < n4) {
        float4 v = in[i];
        __half2 h0 = __floats2half2_rn(v.x, v.y);
        __half2 h1 = __floats2half2_rn(v.z, v.w);
        out[i] = make_uint2(*(uint32_t*)&h0, *(uint32_t*)&h1);
    }
}

// RMSNorm: fp32 in (strided) -> fp16 out, vectorized
__global__ void rmsnorm_h_kernel(const float* __restrict__ in, const float* __restrict__ w,
                                 __half* __restrict__ out, int K, int inStride)
{
    const int row = blockIdx.x;
    const float4* ip4 = (const float4*)(in + (size_t)row * inStride);
    const float4* w4  = (const float4*)w;
    uint2* op4 = (uint2*)(out + (size_t)row * K);
    const int K4 = K >> 2;

    float ss = 0.f;
    for (int i = threadIdx.x; i < K4; i += blockDim.x) {
        float4 v = ip4[i];
        ss += v.x * v.x + v.y * v.y + v.z * v.z + v.w * v.w;
    }
#pragma unroll
    for (int o = 16; o; o >>= 1) ss += __shfl_xor_sync(0xffffffffu, ss, o);

    __shared__ float red[8];
    __shared__ float rs;
    int wid = threadIdx.x >> 5, lid = threadIdx.x & 31;
    if (lid == 0) red[wid] = ss;
    __syncthreads();
    if (threadIdx.x == 0) {
        float t = 0.f;
        for (int i = 0; i < 8; i++) t += red[i];
        rs = rsqrtf(t / (float)K + 1e-6f);
    }
    __syncthreads();
    float r = rs;
    for (int i = threadIdx.x; i < K4; i += blockDim.x) {
        float4 v = ip4[i];
        float4 ww = w4[i];
        __half2 h0 = __floats2half2_rn(v.x * r * ww.x, v.y * r * ww.y);
        __half2 h1 = __floats2half2_rn(v.z * r * ww.z, v.w * r * ww.w);
        op4[i] = make_uint2(*(uint32_t*)&h0, *(uint32_t*)&h1);
    }
}

// RoPE on q_pe + convert full q row to fp16
__global__ void rope_q_conv_kernel(const float* __restrict__ fcos, const float* __restrict__ fsin)
{
    const int row = blockIdx.x;
    const int p = threadIdx.x;          // 1024 pairs per row
    const int h = p >> 6, j = p & 63;
    const int s = row & (SEQ - 1);
    size_t base = (size_t)row * QW + h * DQK + 2 * j;
    float2 xv = *(const float2*)&g_q[base];
    float x0 = xv.x, x1 = xv.y;
    if (j >= 32) {
        const int i = j - 32;
        float c = fcos[s * 32 + i], sn = fsin[s * 32 + i];
        float y0 = x0 * c - x1 * sn;
        float y1 = x0 * sn + x1 * c;
        x0 = y0; x1 = y1;
    }
    __half2 hv = __floats2half2_rn(x0, x1);
    *(__half2*)&g_qh[base] = hv;
}

// Build K (split hi/lo fp16) + V (single fp16), one pass over g_kv2, pair-vectorized
__global__ void build_kv_kernel(const float* __restrict__ fcos, const float* __restrict__ fsin)
{
    const int row = blockIdx.x;
    const int tid = threadIdx.x;        // 256
    __shared__ float pe[64];
    const int s = row & (SEQ - 1);
    if (tid < 32) {
        float x0 = g_kv[(size_t)row * KVAW + KVLR + 2 * tid];
        float x1 = g_kv[(size_t)row * KVAW + KVLR + 2 * tid + 1];
        float c = fcos[s * 32 + tid], sn = fsin[s * 32 + tid];
        pe[2 * tid]     = x0 * c - x1 * sn;
        pe[2 * tid + 1] = x0 * sn + x1 * c;
    }
    __syncthreads();
#pragma unroll
    for (int l = 0; l < 4; l++) {
        int idx = tid + l * 256;        // pair index 0..1023
        int h = idx >> 6, dp = idx & 63;  // d = 2*dp
        // K pair
        float2 kvv;
        if (dp < 32) kvv = *(const float2*)&g_kv2[(size_t)row * KV2W + h * (DNn + DVv) + 2 * dp];
        else         kvv = *(const float2*)&pe[2 * dp - 64];
        __half2 kh = __floats2half2_rn(kvv.x, kvv.y);
        float2 kf = __half22float2(kh);
        __half2 kl = __floats2half2_rn(kvv.x - kf.x, kvv.y - kf.y);
        *(__half2*)&g_khi[(size_t)row * QW + 2 * idx] = kh;
        *(__half2*)&g_klo[(size_t)row * QW + 2 * idx] = kl;
        // V pair
        float2 vv = *(const float2*)&g_kv2[(size_t)row * KV2W + h * (DNn + DVv) + DNn + 2 * dp];
        *(__half2*)&g_vhi[(size_t)row * OW + 2 * idx] = __floats2half2_rn(vv.x, vv.y);
    }
}

// ============================================================
// 2-term fp16 GEMM via mma.sync: C[M,N] = A[M,K] @ (Whi+Wlo)[N,K]^T
// 128x128x32 tiles, 3-stage cp.async pipeline, 8 warps (4m x 2n), occ 2.
// ============================================================
#define GBM 128
#define GBN 128
#define ROWB 80
#define MAT_BYTES (128 * ROWB)         // 10240
#define OFF_A   0
#define OFF_WHI (1 * MAT_BYTES)
#define OFF_WLO (2 * MAT_BYTES)
#define STAGE_BYTES (3 * MAT_BYTES)    // 30720
#define NSTAGE 3
#define GS_TOTAL (NSTAGE * STAGE_BYTES) // 92160

__global__ void __launch_bounds__(256, 2)
gemm_mma(const __half* __restrict__ A,
         const __half* __restrict__ Whi, const __half* __restrict__ Wlo,
         float* __restrict__ C, int N, int K)
{
    extern __shared__ char smx[];
    const uint32_t sb = smem_u32(smx);
    const int tid  = threadIdx.x;
    const int lane = tid & 31;
    const int warp = tid >> 5;
    const int wm = warp >> 1, wn = warp & 1;
    const int m0 = blockIdx.y * GBM;
    const int n0 = blockIdx.x * GBN;

    const int lrow = tid & 127;
    const int lc   = tid >> 7;
    const size_t a_g = (size_t)(m0 + lrow) * K;
    int wr = n0 + lrow; if (wr >= N) wr = N - 1;
    const size_t w_g = (size_t)wr * K;
    const uint32_t s_row = (uint32_t)lrow * ROWB;

    const uint32_t a_lm = (uint32_t)(wm * 32 + (lane & 15)) * ROWB + (uint32_t)(lane >> 4) * 16;
    const uint32_t b_lm = (uint32_t)(wn * 64 + (lane & 7) + ((lane >> 4) << 3)) * ROWB
                        + (uint32_t)((lane >> 3) & 1) * 16;

    float acc[2][8][4];
#pragma unroll
    for (int i = 0; i < 2; i++)
#pragma unroll
        for (int j = 0; j < 8; j++)
#pragma unroll
            for (int q = 0; q < 4; q++) acc[i][j][q] = 0.f;

    const int nch = K >> 5;

    // prologue: chunks 0,1 into stages 0,1
#pragma unroll
    for (int p = 0; p < NSTAGE - 1; p++) {
        const int k0 = p << 5;
        const uint32_t st = sb + p * STAGE_BYTES + s_row;
#pragma unroll
        for (int u = 0; u < 2; u++) {
            const int cc = lc + u * 2;
            CP16(st + OFF_A   + cc * 16, A   + a_g + k0 + cc * 8);
            CP16(st + OFF_WHI + cc * 16, Whi + w_g + k0 + cc * 8);
            CP16(st + OFF_WLO + cc * 16, Wlo + w_g + k0 + cc * 8);
        }
        CP_COMMIT();
    }

    int stage = 0;
    for (int c = 0; c < nch; c++) {
        CP_WAIT(NSTAGE - 2);          // chunk c resident
        __syncthreads();              // everyone done with stage we're about to overwrite

        if (c + NSTAGE - 1 < nch) {
            const int k0 = (c + NSTAGE - 1) << 5;
            int ws = stage + NSTAGE - 1; if (ws >= NSTAGE) ws -= NSTAGE;
            const uint32_t st = sb + ws * STAGE_BYTES + s_row;
#pragma unroll
            for (int u = 0; u < 2; u++) {
                const int cc = lc + u * 2;
                CP16(st + OFF_A   + cc * 16, A   + a_g + k0 + cc * 8);
                CP16(st + OFF_WHI + cc * 16, Whi + w_g + k0 + cc * 8);
                CP16(st + OFF_WLO + cc * 16, Wlo + w_g + k0 + cc * 8);
            }
        }
        CP_COMMIT();

        const uint32_t base = sb + stage * STAGE_BYTES;
#pragma unroll
        for (int kk = 0; kk < 2; kk++) {
            uint32_t a[2][4], bh[4][4], bl[4][4];
#pragma unroll
            for (int i = 0; i < 2; i++) {
                const uint32_t ao = base + OFF_A + a_lm + i * (16 * ROWB) + kk * 32;
                LDSM4(a[i][0], a[i][1], a[i][2], a[i][3], ao);
            }
#pragma unroll
            for (int g = 0; g < 4; g++) {
                const uint32_t bo = base + b_lm + g * (16 * ROWB) + kk * 32;
                LDSM4(bh[g][0], bh[g][1], bh[g][2], bh[g][3], bo + OFF_WHI);
                LDSM4(bl[g][0], bl[g][1], bl[g][2], bl[g][3], bo + OFF_WLO);
            }
#pragma unroll
            for (int i = 0; i < 2; i++) {
#pragma unroll
                for (int j = 0; j < 8; j++) {
                    const int g = j >> 1, h = (j & 1) * 2;
                    MMA_F16(acc[i][j], a[i], bh[g][h], bh[g][h + 1]);
                    MMA_F16(acc[i][j], a[i], bl[g][h], bl[g][h + 1]);
                }
            }
        }
        if (++stage == NSTAGE) stage = 0;
    }

#pragma unroll
    for (int i = 0; i < 2; i++) {
        const int row = m0 + wm * 32 + i * 16 + (lane >> 2);
#pragma unroll
        for (int j = 0; j < 8; j++) {
            const int col = n0 + wn * 64 + j * 8 + 2 * (lane & 3);
            if (col < N) {
                *(float2*)&C[(size_t)row * N + col]       = make_float2(acc[i][j][0], acc[i][j][1]);
                *(float2*)&C[(size_t)(row + 8) * N + col] = make_float2(acc[i][j][2], acc[i][j][3]);
            }
        }
    }
}

// ============================================================
// Flash attention — FA2-style, fp16 mma.sync
// BQ=128, BK=64, 8 warps, block 256.
// Q fragments in registers; K hi/lo + V single in 3-stage cp.async ring.
// ============================================================
#define RB 272
#define SK_HI 0
#define SK_LO 17408
#define SV    34816
#define FSTG  52224                   // per stage: K_hi + K_lo + V
#define F_TOTAL (3 * FSTG)            // 156672

__global__ void __launch_bounds__(256, 1)
flash_mma(const __half* __restrict__ q16,
          const __half* __restrict__ khi, const __half* __restrict__ klo,
          const __half* __restrict__ vhi)
{
    extern __shared__ char smx[];
    const uint32_t sb = smem_u32(smx);
    const int tid = threadIdx.x, lane = tid & 31, wid = tid >> 5;
    const int q0 = blockIdx.x * 128;
    const int h  = blockIdx.y;
    const int b  = blockIdx.z;
    const float scale = 0.088388347648318447f;  // 128^-0.5

    const uint32_t a_off  = (uint32_t)(wid * 16 + (lane & 15)) * RB + (uint32_t)(lane >> 4) * 16;
    const uint32_t bK_off = (uint32_t)((lane & 7) + ((lane >> 4) << 3)) * RB
                          + (uint32_t)((lane >> 3) & 1) * 16;
    const uint32_t bV_off = (uint32_t)((lane & 7) + (((lane >> 3) & 1) << 3)) * RB
                          + (uint32_t)(lane >> 4) * 16;

    // ---- stage Q tile through smem (stage 0 buffer), hoist fragments to regs
    {
        int r = tid >> 4;
        const int cc = tid & 15;
#pragma unroll
        for (int it = 0; it < 8; it++, r += 16) {
            size_t go = (size_t)(b * SEQ + q0 + r) * QW + h * DQK + cc * 8;
            *(uint4*)(smx + (uint32_t)r * RB + cc * 16) = *(const uint4*)(q16 + go);
        }
    }
    __syncthreads();
    uint32_t aq[8][4];
#pragma unroll
    for (int kk = 0; kk < 8; kk++)
        LDSM4(aq[kk][0], aq[kk][1], aq[kk][2], aq[kk][3], sb + a_off + kk * 32);
    __syncthreads();

    float oacc[16][4];
#pragma unroll
    for (int t = 0; t < 16; t++)
#pragma unroll
        for (int qq = 0; qq < 4; qq++) oacc[t][qq] = 0.f;
    float m0 = -1e30f, m1 = -1e30f, l0 = 0.f, l1 = 0.f;

    const int row0 = q0 + wid * 16 + (lane >> 2);
    const int row1 = row0 + 8;

    const int nkt = (blockIdx.x + 1) * 2;
    const int ldr_r0 = tid >> 4;        // loader: 4 rows per thread, step 16
    const int ldr_c  = tid & 15;

    // prologue: tiles 0,1 into stages 0,1
#pragma unroll
    for (int p = 0; p < 2; p++) {
        const uint32_t stg = sb + p * FSTG;
        int r = ldr_r0;
#pragma unroll
        for (int it = 0; it < 4; it++, r += 16) {
            size_t grow = (size_t)(b * SEQ + p * 64 + r);
            size_t gk = grow * QW + h * DQK + ldr_c * 8;
            size_t gv = grow * OW + h * DVv + ldr_c * 8;
            uint32_t so = (uint32_t)r * RB + ldr_c * 16;
            CP16(stg + SK_HI + so, khi + gk);
            CP16(stg + SK_LO + so, klo + gk);
            CP16(stg + SV    + so, vhi + gv);
        }
        CP_COMMIT();
    }

    int stage = 0;
    for (int kt = 0; kt < nkt; kt++) {
        const int t0 = kt * 64;
        CP_WAIT(1);
        __syncthreads();

        if (kt + 2 < nkt) {
            int ws = stage + 2; if (ws >= 3) ws -= 3;
            const uint32_t stg = sb + ws * FSTG;
            int r = ldr_r0;
#pragma unroll
            for (int it = 0; it < 4; it++, r += 16) {
                size_t grow = (size_t)(b * SEQ + (kt + 2) * 64 + r);
                size_t gk = grow * QW + h * DQK + ldr_c * 8;
                size_t gv = grow * OW + h * DVv + ldr_c * 8;
                uint32_t so = (uint32_t)r * RB + ldr_c * 16;
                CP16(stg + SK_HI + so, khi + gk);
                CP16(stg + SK_LO + so, klo + gk);
                CP16(stg + SV    + so, vhi + gv);
            }
        }
        CP_COMMIT();

        const uint32_t stg = sb + stage * FSTG;

        // ---- S = Q @ K^T  (warp tile 16 x 64; K 2-term)
        float sacc[8][4];
#pragma unroll
        for (int t = 0; t < 8; t++)
#pragma unroll
            for (int qq = 0; qq < 4; qq++) sacc[t][qq] = 0.f;

#pragma unroll
        for (int kk = 0; kk < 8; kk++) {
#pragma unroll
            for (int g = 0; g < 4; g++) {
                uint32_t bh[4], bl[4];
                const uint32_t bo = bK_off + g * (16 * RB) + kk * 32;
                LDSM4(bh[0], bh[1], bh[2], bh[3], stg + SK_HI + bo);
                LDSM4(bl[0], bl[1], bl[2], bl[3], stg + SK_LO + bo);
                MMA_F16(sacc[2*g],   aq[kk], bh[0], bh[1]);
                MMA_F16(sacc[2*g+1], aq[kk], bh[2], bh[3]);
                MMA_F16(sacc[2*g],   aq[kk], bl[0], bl[1]);
                MMA_F16(sacc[2*g+1], aq[kk], bl[2], bl[3]);
            }
        }

        // ---- scale + causal mask
        const int cb = t0 + 2 * (lane & 3);
#pragma unroll
        for (int t = 0; t < 8; t++) {
            const int c0 = cb + 8 * t, c1 = c0 + 1;
            sacc[t][0] = sacc[t][0] * scale + ((c0 > row0) ? -1e9f : 0.f);
            sacc[t][1] = sacc[t][1] * scale + ((c1 > row0) ? -1e9f : 0.f);
            sacc[t][2] = sacc[t][2] * scale + ((c0 > row1) ? -1e9f : 0.f);
            sacc[t][3] = sacc[t][3] * scale + ((c1 > row1) ? -1e9f : 0.f);
        }

        // ---- online softmax
        float mx0 = -1e30f, mx1 = -1e30f;
#pragma unroll
        for (int t = 0; t < 8; t++) {
            mx0 = fmaxf(mx0, fmaxf(sacc[t][0], sacc[t][1]));
            mx1 = fmaxf(mx1, fmaxf(sacc[t][2], sacc[t][3]));
        }
        mx0 = fmaxf(mx0, __shfl_xor_sync(0xffffffffu, mx0, 1));
        mx0 = fmaxf(mx0, __shfl_xor_sync(0xffffffffu, mx0, 2));
        mx1 = fmaxf(mx1, __shfl_xor_sync(0xffffffffu, mx1, 1));
        mx1 = fmaxf(mx1, __shfl_xor_sync(0xffffffffu, mx1, 2));

        const float mn0 = fmaxf(m0, mx0), mn1 = fmaxf(m1, mx1);
        const float al0 = __expf(m0 - mn0), al1 = __expf(m1 - mn1);
        m0 = mn0; m1 = mn1;

        float ps0 = 0.f, ps1 = 0.f;
#pragma unroll
        for (int t = 0; t < 8; t++) {
            sacc[t][0] = __expf(sacc[t][0] - mn0);
            sacc[t][1] = __expf(sacc[t][1] - mn0);
            sacc[t][2] = __expf(sacc[t][2] - mn1);
            sacc[t][3] = __expf(sacc[t][3] - mn1);
            ps0 += sacc[t][0] + sacc[t][1];
            ps1 += sacc[t][2] + sacc[t][3];
        }
        ps0 += __shfl_xor_sync(0xffffffffu, ps0, 1);
        ps0 += __shfl_xor_sync(0xffffffffu, ps0, 2);
        ps1 += __shfl_xor_sync(0xffffffffu, ps1, 1);
        ps1 += __shfl_xor_sync(0xffffffffu, ps1, 2);
        l0 = l0 * al0 + ps0;
        l1 = l1 * al1 + ps1;

#pragma unroll
        for (int t = 0; t < 16; t++) {
            oacc[t][0] *= al0; oacc[t][1] *= al0;
            oacc[t][2] *= al1; oacc[t][3] *= al1;
        }

        // ---- O += P @ V  (P single fp16; V single fp16)
#pragma unroll
        for (int jj = 0; jj < 4; jj++) {
            const int t2 = 2 * jj, t3 = 2 * jj + 1;
            uint32_t phi[4];
            {
                __half2 h0 = __floats2half2_rn(sacc[t2][0], sacc[t2][1]);
                __half2 h1 = __floats2half2_rn(sacc[t2][2], sacc[t2][3]);
                __half2 h2 = __floats2half2_rn(sacc[t3][0], sacc[t3][1]);
                __half2 h3 = __floats2half2_rn(sacc[t3][2], sacc[t3][3]);
                phi[0] = *(uint32_t*)&h0; phi[1] = *(uint32_t*)&h1;
                phi[2] = *(uint32_t*)&h2; phi[3] = *(uint32_t*)&h3;
            }
#pragma unroll
            for (int g = 0; g < 8; g++) {
                uint32_t bv[4];
                const uint32_t bo = bV_off + jj * (16 * RB) + g * 32;
                LDSM4T(bv[0], bv[1], bv[2], bv[3], stg + SV + bo);
                MMA_F16(oacc[2*g],   phi, bv[0], bv[1]);
                MMA_F16(oacc[2*g+1], phi, bv[2], bv[3]);
            }
        }
        if (++stage == 3) stage = 0;
    }

    // ---- epilogue: write fp16 attn directly (A operand of final GEMM)
    const float inv0 = 1.f / l0, inv1 = 1.f / l1;
    const size_t o0 = (size_t)(b * SEQ + row0) * OW + h * DVv;
    const size_t o1 = (size_t)(b * SEQ + row1) * OW + h * DVv;
#pragma unroll
    for (int t = 0; t < 16; t++) {
        const int d0 = 8 * t + 2 * (lane & 3);
        __half2 v0 = __floats2half2_rn(oacc[t][0] * inv0, oacc[t][1] * inv0);
        __half2 v1 = __floats2half2_rn(oacc[t][2] * inv1, oacc[t][3] * inv1);
        *(__half2*)&g_ath[o0 + d0] = v0;
        *(__half2*)&g_ath[o1 + d0] = v1;
    }
}

// ============================================================
// launch
// ============================================================
static inline void splitw(const float* in, __half* hi, __half* lo, size_t n)
{
    split_h4_kernel<<<(int)((n / 4 + 255) / 256), 256>>>(
        (const float4*)in, (uint2*)hi, (uint2*)lo, (int)(n / 4));
}

extern "C" void kernel_launch(void* const* d_in, const int* in_sizes, int n_in,
                              void* d_out, int out_size)
{
    const float* x      = (const float*)d_in[0];
    const float* wq_a   = (const float*)d_in[1];
    const float* qnw    = (const float*)d_in[2];
    const float* wq_b   = (const float*)d_in[3];
    const float* wkv_a  = (const float*)d_in[4];
    const float* kvnw   = (const float*)d_in[5];
    const float* wkv_b  = (const float*)d_in[6];
    const float* wo     = (const float*)d_in[7];
    const float* fcos   = (const float*)d_in[9];
    const float* fsin   = (const float*)d_in[10];

    float* out = (float*)d_out;

    float *p_qa, *p_q, *p_kv, *p_kv2;
    cudaGetSymbolAddress((void**)&p_qa,   g_qa);
    cudaGetSymbolAddress((void**)&p_q,    g_q);
    cudaGetSymbolAddress((void**)&p_kv,   g_kv);
    cudaGetSymbolAddress((void**)&p_kv2,  g_kv2);

    __half *xh, *wqah, *wqal, *wqbh, *wqbl, *wkah, *wkal, *wkbh, *wkbl, *woh, *wol,
           *qanh, *ckvnh, *ath, *qh, *khi, *klo, *vhi;
    cudaGetSymbolAddress((void**)&xh,   g_xh);
    cudaGetSymbolAddress((void**)&wqah, g_wqa_hi); cudaGetSymbolAddress((void**)&wqal, g_wqa_lo);
    cudaGetSymbolAddress((void**)&wqbh, g_wqb_hi); cudaGetSymbolAddress((void**)&wqbl, g_wqb_lo);
    cudaGetSymbolAddress((void**)&wkah, g_wkva_hi);cudaGetSymbolAddress((void**)&wkal, g_wkva_lo);
    cudaGetSymbolAddress((void**)&wkbh, g_wkvb_hi);cudaGetSymbolAddress((void**)&wkbl, g_wkvb_lo);
    cudaGetSymbolAddress((void**)&woh,  g_wo_hi);  cudaGetSymbolAddress((void**)&wol,  g_wo_lo);
    cudaGetSymbolAddress((void**)&qanh, g_qanh);
    cudaGetSymbolAddress((void**)&ckvnh,g_ckvnh);
    cudaGetSymbolAddress((void**)&ath,  g_ath);
    cudaGetSymbolAddress((void**)&qh,   g_qh);
    cudaGetSymbolAddress((void**)&khi,  g_khi);    cudaGetSymbolAddress((void**)&klo,  g_klo);
    cudaGetSymbolAddress((void**)&vhi,  g_vhi);

    cudaFuncSetAttribute(gemm_mma,  cudaFuncAttributeMaxDynamicSharedMemorySize, GS_TOTAL);
    cudaFuncSetAttribute(flash_mma, cudaFuncAttributeMaxDynamicSharedMemorySize, F_TOTAL);

    // operand prep
    conv_h4_kernel<<<(ROWS * DIM / 4) / 256, 256>>>((const float4*)x, (uint2*)xh, ROWS * DIM / 4);
    splitw(wq_a,  wqah, wqal, (size_t)QLR * DIM);
    splitw(wq_b,  wqbh, wqbl, (size_t)QW * QLR);
    splitw(wkv_a, wkah, wkal, (size_t)KVAW * DIM);
    splitw(wkv_b, wkbh, wkbl, (size_t)KV2W * KVLR);
    splitw(wo,    woh,  wol,  (size_t)DIM * OW);

    // q path
    gemm_mma<<<dim3(QLR / 128, ROWS / 128), 256, GS_TOTAL>>>(xh, wqah, wqal, p_qa, QLR, DIM);
    rmsnorm_h_kernel<<<ROWS, 256>>>(p_qa, qnw, qanh, QLR, QLR);
    gemm_mma<<<dim3(QW / 128, ROWS / 128), 256, GS_TOTAL>>>(qanh, wqbh, wqbl, p_q, QW, QLR);
    rope_q_conv_kernel<<<ROWS, 1024>>>(fcos, fsin);

    // kv path
    gemm_mma<<<dim3((KVAW + 127) / 128, ROWS / 128), 256, GS_TOTAL>>>(xh, wkah, wkal, p_kv, KVAW, DIM);
    rmsnorm_h_kernel<<<ROWS, 256>>>(p_kv, kvnw, ckvnh, KVLR, KVAW);
    gemm_mma<<<dim3(KV2W / 128, ROWS / 128), 256, GS_TOTAL>>>(ckvnh, wkbh, wkbl, p_kv2, KV2W, KVLR);
    build_kv_kernel<<<ROWS, 256>>>(fcos, fsin);

    // attention (tensor-core flash)
    flash_mma<<<dim3(SEQ / 128, NH, BSZ), 256, F_TOTAL>>>(qh, khi, klo, vhi);

    // output projection
    gemm_mma<<<dim3(DIM / 128, ROWS / 128), 256, GS_TOTAL>>>(ath, woh, wol, out, DIM, OW);
}

// round 9
// speedup vs baseline: 4.1330x; 1.0454x over previous
#include <cuda_runtime.h>
#include <cuda_fp16.h>
#include <cstdint>
#include <math.h>

// Problem constants
#define BSZ   2
#define SEQ   2048
#define DIM   2048
#define NH    16
#define DRr   64
#define DNn   64
#define DQK   128
#define DVv   128
#define QLR   1536
#define KVLR  1024
#define ROWS  (BSZ*SEQ)          // 4096
#define KVAW  (KVLR + DRr)       // 1088
#define KV2W  (NH*(DNn+DVv))     // 3072
#define QW    (NH*DQK)           // 2048
#define OW    (NH*DVv)           // 2048

// -------- fp32 scratch --------
__device__ float g_qa  [ (size_t)ROWS * QLR  ];
__device__ float g_q   [ (size_t)ROWS * QW   ];
__device__ float g_kv  [ (size_t)ROWS * KVAW ];
__device__ float g_kv2 [ (size_t)ROWS * KV2W ];

// -------- fp16 operands --------
__device__ __half g_xh   [(size_t)ROWS*DIM];
__device__ __half g_wqa_hi[(size_t)QLR*DIM],   g_wqa_lo[(size_t)QLR*DIM];
__device__ __half g_wqb_hi[(size_t)QW*QLR],    g_wqb_lo[(size_t)QW*QLR];
__device__ __half g_wkva_hi[(size_t)KVAW*DIM], g_wkva_lo[(size_t)KVAW*DIM];
__device__ __half g_wkvb_hi[(size_t)KV2W*KVLR],g_wkvb_lo[(size_t)KV2W*KVLR];
__device__ __half g_wo_hi [(size_t)DIM*OW],    g_wo_lo [(size_t)DIM*OW];
__device__ __half g_qanh [(size_t)ROWS*QLR];
__device__ __half g_ckvnh[(size_t)ROWS*KVLR];
__device__ __half g_ath  [(size_t)ROWS*OW];
__device__ __half g_qh   [(size_t)ROWS*QW];
__device__ __half g_khi  [(size_t)ROWS*QW];
__device__ __half g_vhi  [(size_t)ROWS*OW];

// ============================================================
// helpers (sm_80-compatible instructions only — plain sm_103 target!)
// ============================================================
__device__ __forceinline__ uint32_t smem_u32(const void* p) {
    uint32_t a;
    asm("{ .reg .u64 t; cvta.to.shared.u64 t, %1; cvt.u32.u64 %0, t; }" : "=r"(a) : "l"(p));
    return a;
}

#define CP16(dst, src) \
    asm volatile("cp.async.cg.shared.global [%0], [%1], 16;" :: "r"(dst), "l"(src))
#define CP_COMMIT() asm volatile("cp.async.commit_group;" ::: "memory")
#define CP_WAIT(n)  asm volatile("cp.async.wait_group %0;" :: "n"(n) : "memory")

#define LDSM4(r0, r1, r2, r3, addr) \
    asm volatile("ldmatrix.sync.aligned.m8n8.x4.shared.b16 {%0,%1,%2,%3}, [%4];" \
        : "=r"(r0), "=r"(r1), "=r"(r2), "=r"(r3) : "r"(addr))

#define LDSM4T(r0, r1, r2, r3, addr) \
    asm volatile("ldmatrix.sync.aligned.m8n8.x4.trans.shared.b16 {%0,%1,%2,%3}, [%4];" \
        : "=r"(r0), "=r"(r1), "=r"(r2), "=r"(r3) : "r"(addr))

#define MMA_F16(d, a, b0, b1) \
    asm volatile("mma.sync.aligned.m16n8k16.row.col.f32.f16.f16.f32 " \
        "{%0,%1,%2,%3},{%4,%5,%6,%7},{%8,%9},{%0,%1,%2,%3};" \
        : "+f"((d)[0]), "+f"((d)[1]), "+f"((d)[2]), "+f"((d)[3]) \
        : "r"((a)[0]), "r"((a)[1]), "r"((a)[2]), "r"((a)[3]), "r"(b0), "r"(b1))

// ============================================================
// elementwise kernels (vectorized: 4 elems/thread)
// ============================================================
__global__ void split_h4_kernel(const float4* __restrict__ in,
                                uint2* __restrict__ hi, uint2* __restrict__ lo, int n4)
{
    int i = blockIdx.x * blockDim.x + threadIdx.x;
    if (i < n4) {
        float4 v = in[i];
        __half2 h0 = __floats2half2_rn(v.x, v.y);
        __half2 h1 = __floats2half2_rn(v.z, v.w);
        float2 f0 = __half22float2(h0), f1 = __half22float2(h1);
        __half2 e0 = __floats2half2_rn(v.x - f0.x, v.y - f0.y);
        __half2 e1 = __floats2half2_rn(v.z - f1.x, v.w - f1.y);
        hi[i] = make_uint2(*(uint32_t*)&h0, *(uint32_t*)&h1);
        lo[i] = make_uint2(*(uint32_t*)&e0, *(uint32_t*)&e1);
    }
}

__global__ void conv_h4_kernel(const float4* __restrict__ in, uint2* __restrict__ out, int n4)
{
    int i = blockIdx.x * blockDim.x + threadIdx.x;
    if (i < n4) {
        float4 v = in[i];
        __half2 h0 = __floats2half2_rn(v.x, v.y);
        __half2 h1 = __floats2half2_rn(v.z, v.w);
        out[i] = make_uint2(*(uint32_t*)&h0, *(uint32_t*)&h1);
    }
}

// RMSNorm: fp32 in (strided) -> fp16 out, vectorized
__global__ void rmsnorm_h_kernel(const float* __restrict__ in, const float* __restrict__ w,
                                 __half* __restrict__ out, int K, int inStride)
{
    const int row = blockIdx.x;
    const float4* ip4 = (const float4*)(in + (size_t)row * inStride);
    const float4* w4  = (const float4*)w;
    uint2* op4 = (uint2*)(out + (size_t)row * K);
    const int K4 = K >> 2;

    float ss = 0.f;
    for (int i = threadIdx.x; i < K4; i += blockDim.x) {
        float4 v = ip4[i];
        ss += v.x * v.x + v.y * v.y + v.z * v.z + v.w * v.w;
    }
#pragma unroll
    for (int o = 16; o; o >>= 1) ss += __shfl_xor_sync(0xffffffffu, ss, o);

    __shared__ float red[8];
    __shared__ float rs;
    int wid = threadIdx.x >> 5, lid = threadIdx.x & 31;
    if (lid == 0) red[wid] = ss;
    __syncthreads();
    if (threadIdx.x == 0) {
        float t = 0.f;
        for (int i = 0; i < 8; i++) t += red[i];
        rs = rsqrtf(t / (float)K + 1e-6f);
    }
    __syncthreads();
    float r = rs;
    for (int i = threadIdx.x; i < K4; i += blockDim.x) {
        float4 v = ip4[i];
        float4 ww = w4[i];
        __half2 h0 = __floats2half2_rn(v.x * r * ww.x, v.y * r * ww.y);
        __half2 h1 = __floats2half2_rn(v.z * r * ww.z, v.w * r * ww.w);
        op4[i] = make_uint2(*(uint32_t*)&h0, *(uint32_t*)&h1);
    }
}

// RoPE on q_pe + convert full q row to fp16
__global__ void rope_q_conv_kernel(const float* __restrict__ fcos, const float* __restrict__ fsin)
{
    const int row = blockIdx.x;
    const int p = threadIdx.x;          // 1024 pairs per row
    const int h = p >> 6, j = p & 63;
    const int s = row & (SEQ - 1);
    size_t base = (size_t)row * QW + h * DQK + 2 * j;
    float2 xv = *(const float2*)&g_q[base];
    float x0 = xv.x, x1 = xv.y;
    if (j >= 32) {
        const int i = j - 32;
        float c = fcos[s * 32 + i], sn = fsin[s * 32 + i];
        float y0 = x0 * c - x1 * sn;
        float y1 = x0 * sn + x1 * c;
        x0 = y0; x1 = y1;
    }
    __half2 hv = __floats2half2_rn(x0, x1);
    *(__half2*)&g_qh[base] = hv;
}

// Build K (single fp16) + V (single fp16), one pass over g_kv2, pair-vectorized
__global__ void build_kv_kernel(const float* __restrict__ fcos, const float* __restrict__ fsin)
{
    const int row = blockIdx.x;
    const int tid = threadIdx.x;        // 256
    __shared__ float pe[64];
    const int s = row & (SEQ - 1);
    if (tid < 32) {
        float x0 = g_kv[(size_t)row * KVAW + KVLR + 2 * tid];
        float x1 = g_kv[(size_t)row * KVAW + KVLR + 2 * tid + 1];
        float c = fcos[s * 32 + tid], sn = fsin[s * 32 + tid];
        pe[2 * tid]     = x0 * c - x1 * sn;
        pe[2 * tid + 1] = x0 * sn + x1 * c;
    }
    __syncthreads();
#pragma unroll
    for (int l = 0; l < 4; l++) {
        int idx = tid + l * 256;        // pair index 0..1023
        int h = idx >> 6, dp = idx & 63;  // d = 2*dp
        // K pair
        float2 kvv;
        if (dp < 32) kvv = *(const float2*)&g_kv2[(size_t)row * KV2W + h * (DNn + DVv) + 2 * dp];
        else         kvv = *(const float2*)&pe[2 * dp - 64];
        *(__half2*)&g_khi[(size_t)row * QW + 2 * idx] = __floats2half2_rn(kvv.x, kvv.y);
        // V pair
        float2 vv = *(const float2*)&g_kv2[(size_t)row * KV2W + h * (DNn + DVv) + DNn + 2 * dp];
        *(__half2*)&g_vhi[(size_t)row * OW + 2 * idx] = __floats2half2_rn(vv.x, vv.y);
    }
}

// ============================================================
// 2-term fp16 GEMM via mma.sync: C[M,N] = A[M,K] @ (Whi+Wlo)[N,K]^T
// 128x128x32 tiles, 3-stage cp.async pipeline, 8 warps (4m x 2n), occ 2.
// ============================================================
#define GBM 128
#define GBN 128
#define ROWB 80
#define MAT_BYTES (128 * ROWB)         // 10240
#define OFF_A   0
#define OFF_WHI (1 * MAT_BYTES)
#define OFF_WLO (2 * MAT_BYTES)
#define STAGE_BYTES (3 * MAT_BYTES)    // 30720
#define NSTAGE 3
#define GS_TOTAL (NSTAGE * STAGE_BYTES) // 92160

__global__ void __launch_bounds__(256, 2)
gemm_mma(const __half* __restrict__ A,
         const __half* __restrict__ Whi, const __half* __restrict__ Wlo,
         float* __restrict__ C, int N, int K)
{
    extern __shared__ char smx[];
    const uint32_t sb = smem_u32(smx);
    const int tid  = threadIdx.x;
    const int lane = tid & 31;
    const int warp = tid >> 5;
    const int wm = warp >> 1, wn = warp & 1;
    const int m0 = blockIdx.y * GBM;
    const int n0 = blockIdx.x * GBN;

    const int lrow = tid & 127;
    const int lc   = tid >> 7;
    const size_t a_g = (size_t)(m0 + lrow) * K;
    int wr = n0 + lrow; if (wr >= N) wr = N - 1;
    const size_t w_g = (size_t)wr * K;
    const uint32_t s_row = (uint32_t)lrow * ROWB;

    const uint32_t a_lm = (uint32_t)(wm * 32 + (lane & 15)) * ROWB + (uint32_t)(lane >> 4) * 16;
    const uint32_t b_lm = (uint32_t)(wn * 64 + (lane & 7) + ((lane >> 4) << 3)) * ROWB
                        + (uint32_t)((lane >> 3) & 1) * 16;

    float acc[2][8][4];
#pragma unroll
    for (int i = 0; i < 2; i++)
#pragma unroll
        for (int j = 0; j < 8; j++)
#pragma unroll
            for (int q = 0; q < 4; q++) acc[i][j][q] = 0.f;

    const int nch = K >> 5;

    // prologue: chunks 0,1 into stages 0,1
#pragma unroll
    for (int p = 0; p < NSTAGE - 1; p++) {
        const int k0 = p << 5;
        const uint32_t st = sb + p * STAGE_BYTES + s_row;
#pragma unroll
        for (int u = 0; u < 2; u++) {
            const int cc = lc + u * 2;
            CP16(st + OFF_A   + cc * 16, A   + a_g + k0 + cc * 8);
            CP16(st + OFF_WHI + cc * 16, Whi + w_g + k0 + cc * 8);
            CP16(st + OFF_WLO + cc * 16, Wlo + w_g + k0 + cc * 8);
        }
        CP_COMMIT();
    }

    int stage = 0;
    for (int c = 0; c < nch; c++) {
        CP_WAIT(NSTAGE - 2);
        __syncthreads();

        if (c + NSTAGE - 1 < nch) {
            const int k0 = (c + NSTAGE - 1) << 5;
            int ws = stage + NSTAGE - 1; if (ws >= NSTAGE) ws -= NSTAGE;
            const uint32_t st = sb + ws * STAGE_BYTES + s_row;
#pragma unroll
            for (int u = 0; u < 2; u++) {
                const int cc = lc + u * 2;
                CP16(st + OFF_A   + cc * 16, A   + a_g + k0 + cc * 8);
                CP16(st + OFF_WHI + cc * 16, Whi + w_g + k0 + cc * 8);
                CP16(st + OFF_WLO + cc * 16, Wlo + w_g + k0 + cc * 8);
            }
        }
        CP_COMMIT();

        const uint32_t base = sb + stage * STAGE_BYTES;
#pragma unroll
        for (int kk = 0; kk < 2; kk++) {
            uint32_t a[2][4], bh[4][4], bl[4][4];
#pragma unroll
            for (int i = 0; i < 2; i++) {
                const uint32_t ao = base + OFF_A + a_lm + i * (16 * ROWB) + kk * 32;
                LDSM4(a[i][0], a[i][1], a[i][2], a[i][3], ao);
            }
#pragma unroll
            for (int g = 0; g < 4; g++) {
                const uint32_t bo = base + b_lm + g * (16 * ROWB) + kk * 32;
                LDSM4(bh[g][0], bh[g][1], bh[g][2], bh[g][3], bo + OFF_WHI);
                LDSM4(bl[g][0], bl[g][1], bl[g][2], bl[g][3], bo + OFF_WLO);
            }
#pragma unroll
            for (int i = 0; i < 2; i++) {
#pragma unroll
                for (int j = 0; j < 8; j++) {
                    const int g = j >> 1, h = (j & 1) * 2;
                    MMA_F16(acc[i][j], a[i], bh[g][h], bh[g][h + 1]);
                    MMA_F16(acc[i][j], a[i], bl[g][h], bl[g][h + 1]);
                }
            }
        }
        if (++stage == NSTAGE) stage = 0;
    }

#pragma unroll
    for (int i = 0; i < 2; i++) {
        const int row = m0 + wm * 32 + i * 16 + (lane >> 2);
#pragma unroll
        for (int j = 0; j < 8; j++) {
            const int col = n0 + wn * 64 + j * 8 + 2 * (lane & 3);
            if (col < N) {
                *(float2*)&C[(size_t)row * N + col]       = make_float2(acc[i][j][0], acc[i][j][1]);
                *(float2*)&C[(size_t)(row + 8) * N + col] = make_float2(acc[i][j][2], acc[i][j][3]);
            }
        }
    }
}

// ============================================================
// Flash attention — FA2-style, fp16 mma.sync, occupancy 3
// BQ=64, BK=64, 4 warps (each owns 16 rows), block 128.
// Q fragments in registers; K + V (single fp16) in 2-stage cp.async ring.
// Prefetch of tile kt+2 goes into the CURRENT stage, strictly AFTER the
// post-compute __syncthreads (all warps done reading). One commit per iter;
// pending groups stay at exactly 2.
// grid: (SEQ/64, NH, BSZ)
// ============================================================
#define RB 272
#define SK    0
#define SV    17408
#define FSTG  34816                   // per stage: K + V
#define F_TOTAL (2 * FSTG)            // 69632

__global__ void __launch_bounds__(128, 3)
flash_mma(const __half* __restrict__ q16,
          const __half* __restrict__ khi, const __half* __restrict__ vhi)
{
    extern __shared__ char smx[];
    const uint32_t sb = smem_u32(smx);
    const int tid = threadIdx.x, lane = tid & 31, wid = tid >> 5;   // 4 warps
    const int q0 = blockIdx.x * 64;
    const int h  = blockIdx.y;
    const int b  = blockIdx.z;
    const float scale = 0.088388347648318447f;  // 128^-0.5

    const uint32_t a_off  = (uint32_t)(wid * 16 + (lane & 15)) * RB + (uint32_t)(lane >> 4) * 16;
    const uint32_t bK_off = (uint32_t)((lane & 7) + ((lane >> 4) << 3)) * RB
                          + (uint32_t)((lane >> 3) & 1) * 16;
    const uint32_t bV_off = (uint32_t)((lane & 7) + (((lane >> 3) & 1) << 3)) * RB
                          + (uint32_t)(lane >> 4) * 16;

    // ---- stage Q tile (64 x 128) through smem stage-0, hoist fragments
    {
        int r = tid >> 4;
        const int cc = tid & 15;
#pragma unroll
        for (int it = 0; it < 8; it++, r += 8) {
            size_t go = (size_t)(b * SEQ + q0 + r) * QW + h * DQK + cc * 8;
            *(uint4*)(smx + (uint32_t)r * RB + cc * 16) = *(const uint4*)(q16 + go);
        }
    }
    __syncthreads();
    uint32_t aq[8][4];
#pragma unroll
    for (int kk = 0; kk < 8; kk++)
        LDSM4(aq[kk][0], aq[kk][1], aq[kk][2], aq[kk][3], sb + a_off + kk * 32);
    __syncthreads();

    float oacc[16][4];
#pragma unroll
    for (int t = 0; t < 16; t++)
#pragma unroll
        for (int qq = 0; qq < 4; qq++) oacc[t][qq] = 0.f;
    float m0 = -1e30f, m1 = -1e30f, l0 = 0.f, l1 = 0.f;

    const int row0 = q0 + wid * 16 + (lane >> 2);
    const int row1 = row0 + 8;

    const int nkt = blockIdx.x + 1;
    const int ldr_r0 = tid >> 4;        // 8 rows per pass, 8 passes
    const int ldr_c  = tid & 15;

    // prologue: tiles 0,1 into stages 0,1 (empty commit when nkt==1)
#pragma unroll
    for (int p = 0; p < 2; p++) {
        if (p < nkt) {
            const uint32_t stg = sb + p * FSTG;
            int r = ldr_r0;
#pragma unroll
            for (int it = 0; it < 8; it++, r += 8) {
                size_t grow = (size_t)(b * SEQ + p * 64 + r);
                size_t gk = grow * QW + h * DQK + ldr_c * 8;
                size_t gv = grow * OW + h * DVv + ldr_c * 8;
                uint32_t so = (uint32_t)r * RB + ldr_c * 16;
                CP16(stg + SK + so, khi + gk);
                CP16(stg + SV + so, vhi + gv);
            }
        }
        CP_COMMIT();
    }

    int stage = 0;
    for (int kt = 0; kt < nkt; kt++) {
        const int t0 = kt * 64;
        CP_WAIT(1);                    // tile kt resident
        __syncthreads();               // make it visible to all warps

        const uint32_t stg = sb + stage * FSTG;

        // ---- S = Q @ K^T  (warp tile 16 x 64; K single term)
        float sacc[8][4];
#pragma unroll
        for (int t = 0; t < 8; t++)
#pragma unroll
            for (int qq = 0; qq < 4; qq++) sacc[t][qq] = 0.f;

#pragma unroll
        for (int kk = 0; kk < 8; kk++) {
#pragma unroll
            for (int g = 0; g < 4; g++) {
                uint32_t bh[4];
                const uint32_t bo = bK_off + g * (16 * RB) + kk * 32;
                LDSM4(bh[0], bh[1], bh[2], bh[3], stg + SK + bo);
                MMA_F16(sacc[2*g],   aq[kk], bh[0], bh[1]);
                MMA_F16(sacc[2*g+1], aq[kk], bh[2], bh[3]);
            }
        }

        // ---- scale + causal mask
        const int cb = t0 + 2 * (lane & 3);
#pragma unroll
        for (int t = 0; t < 8; t++) {
            const int c0 = cb + 8 * t, c1 = c0 + 1;
            sacc[t][0] = sacc[t][0] * scale + ((c0 > row0) ? -1e9f : 0.f);
            sacc[t][1] = sacc[t][1] * scale + ((c1 > row0) ? -1e9f : 0.f);
            sacc[t][2] = sacc[t][2] * scale + ((c0 > row1) ? -1e9f : 0.f);
            sacc[t][3] = sacc[t][3] * scale + ((c1 > row1) ? -1e9f : 0.f);
        }

        // ---- online softmax
        float mx0 = -1e30f, mx1 = -1e30f;
#pragma unroll
        for (int t = 0; t < 8; t++) {
            mx0 = fmaxf(mx0, fmaxf(sacc[t][0], sacc[t][1]));
            mx1 = fmaxf(mx1, fmaxf(sacc[t][2], sacc[t][3]));
        }
        mx0 = fmaxf(mx0, __shfl_xor_sync(0xffffffffu, mx0, 1));
        mx0 = fmaxf(mx0, __shfl_xor_sync(0xffffffffu, mx0, 2));
        mx1 = fmaxf(mx1, __shfl_xor_sync(0xffffffffu, mx1, 1));
        mx1 = fmaxf(mx1, __shfl_xor_sync(0xffffffffu, mx1, 2));

        const float mn0 = fmaxf(m0, mx0), mn1 = fmaxf(m1, mx1);
        const float al0 = __expf(m0 - mn0), al1 = __expf(m1 - mn1);
        m0 = mn0; m1 = mn1;

        float ps0 = 0.f, ps1 = 0.f;
#pragma unroll
        for (int t = 0; t < 8; t++) {
            sacc[t][0] = __expf(sacc[t][0] - mn0);
            sacc[t][1] = __expf(sacc[t][1] - mn0);
            sacc[t][2] = __expf(sacc[t][2] - mn1);
            sacc[t][3] = __expf(sacc[t][3] - mn1);
            ps0 += sacc[t][0] + sacc[t][1];
            ps1 += sacc[t][2] + sacc[t][3];
        }
        ps0 += __shfl_xor_sync(0xffffffffu, ps0, 1);
        ps0 += __shfl_xor_sync(0xffffffffu, ps0, 2);
        ps1 += __shfl_xor_sync(0xffffffffu, ps1, 1);
        ps1 += __shfl_xor_sync(0xffffffffu, ps1, 2);
        l0 = l0 * al0 + ps0;
        l1 = l1 * al1 + ps1;

#pragma unroll
        for (int t = 0; t < 16; t++) {
            oacc[t][0] *= al0; oacc[t][1] *= al0;
            oacc[t][2] *= al1; oacc[t][3] *= al1;
        }

        // ---- O += P @ V
#pragma unroll
        for (int jj = 0; jj < 4; jj++) {
            const int t2 = 2 * jj, t3 = 2 * jj + 1;
            uint32_t phi[4];
            {
                __half2 h0 = __floats2half2_rn(sacc[t2][0], sacc[t2][1]);
                __half2 h1 = __floats2half2_rn(sacc[t2][2], sacc[t2][3]);
                __half2 h2 = __floats2half2_rn(sacc[t3][0], sacc[t3][1]);
                __half2 h3 = __floats2half2_rn(sacc[t3][2], sacc[t3][3]);
                phi[0] = *(uint32_t*)&h0; phi[1] = *(uint32_t*)&h1;
                phi[2] = *(uint32_t*)&h2; phi[3] = *(uint32_t*)&h3;
            }
#pragma unroll
            for (int g = 0; g < 8; g++) {
                uint32_t bv[4];
                const uint32_t bo = bV_off + jj * (16 * RB) + g * 32;
                LDSM4T(bv[0], bv[1], bv[2], bv[3], stg + SV + bo);
                MMA_F16(oacc[2*g],   phi, bv[0], bv[1]);
                MMA_F16(oacc[2*g+1], phi, bv[2], bv[3]);
            }
        }

        // ---- stage fully consumed by ALL warps: now prefetch tile kt+2 into it
        __syncthreads();
        if (kt + 2 < nkt) {
            int r = ldr_r0;
#pragma unroll
            for (int it = 0; it < 8; it++, r += 8) {
                size_t grow = (size_t)(b * SEQ + (kt + 2) * 64 + r);
                size_t gk = grow * QW + h * DQK + ldr_c * 8;
                size_t gv = grow * OW + h * DVv + ldr_c * 8;
                uint32_t so = stg + (uint32_t)r * RB + ldr_c * 16;
                CP16(so + SK, khi + gk);
                CP16(so + SV, vhi + gv);
            }
        }
        CP_COMMIT();
        stage ^= 1;
    }

    // ---- epilogue: write fp16 attn directly (A operand of final GEMM)
    const float inv0 = 1.f / l0, inv1 = 1.f / l1;
    const size_t o0 = (size_t)(b * SEQ + row0) * OW + h * DVv;
    const size_t o1 = (size_t)(b * SEQ + row1) * OW + h * DVv;
#pragma unroll
    for (int t = 0; t < 16; t++) {
        const int d0 = 8 * t + 2 * (lane & 3);
        __half2 v0 = __floats2half2_rn(oacc[t][0] * inv0, oacc[t][1] * inv0);
        __half2 v1 = __floats2half2_rn(oacc[t][2] * inv1, oacc[t][3] * inv1);
        *(__half2*)&g_ath[o0 + d0] = v0;
        *(__half2*)&g_ath[o1 + d0] = v1;
    }
}

// ============================================================
// launch
// ============================================================
static inline void splitw(const float* in, __half* hi, __half* lo, size_t n)
{
    split_h4_kernel<<<(int)((n / 4 + 255) / 256), 256>>>(
        (const float4*)in, (uint2*)hi, (uint2*)lo, (int)(n / 4));
}

extern "C" void kernel_launch(void* const* d_in, const int* in_sizes, int n_in,
                              void* d_out, int out_size)
{
    const float* x      = (const float*)d_in[0];
    const float* wq_a   = (const float*)d_in[1];
    const float* qnw    = (const float*)d_in[2];
    const float* wq_b   = (const float*)d_in[3];
    const float* wkv_a  = (const float*)d_in[4];
    const float* kvnw   = (const float*)d_in[5];
    const float* wkv_b  = (const float*)d_in[6];
    const float* wo     = (const float*)d_in[7];
    const float* fcos   = (const float*)d_in[9];
    const float* fsin   = (const float*)d_in[10];

    float* out = (float*)d_out;

    float *p_qa, *p_q, *p_kv, *p_kv2;
    cudaGetSymbolAddress((void**)&p_qa,   g_qa);
    cudaGetSymbolAddress((void**)&p_q,    g_q);
    cudaGetSymbolAddress((void**)&p_kv,   g_kv);
    cudaGetSymbolAddress((void**)&p_kv2,  g_kv2);

    __half *xh, *wqah, *wqal, *wqbh, *wqbl, *wkah, *wkal, *wkbh, *wkbl, *woh, *wol,
           *qanh, *ckvnh, *ath, *qh, *khi, *vhi;
    cudaGetSymbolAddress((void**)&xh,   g_xh);
    cudaGetSymbolAddress((void**)&wqah, g_wqa_hi); cudaGetSymbolAddress((void**)&wqal, g_wqa_lo);
    cudaGetSymbolAddress((void**)&wqbh, g_wqb_hi); cudaGetSymbolAddress((void**)&wqbl, g_wqb_lo);
    cudaGetSymbolAddress((void**)&wkah, g_wkva_hi);cudaGetSymbolAddress((void**)&wkal, g_wkva_lo);
    cudaGetSymbolAddress((void**)&wkbh, g_wkvb_hi);cudaGetSymbolAddress((void**)&wkbl, g_wkvb_lo);
    cudaGetSymbolAddress((void**)&woh,  g_wo_hi);  cudaGetSymbolAddress((void**)&wol,  g_wo_lo);
    cudaGetSymbolAddress((void**)&qanh, g_qanh);
    cudaGetSymbolAddress((void**)&ckvnh,g_ckvnh);
    cudaGetSymbolAddress((void**)&ath,  g_ath);
    cudaGetSymbolAddress((void**)&qh,   g_qh);
    cudaGetSymbolAddress((void**)&khi,  g_khi);
    cudaGetSymbolAddress((void**)&vhi,  g_vhi);

    cudaFuncSetAttribute(gemm_mma,  cudaFuncAttributeMaxDynamicSharedMemorySize, GS_TOTAL);
    cudaFuncSetAttribute(flash_mma, cudaFuncAttributeMaxDynamicSharedMemorySize, F_TOTAL);

    // operand prep
    conv_h4_kernel<<<(ROWS * DIM / 4) / 256, 256>>>((const float4*)x, (uint2*)xh, ROWS * DIM / 4);
    splitw(wq_a,  wqah, wqal, (size_t)QLR * DIM);
    splitw(wq_b,  wqbh, wqbl, (size_t)QW * QLR);
    splitw(wkv_a, wkah, wkal, (size_t)KVAW * DIM);
    splitw(wkv_b, wkbh, wkbl, (size_t)KV2W * KVLR);
    splitw(wo,    woh,  wol,  (size_t)DIM * OW);

    // q path
    gemm_mma<<<dim3(QLR / 128, ROWS / 128), 256, GS_TOTAL>>>(xh, wqah, wqal, p_qa, QLR, DIM);
    rmsnorm_h_kernel<<<ROWS, 256>>>(p_qa, qnw, qanh, QLR, QLR);
    gemm_mma<<<dim3(QW / 128, ROWS / 128), 256, GS_TOTAL>>>(qanh, wqbh, wqbl, p_q, QW, QLR);
    rope_q_conv_kernel<<<ROWS, 1024>>>(fcos, fsin);

    // kv path
    gemm_mma<<<dim3((KVAW + 127) / 128, ROWS / 128), 256, GS_TOTAL>>>(xh, wkah, wkal, p_kv, KVAW, DIM);
    rmsnorm_h_kernel<<<ROWS, 256>>>(p_kv, kvnw, ckvnh, KVLR, KVAW);
    gemm_mma<<<dim3(KV2W / 128, ROWS / 128), 256, GS_TOTAL>>>(ckvnh, wkbh, wkbl, p_kv2, KV2W, KVLR);
    build_kv_kernel<<<ROWS, 256>>>(fcos, fsin);

    // attention (tensor-core flash, occ 3)
    flash_mma<<<dim3(SEQ / 64, NH, BSZ), 128, F_TOTAL>>>(qh, khi, vhi);

    // output projection
    gemm_mma<<<dim3(DIM / 128, ROWS / 128), 256, GS_TOTAL>>>(ath, woh, wol, out, DIM, OW);
}

// round 10
// speedup vs baseline: 6.0805x; 1.4712x over previous
#include <cuda_runtime.h>
#include <cuda_fp16.h>
#include <cstdint>
#include <math.h>

// Problem constants
#define BSZ   2
#define SEQ   2048
#define DIM   2048
#define NH    16
#define DRr   64
#define DNn   64
#define DQK   128
#define DVv   128
#define QLR   1536
#define KVLR  1024
#define ROWS  (BSZ*SEQ)          // 4096
#define KVAW  (KVLR + DRr)       // 1088
#define KV2W  (NH*(DNn+DVv))     // 3072
#define QW    (NH*DQK)           // 2048
#define OW    (NH*DVv)           // 2048

// -------- fp32 scratch --------
__device__ float g_qa  [ (size_t)ROWS * QLR  ];
__device__ float g_q   [ (size_t)ROWS * QW   ];
__device__ float g_kv  [ (size_t)ROWS * KVAW ];
__device__ float g_kv2 [ (size_t)ROWS * KV2W ];

// -------- fp16 operands --------
__device__ __half g_xh   [(size_t)ROWS*DIM];
__device__ __half g_wqa  [(size_t)QLR*DIM];
__device__ __half g_wqb  [(size_t)QW*QLR];
__device__ __half g_wkva [(size_t)KVAW*DIM];
__device__ __half g_wkvb [(size_t)KV2W*KVLR];
__device__ __half g_wo16 [(size_t)DIM*OW];
__device__ __half g_qanh [(size_t)ROWS*QLR];
__device__ __half g_ckvnh[(size_t)ROWS*KVLR];
__device__ __half g_ath  [(size_t)ROWS*OW];
__device__ __half g_qh   [(size_t)ROWS*QW];
__device__ __half g_khi  [(size_t)ROWS*QW];
__device__ __half g_vhi  [(size_t)ROWS*OW];

// ============================================================
// helpers (sm_80-compatible instructions only — plain sm_103 target!)
// ============================================================
__device__ __forceinline__ uint32_t smem_u32(const void* p) {
    uint32_t a;
    asm("{ .reg .u64 t; cvta.to.shared.u64 t, %1; cvt.u32.u64 %0, t; }" : "=r"(a) : "l"(p));
    return a;
}

#define CP16(dst, src) \
    asm volatile("cp.async.cg.shared.global [%0], [%1], 16;" :: "r"(dst), "l"(src))
#define CP_COMMIT() asm volatile("cp.async.commit_group;" ::: "memory")
#define CP_WAIT(n)  asm volatile("cp.async.wait_group %0;" :: "n"(n) : "memory")

#define LDSM4(r0, r1, r2, r3, addr) \
    asm volatile("ldmatrix.sync.aligned.m8n8.x4.shared.b16 {%0,%1,%2,%3}, [%4];" \
        : "=r"(r0), "=r"(r1), "=r"(r2), "=r"(r3) : "r"(addr))

#define LDSM4T(r0, r1, r2, r3, addr) \
    asm volatile("ldmatrix.sync.aligned.m8n8.x4.trans.shared.b16 {%0,%1,%2,%3}, [%4];" \
        : "=r"(r0), "=r"(r1), "=r"(r2), "=r"(r3) : "r"(addr))

#define MMA_F16(d, a, b0, b1) \
    asm volatile("mma.sync.aligned.m16n8k16.row.col.f32.f16.f16.f32 " \
        "{%0,%1,%2,%3},{%4,%5,%6,%7},{%8,%9},{%0,%1,%2,%3};" \
        : "+f"((d)[0]), "+f"((d)[1]), "+f"((d)[2]), "+f"((d)[3]) \
        : "r"((a)[0]), "r"((a)[1]), "r"((a)[2]), "r"((a)[3]), "r"(b0), "r"(b1))

// ============================================================
// elementwise kernels (vectorized: 4 elems/thread)
// ============================================================
__global__ void conv_h4_kernel(const float4* __restrict__ in, uint2* __restrict__ out, int n4)
{
    int i = blockIdx.x * blockDim.x + threadIdx.x;
    if (i < n4) {
        float4 v = in[i];
        __half2 h0 = __floats2half2_rn(v.x, v.y);
        __half2 h1 = __floats2half2_rn(v.z, v.w);
        out[i] = make_uint2(*(uint32_t*)&h0, *(uint32_t*)&h1);
    }
}

// RMSNorm: fp32 in (strided) -> fp16 out, vectorized
__global__ void rmsnorm_h_kernel(const float* __restrict__ in, const float* __restrict__ w,
                                 __half* __restrict__ out, int K, int inStride)
{
    const int row = blockIdx.x;
    const float4* ip4 = (const float4*)(in + (size_t)row * inStride);
    const float4* w4  = (const float4*)w;
    uint2* op4 = (uint2*)(out + (size_t)row * K);
    const int K4 = K >> 2;

    float ss = 0.f;
    for (int i = threadIdx.x; i < K4; i += blockDim.x) {
        float4 v = ip4[i];
        ss += v.x * v.x + v.y * v.y + v.z * v.z + v.w * v.w;
    }
#pragma unroll
    for (int o = 16; o; o >>= 1) ss += __shfl_xor_sync(0xffffffffu, ss, o);

    __shared__ float red[8];
    __shared__ float rs;
    int wid = threadIdx.x >> 5, lid = threadIdx.x & 31;
    if (lid == 0) red[wid] = ss;
    __syncthreads();
    if (threadIdx.x == 0) {
        float t = 0.f;
        for (int i = 0; i < 8; i++) t += red[i];
        rs = rsqrtf(t / (float)K + 1e-6f);
    }
    __syncthreads();
    float r = rs;
    for (int i = threadIdx.x; i < K4; i += blockDim.x) {
        float4 v = ip4[i];
        float4 ww = w4[i];
        __half2 h0 = __floats2half2_rn(v.x * r * ww.x, v.y * r * ww.y);
        __half2 h1 = __floats2half2_rn(v.z * r * ww.z, v.w * r * ww.w);
        op4[i] = make_uint2(*(uint32_t*)&h0, *(uint32_t*)&h1);
    }
}

// RoPE on q_pe + convert full q row to fp16
__global__ void rope_q_conv_kernel(const float* __restrict__ fcos, const float* __restrict__ fsin)
{
    const int row = blockIdx.x;
    const int p = threadIdx.x;          // 1024 pairs per row
    const int h = p >> 6, j = p & 63;
    const int s = row & (SEQ - 1);
    size_t base = (size_t)row * QW + h * DQK + 2 * j;
    float2 xv = *(const float2*)&g_q[base];
    float x0 = xv.x, x1 = xv.y;
    if (j >= 32) {
        const int i = j - 32;
        float c = fcos[s * 32 + i], sn = fsin[s * 32 + i];
        float y0 = x0 * c - x1 * sn;
        float y1 = x0 * sn + x1 * c;
        x0 = y0; x1 = y1;
    }
    __half2 hv = __floats2half2_rn(x0, x1);
    *(__half2*)&g_qh[base] = hv;
}

// Build K (single fp16) + V (single fp16), one pass over g_kv2, pair-vectorized
__global__ void build_kv_kernel(const float* __restrict__ fcos, const float* __restrict__ fsin)
{
    const int row = blockIdx.x;
    const int tid = threadIdx.x;        // 256
    __shared__ float pe[64];
    const int s = row & (SEQ - 1);
    if (tid < 32) {
        float x0 = g_kv[(size_t)row * KVAW + KVLR + 2 * tid];
        float x1 = g_kv[(size_t)row * KVAW + KVLR + 2 * tid + 1];
        float c = fcos[s * 32 + tid], sn = fsin[s * 32 + tid];
        pe[2 * tid]     = x0 * c - x1 * sn;
        pe[2 * tid + 1] = x0 * sn + x1 * c;
    }
    __syncthreads();
#pragma unroll
    for (int l = 0; l < 4; l++) {
        int idx = tid + l * 256;        // pair index 0..1023
        int h = idx >> 6, dp = idx & 63;  // d = 2*dp
        // K pair
        float2 kvv;
        if (dp < 32) kvv = *(const float2*)&g_kv2[(size_t)row * KV2W + h * (DNn + DVv) + 2 * dp];
        else         kvv = *(const float2*)&pe[2 * dp - 64];
        *(__half2*)&g_khi[(size_t)row * QW + 2 * idx] = __floats2half2_rn(kvv.x, kvv.y);
        // V pair
        float2 vv = *(const float2*)&g_kv2[(size_t)row * KV2W + h * (DNn + DVv) + DNn + 2 * dp];
        *(__half2*)&g_vhi[(size_t)row * OW + 2 * idx] = __floats2half2_rn(vv.x, vv.y);
    }
}

// ============================================================
// single-term fp16 GEMM via mma.sync: C[M,N] = A[M,K] @ W[N,K]^T
// 128x128x32 tiles, 3-stage cp.async pipeline, 8 warps (4m x 2n), occ 2.
// ============================================================
#define GBM 128
#define GBN 128
#define ROWB 80
#define MAT_BYTES (128 * ROWB)         // 10240
#define OFF_A   0
#define OFF_W   (1 * MAT_BYTES)
#define STAGE_BYTES (2 * MAT_BYTES)    // 20480
#define NSTAGE 3
#define GS_TOTAL (NSTAGE * STAGE_BYTES) // 61440

__global__ void __launch_bounds__(256, 2)
gemm_mma(const __half* __restrict__ A, const __half* __restrict__ W,
         float* __restrict__ C, int N, int K)
{
    extern __shared__ char smx[];
    const uint32_t sb = smem_u32(smx);
    const int tid  = threadIdx.x;
    const int lane = tid & 31;
    const int warp = tid >> 5;
    const int wm = warp >> 1, wn = warp & 1;
    const int m0 = blockIdx.y * GBM;
    const int n0 = blockIdx.x * GBN;

    const int lrow = tid & 127;
    const int lc   = tid >> 7;
    const size_t a_g = (size_t)(m0 + lrow) * K;
    int wr = n0 + lrow; if (wr >= N) wr = N - 1;
    const size_t w_g = (size_t)wr * K;
    const uint32_t s_row = (uint32_t)lrow * ROWB;

    const uint32_t a_lm = (uint32_t)(wm * 32 + (lane & 15)) * ROWB + (uint32_t)(lane >> 4) * 16;
    const uint32_t b_lm = (uint32_t)(wn * 64 + (lane & 7) + ((lane >> 4) << 3)) * ROWB
                        + (uint32_t)((lane >> 3) & 1) * 16;

    float acc[2][8][4];
#pragma unroll
    for (int i = 0; i < 2; i++)
#pragma unroll
        for (int j = 0; j < 8; j++)
#pragma unroll
            for (int q = 0; q < 4; q++) acc[i][j][q] = 0.f;

    const int nch = K >> 5;

    // prologue: chunks 0,1 into stages 0,1
#pragma unroll
    for (int p = 0; p < NSTAGE - 1; p++) {
        const int k0 = p << 5;
        const uint32_t st = sb + p * STAGE_BYTES + s_row;
#pragma unroll
        for (int u = 0; u < 2; u++) {
            const int cc = lc + u * 2;
            CP16(st + OFF_A + cc * 16, A + a_g + k0 + cc * 8);
            CP16(st + OFF_W + cc * 16, W + w_g + k0 + cc * 8);
        }
        CP_COMMIT();
    }

    int stage = 0;
    for (int c = 0; c < nch; c++) {
        CP_WAIT(NSTAGE - 2);
        __syncthreads();

        if (c + NSTAGE - 1 < nch) {
            const int k0 = (c + NSTAGE - 1) << 5;
            int ws = stage + NSTAGE - 1; if (ws >= NSTAGE) ws -= NSTAGE;
            const uint32_t st = sb + ws * STAGE_BYTES + s_row;
#pragma unroll
            for (int u = 0; u < 2; u++) {
                const int cc = lc + u * 2;
                CP16(st + OFF_A + cc * 16, A + a_g + k0 + cc * 8);
                CP16(st + OFF_W + cc * 16, W + w_g + k0 + cc * 8);
            }
        }
        CP_COMMIT();

        const uint32_t base = sb + stage * STAGE_BYTES;
#pragma unroll
        for (int kk = 0; kk < 2; kk++) {
            uint32_t a[2][4], bh[4][4];
#pragma unroll
            for (int i = 0; i < 2; i++) {
                const uint32_t ao = base + OFF_A + a_lm + i * (16 * ROWB) + kk * 32;
                LDSM4(a[i][0], a[i][1], a[i][2], a[i][3], ao);
            }
#pragma unroll
            for (int g = 0; g < 4; g++) {
                const uint32_t bo = base + OFF_W + b_lm + g * (16 * ROWB) + kk * 32;
                LDSM4(bh[g][0], bh[g][1], bh[g][2], bh[g][3], bo);
            }
#pragma unroll
            for (int i = 0; i < 2; i++) {
#pragma unroll
                for (int j = 0; j < 8; j++) {
                    const int g = j >> 1, h = (j & 1) * 2;
                    MMA_F16(acc[i][j], a[i], bh[g][h], bh[g][h + 1]);
                }
            }
        }
        if (++stage == NSTAGE) stage = 0;
    }

#pragma unroll
    for (int i = 0; i < 2; i++) {
        const int row = m0 + wm * 32 + i * 16 + (lane >> 2);
#pragma unroll
        for (int j = 0; j < 8; j++) {
            const int col = n0 + wn * 64 + j * 8 + 2 * (lane & 3);
            if (col < N) {
                *(float2*)&C[(size_t)row * N + col]       = make_float2(acc[i][j][0], acc[i][j][1]);
                *(float2*)&C[(size_t)(row + 8) * N + col] = make_float2(acc[i][j][2], acc[i][j][3]);
            }
        }
    }
}

// ============================================================
// Flash attention — FA2-style, fp16 mma.sync, occupancy 3
// BQ=64, BK=64, 4 warps (each owns 16 rows), block 128.
// Q fragments in registers; K + V (single fp16) in 2-stage cp.async ring.
// Prefetch of tile kt+2 goes into the CURRENT stage, strictly AFTER the
// post-compute __syncthreads. One commit per iter; pending groups stay at 2.
// grid: (SEQ/64, NH, BSZ)
// ============================================================
#define RB 272
#define SK    0
#define SV    17408
#define FSTG  34816                   // per stage: K + V
#define F_TOTAL (2 * FSTG)            // 69632

__global__ void __launch_bounds__(128, 3)
flash_mma(const __half* __restrict__ q16,
          const __half* __restrict__ khi, const __half* __restrict__ vhi)
{
    extern __shared__ char smx[];
    const uint32_t sb = smem_u32(smx);
    const int tid = threadIdx.x, lane = tid & 31, wid = tid >> 5;   // 4 warps
    const int q0 = blockIdx.x * 64;
    const int h  = blockIdx.y;
    const int b  = blockIdx.z;
    const float scale = 0.088388347648318447f;  // 128^-0.5

    const uint32_t a_off  = (uint32_t)(wid * 16 + (lane & 15)) * RB + (uint32_t)(lane >> 4) * 16;
    const uint32_t bK_off = (uint32_t)((lane & 7) + ((lane >> 4) << 3)) * RB
                          + (uint32_t)((lane >> 3) & 1) * 16;
    const uint32_t bV_off = (uint32_t)((lane & 7) + (((lane >> 3) & 1) << 3)) * RB
                          + (uint32_t)(lane >> 4) * 16;

    // ---- stage Q tile (64 x 128) through smem stage-0, hoist fragments
    {
        int r = tid >> 4;
        const int cc = tid & 15;
#pragma unroll
        for (int it = 0; it < 8; it++, r += 8) {
            size_t go = (size_t)(b * SEQ + q0 + r) * QW + h * DQK + cc * 8;
            *(uint4*)(smx + (uint32_t)r * RB + cc * 16) = *(const uint4*)(q16 + go);
        }
    }
    __syncthreads();
    uint32_t aq[8][4];
#pragma unroll
    for (int kk = 0; kk < 8; kk++)
        LDSM4(aq[kk][0], aq[kk][1], aq[kk][2], aq[kk][3], sb + a_off + kk * 32);
    __syncthreads();

    float oacc[16][4];
#pragma unroll
    for (int t = 0; t < 16; t++)
#pragma unroll
        for (int qq = 0; qq < 4; qq++) oacc[t][qq] = 0.f;
    float m0 = -1e30f, m1 = -1e30f, l0 = 0.f, l1 = 0.f;

    const int row0 = q0 + wid * 16 + (lane >> 2);
    const int row1 = row0 + 8;

    const int nkt = blockIdx.x + 1;
    const int ldr_r0 = tid >> 4;        // 8 rows per pass, 8 passes
    const int ldr_c  = tid & 15;

    // prologue: tiles 0,1 into stages 0,1 (empty commit when nkt==1)
#pragma unroll
    for (int p = 0; p < 2; p++) {
        if (p < nkt) {
            const uint32_t stg = sb + p * FSTG;
            int r = ldr_r0;
#pragma unroll
            for (int it = 0; it < 8; it++, r += 8) {
                size_t grow = (size_t)(b * SEQ + p * 64 + r);
                size_t gk = grow * QW + h * DQK + ldr_c * 8;
                size_t gv = grow * OW + h * DVv + ldr_c * 8;
                uint32_t so = (uint32_t)r * RB + ldr_c * 16;
                CP16(stg + SK + so, khi + gk);
                CP16(stg + SV + so, vhi + gv);
            }
        }
        CP_COMMIT();
    }

    int stage = 0;
    for (int kt = 0; kt < nkt; kt++) {
        const int t0 = kt * 64;
        CP_WAIT(1);                    // tile kt resident
        __syncthreads();               // make it visible to all warps

        const uint32_t stg = sb + stage * FSTG;

        // ---- S = Q @ K^T  (warp tile 16 x 64)
        float sacc[8][4];
#pragma unroll
        for (int t = 0; t < 8; t++)
#pragma unroll
            for (int qq = 0; qq < 4; qq++) sacc[t][qq] = 0.f;

#pragma unroll
        for (int kk = 0; kk < 8; kk++) {
#pragma unroll
            for (int g = 0; g < 4; g++) {
                uint32_t bh[4];
                const uint32_t bo = bK_off + g * (16 * RB) + kk * 32;
                LDSM4(bh[0], bh[1], bh[2], bh[3], stg + SK + bo);
                MMA_F16(sacc[2*g],   aq[kk], bh[0], bh[1]);
                MMA_F16(sacc[2*g+1], aq[kk], bh[2], bh[3]);
            }
        }

        // ---- scale + causal mask
        const int cb = t0 + 2 * (lane & 3);
#pragma unroll
        for (int t = 0; t < 8; t++) {
            const int c0 = cb + 8 * t, c1 = c0 + 1;
            sacc[t][0] = sacc[t][0] * scale + ((c0 > row0) ? -1e9f : 0.f);
            sacc[t][1] = sacc[t][1] * scale + ((c1 > row0) ? -1e9f : 0.f);
            sacc[t][2] = sacc[t][2] * scale + ((c0 > row1) ? -1e9f : 0.f);
            sacc[t][3] = sacc[t][3] * scale + ((c1 > row1) ? -1e9f : 0.f);
        }

        // ---- online softmax
        float mx0 = -1e30f, mx1 = -1e30f;
#pragma unroll
        for (int t = 0; t < 8; t++) {
            mx0 = fmaxf(mx0, fmaxf(sacc[t][0], sacc[t][1]));
            mx1 = fmaxf(mx1, fmaxf(sacc[t][2], sacc[t][3]));
        }
        mx0 = fmaxf(mx0, __shfl_xor_sync(0xffffffffu, mx0, 1));
        mx0 = fmaxf(mx0, __shfl_xor_sync(0xffffffffu, mx0, 2));
        mx1 = fmaxf(mx1, __shfl_xor_sync(0xffffffffu, mx1, 1));
        mx1 = fmaxf(mx1, __shfl_xor_sync(0xffffffffu, mx1, 2));

        const float mn0 = fmaxf(m0, mx0), mn1 = fmaxf(m1, mx1);
        const float al0 = __expf(m0 - mn0), al1 = __expf(m1 - mn1);
        m0 = mn0; m1 = mn1;

        float ps0 = 0.f, ps1 = 0.f;
#pragma unroll
        for (int t = 0; t < 8; t++) {
            sacc[t][0] = __expf(sacc[t][0] - mn0);
            sacc[t][1] = __expf(sacc[t][1] - mn0);
            sacc[t][2] = __expf(sacc[t][2] - mn1);
            sacc[t][3] = __expf(sacc[t][3] - mn1);
            ps0 += sacc[t][0] + sacc[t][1];
            ps1 += sacc[t][2] + sacc[t][3];
        }
        ps0 += __shfl_xor_sync(0xffffffffu, ps0, 1);
        ps0 += __shfl_xor_sync(0xffffffffu, ps0, 2);
        ps1 += __shfl_xor_sync(0xffffffffu, ps1, 1);
        ps1 += __shfl_xor_sync(0xffffffffu, ps1, 2);
        l0 = l0 * al0 + ps0;
        l1 = l1 * al1 + ps1;

#pragma unroll
        for (int t = 0; t < 16; t++) {
            oacc[t][0] *= al0; oacc[t][1] *= al0;
            oacc[t][2] *= al1; oacc[t][3] *= al1;
        }

        // ---- O += P @ V
#pragma unroll
        for (int jj = 0; jj < 4; jj++) {
            const int t2 = 2 * jj, t3 = 2 * jj + 1;
            uint32_t phi[4];
            {
                __half2 h0 = __floats2half2_rn(sacc[t2][0], sacc[t2][1]);
                __half2 h1 = __floats2half2_rn(sacc[t2][2], sacc[t2][3]);
                __half2 h2 = __floats2half2_rn(sacc[t3][0], sacc[t3][1]);
                __half2 h3 = __floats2half2_rn(sacc[t3][2], sacc[t3][3]);
                phi[0] = *(uint32_t*)&h0; phi[1] = *(uint32_t*)&h1;
                phi[2] = *(uint32_t*)&h2; phi[3] = *(uint32_t*)&h3;
            }
#pragma unroll
            for (int g = 0; g < 8; g++) {
                uint32_t bv[4];
                const uint32_t bo = bV_off + jj * (16 * RB) + g * 32;
                LDSM4T(bv[0], bv[1], bv[2], bv[3], stg + SV + bo);
                MMA_F16(oacc[2*g],   phi, bv[0], bv[1]);
                MMA_F16(oacc[2*g+1], phi, bv[2], bv[3]);
            }
        }

        // ---- stage fully consumed by ALL warps: now prefetch tile kt+2 into it
        __syncthreads();
        if (kt + 2 < nkt) {
            int r = ldr_r0;
#pragma unroll
            for (int it = 0; it < 8; it++, r += 8) {
                size_t grow = (size_t)(b * SEQ + (kt + 2) * 64 + r);
                size_t gk = grow * QW + h * DQK + ldr_c * 8;
                size_t gv = grow * OW + h * DVv + ldr_c * 8;
                uint32_t so = stg + (uint32_t)r * RB + ldr_c * 16;
                CP16(so + SK, khi + gk);
                CP16(so + SV, vhi + gv);
            }
        }
        CP_COMMIT();
        stage ^= 1;
    }

    // ---- epilogue: write fp16 attn directly (A operand of final GEMM)
    const float inv0 = 1.f / l0, inv1 = 1.f / l1;
    const size_t o0 = (size_t)(b * SEQ + row0) * OW + h * DVv;
    const size_t o1 = (size_t)(b * SEQ + row1) * OW + h * DVv;
#pragma unroll
    for (int t = 0; t < 16; t++) {
        const int d0 = 8 * t + 2 * (lane & 3);
        __half2 v0 = __floats2half2_rn(oacc[t][0] * inv0, oacc[t][1] * inv0);
        __half2 v1 = __floats2half2_rn(oacc[t][2] * inv1, oacc[t][3] * inv1);
        *(__half2*)&g_ath[o0 + d0] = v0;
        *(__half2*)&g_ath[o1 + d0] = v1;
    }
}

// ============================================================
// launch
// ============================================================
static inline void convw(const float* in, __half* out, size_t n)
{
    conv_h4_kernel<<<(int)((n / 4 + 255) / 256), 256>>>(
        (const float4*)in, (uint2*)out, (int)(n / 4));
}

extern "C" void kernel_launch(void* const* d_in, const int* in_sizes, int n_in,
                              void* d_out, int out_size)
{
    const float* x      = (const float*)d_in[0];
    const float* wq_a   = (const float*)d_in[1];
    const float* qnw    = (const float*)d_in[2];
    const float* wq_b   = (const float*)d_in[3];
    const float* wkv_a  = (const float*)d_in[4];
    const float* kvnw   = (const float*)d_in[5];
    const float* wkv_b  = (const float*)d_in[6];
    const float* wo     = (const float*)d_in[7];
    const float* fcos   = (const float*)d_in[9];
    const float* fsin   = (const float*)d_in[10];

    float* out = (float*)d_out;

    float *p_qa, *p_q, *p_kv, *p_kv2;
    cudaGetSymbolAddress((void**)&p_qa,   g_qa);
    cudaGetSymbolAddress((void**)&p_q,    g_q);
    cudaGetSymbolAddress((void**)&p_kv,   g_kv);
    cudaGetSymbolAddress((void**)&p_kv2,  g_kv2);

    __half *xh, *wqa, *wqb, *wka, *wkb, *wo16, *qanh, *ckvnh, *ath, *qh, *khi, *vhi;
    cudaGetSymbolAddress((void**)&xh,   g_xh);
    cudaGetSymbolAddress((void**)&wqa,  g_wqa);
    cudaGetSymbolAddress((void**)&wqb,  g_wqb);
    cudaGetSymbolAddress((void**)&wka,  g_wkva);
    cudaGetSymbolAddress((void**)&wkb,  g_wkvb);
    cudaGetSymbolAddress((void**)&wo16, g_wo16);
    cudaGetSymbolAddress((void**)&qanh, g_qanh);
    cudaGetSymbolAddress((void**)&ckvnh,g_ckvnh);
    cudaGetSymbolAddress((void**)&ath,  g_ath);
    cudaGetSymbolAddress((void**)&qh,   g_qh);
    cudaGetSymbolAddress((void**)&khi,  g_khi);
    cudaGetSymbolAddress((void**)&vhi,  g_vhi);

    cudaFuncSetAttribute(gemm_mma,  cudaFuncAttributeMaxDynamicSharedMemorySize, GS_TOTAL);
    cudaFuncSetAttribute(flash_mma, cudaFuncAttributeMaxDynamicSharedMemorySize, F_TOTAL);

    // operand prep (all single fp16)
    convw(x,     xh,   (size_t)ROWS * DIM);
    convw(wq_a,  wqa,  (size_t)QLR * DIM);
    convw(wq_b,  wqb,  (size_t)QW * QLR);
    convw(wkv_a, wka,  (size_t)KVAW * DIM);
    convw(wkv_b, wkb,  (size_t)KV2W * KVLR);
    convw(wo,    wo16, (size_t)DIM * OW);

    // q path
    gemm_mma<<<dim3(QLR / 128, ROWS / 128), 256, GS_TOTAL>>>(xh, wqa, p_qa, QLR, DIM);
    rmsnorm_h_kernel<<<ROWS, 256>>>(p_qa, qnw, qanh, QLR, QLR);
    gemm_mma<<<dim3(QW / 128, ROWS / 128), 256, GS_TOTAL>>>(qanh, wqb, p_q, QW, QLR);
    rope_q_conv_kernel<<<ROWS, 1024>>>(fcos, fsin);

    // kv path
    gemm_mma<<<dim3((KVAW + 127) / 128, ROWS / 128), 256, GS_TOTAL>>>(xh, wka, p_kv, KVAW, DIM);
    rmsnorm_h_kernel<<<ROWS, 256>>>(p_kv, kvnw, ckvnh, KVLR, KVAW);
    gemm_mma<<<dim3(KV2W / 128, ROWS / 128), 256, GS_TOTAL>>>(ckvnh, wkb, p_kv2, KV2W, KVLR);
    build_kv_kernel<<<ROWS, 256>>>(fcos, fsin);

    // attention (tensor-core flash, occ 3)
    flash_mma<<<dim3(SEQ / 64, NH, BSZ), 128, F_TOTAL>>>(qh, khi, vhi);

    // output projection
    gemm_mma<<<dim3(DIM / 128, ROWS / 128), 256, GS_TOTAL>>>(ath, wo16, out, DIM, OW);
}

// round 11
// speedup vs baseline: 6.2195x; 1.0229x over previous
#include <cuda_runtime.h>
#include <cuda_fp16.h>
#include <cstdint>
#include <math.h>

// Problem constants
#define BSZ   2
#define SEQ   2048
#define DIM   2048
#define NH    16
#define DRr   64
#define DNn   64
#define DQK   128
#define DVv   128
#define QLR   1536
#define KVLR  1024
#define ROWS  (BSZ*SEQ)          // 4096
#define KVAW  (KVLR + DRr)       // 1088
#define KV2W  (NH*(DNn+DVv))     // 3072
#define QW    (NH*DQK)           // 2048
#define OW    (NH*DVv)           // 2048

// -------- fp32 scratch --------
__device__ float g_qa  [ (size_t)ROWS * QLR  ];
__device__ float g_kv  [ (size_t)ROWS * KVAW ];

// -------- fp16 operands --------
__device__ __half g_xh   [(size_t)ROWS*DIM];
__device__ __half g_wqa  [(size_t)QLR*DIM];
__device__ __half g_wqb  [(size_t)QW*QLR];
__device__ __half g_wkva [(size_t)KVAW*DIM];
__device__ __half g_wkvb [(size_t)KV2W*KVLR];
__device__ __half g_wo16 [(size_t)DIM*OW];
__device__ __half g_qanh [(size_t)ROWS*QLR];
__device__ __half g_ckvnh[(size_t)ROWS*KVLR];
__device__ __half g_ath  [(size_t)ROWS*OW];
__device__ __half g_qh   [(size_t)ROWS*QW];
__device__ __half g_khi  [(size_t)ROWS*QW];
__device__ __half g_vhi  [(size_t)ROWS*OW];

// ============================================================
// helpers (sm_80-compatible instructions only — plain sm_103 target!)
// ============================================================
__device__ __forceinline__ uint32_t smem_u32(const void* p) {
    uint32_t a;
    asm("{ .reg .u64 t; cvta.to.shared.u64 t, %1; cvt.u32.u64 %0, t; }" : "=r"(a) : "l"(p));
    return a;
}

#define CP16(dst, src) \
    asm volatile("cp.async.cg.shared.global [%0], [%1], 16;" :: "r"(dst), "l"(src))
#define CP_COMMIT() asm volatile("cp.async.commit_group;" ::: "memory")
#define CP_WAIT(n)  asm volatile("cp.async.wait_group %0;" :: "n"(n) : "memory")

#define LDSM4(r0, r1, r2, r3, addr) \
    asm volatile("ldmatrix.sync.aligned.m8n8.x4.shared.b16 {%0,%1,%2,%3}, [%4];" \
        : "=r"(r0), "=r"(r1), "=r"(r2), "=r"(r3) : "r"(addr))

#define LDSM4T(r0, r1, r2, r3, addr) \
    asm volatile("ldmatrix.sync.aligned.m8n8.x4.trans.shared.b16 {%0,%1,%2,%3}, [%4];" \
        : "=r"(r0), "=r"(r1), "=r"(r2), "=r"(r3) : "r"(addr))

#define MMA_F16(d, a, b0, b1) \
    asm volatile("mma.sync.aligned.m16n8k16.row.col.f32.f16.f16.f32 " \
        "{%0,%1,%2,%3},{%4,%5,%6,%7},{%8,%9},{%0,%1,%2,%3};" \
        : "+f"((d)[0]), "+f"((d)[1]), "+f"((d)[2]), "+f"((d)[3]) \
        : "r"((a)[0]), "r"((a)[1]), "r"((a)[2]), "r"((a)[3]), "r"(b0), "r"(b1))

// ============================================================
// elementwise kernels (vectorized: 4 elems/thread)
// ============================================================
__global__ void conv_h4_kernel(const float4* __restrict__ in, uint2* __restrict__ out, int n4)
{
    int i = blockIdx.x * blockDim.x + threadIdx.x;
    if (i < n4) {
        float4 v = in[i];
        __half2 h0 = __floats2half2_rn(v.x, v.y);
        __half2 h1 = __floats2half2_rn(v.z, v.w);
        out[i] = make_uint2(*(uint32_t*)&h0, *(uint32_t*)&h1);
    }
}

// RMSNorm: fp32 in (strided) -> fp16 out, vectorized
__global__ void rmsnorm_h_kernel(const float* __restrict__ in, const float* __restrict__ w,
                                 __half* __restrict__ out, int K, int inStride)
{
    const int row = blockIdx.x;
    const float4* ip4 = (const float4*)(in + (size_t)row * inStride);
    const float4* w4  = (const float4*)w;
    uint2* op4 = (uint2*)(out + (size_t)row * K);
    const int K4 = K >> 2;

    float ss = 0.f;
    for (int i = threadIdx.x; i < K4; i += blockDim.x) {
        float4 v = ip4[i];
        ss += v.x * v.x + v.y * v.y + v.z * v.z + v.w * v.w;
    }
#pragma unroll
    for (int o = 16; o; o >>= 1) ss += __shfl_xor_sync(0xffffffffu, ss, o);

    __shared__ float red[8];
    __shared__ float rs;
    int wid = threadIdx.x >> 5, lid = threadIdx.x & 31;
    if (lid == 0) red[wid] = ss;
    __syncthreads();
    if (threadIdx.x == 0) {
        float t = 0.f;
        for (int i = 0; i < 8; i++) t += red[i];
        rs = rsqrtf(t / (float)K + 1e-6f);
    }
    __syncthreads();
    float r = rs;
    for (int i = threadIdx.x; i < K4; i += blockDim.x) {
        float4 v = ip4[i];
        float4 ww = w4[i];
        __half2 h0 = __floats2half2_rn(v.x * r * ww.x, v.y * r * ww.y);
        __half2 h1 = __floats2half2_rn(v.z * r * ww.z, v.w * r * ww.w);
        op4[i] = make_uint2(*(uint32_t*)&h0, *(uint32_t*)&h1);
    }
}

// Fill rotated k_pe into g_khi cols [h*128+64, h*128+128) for all heads.
__global__ void fill_kpe_kernel(const float* __restrict__ fcos, const float* __restrict__ fsin)
{
    const int row = blockIdx.x;
    const int tid = threadIdx.x;        // 256
    __shared__ float pe[64];
    const int s = row & (SEQ - 1);
    if (tid < 32) {
        float x0 = g_kv[(size_t)row * KVAW + KVLR + 2 * tid];
        float x1 = g_kv[(size_t)row * KVAW + KVLR + 2 * tid + 1];
        float c = fcos[s * 32 + tid], sn = fsin[s * 32 + tid];
        pe[2 * tid]     = x0 * c - x1 * sn;
        pe[2 * tid + 1] = x0 * sn + x1 * c;
    }
    __syncthreads();
#pragma unroll
    for (int l = 0; l < 2; l++) {
        int idx = tid + l * 256;        // 0..511: h = idx>>5, pair = idx&31
        int h = idx >> 5, pr = idx & 31;
        *(__half2*)&g_khi[(size_t)row * QW + h * DQK + DNn + 2 * pr] =
            __floats2half2_rn(pe[2 * pr], pe[2 * pr + 1]);
    }
}

// ============================================================
// single-term fp16 GEMM via mma.sync: C = A[M,K] @ W[N,K]^T
// 128x128x32 tiles, 3-stage cp.async pipeline, 8 warps (4m x 2n), occ 2.
// EPI = 0: fp32 C row-major (bounds-checked)
// EPI = 1: fused RoPE on d>=64 of each 128-head-slice + fp16 -> Hq (N=2048)
// EPI = 2: fused scatter of kv2 cols -> Hk (k_nope) / Hv (v), fp16 (N=3072)
// ============================================================
#define GBM 128
#define GBN 128
#define ROWB 80
#define MAT_BYTES (128 * ROWB)         // 10240
#define OFF_A   0
#define OFF_W   (1 * MAT_BYTES)
#define STAGE_BYTES (2 * MAT_BYTES)    // 20480
#define NSTAGE 3
#define GS_TOTAL (NSTAGE * STAGE_BYTES) // 61440

template<int EPI>
__global__ void __launch_bounds__(256, 2)
gemm_mma(const __half* __restrict__ A, const __half* __restrict__ W,
         float* __restrict__ C, __half* __restrict__ Hq,
         __half* __restrict__ Hk, __half* __restrict__ Hv,
         int N, int K,
         const float* __restrict__ fcos, const float* __restrict__ fsin)
{
    extern __shared__ char smx[];
    const uint32_t sb = smem_u32(smx);
    const int tid  = threadIdx.x;
    const int lane = tid & 31;
    const int warp = tid >> 5;
    const int wm = warp >> 1, wn = warp & 1;
    const int m0 = blockIdx.y * GBM;
    const int n0 = blockIdx.x * GBN;

    const int lrow = tid & 127;
    const int lc   = tid >> 7;
    const size_t a_g = (size_t)(m0 + lrow) * K;
    int wr = n0 + lrow; if (wr >= N) wr = N - 1;
    const size_t w_g = (size_t)wr * K;
    const uint32_t s_row = (uint32_t)lrow * ROWB;

    const uint32_t a_lm = (uint32_t)(wm * 32 + (lane & 15)) * ROWB + (uint32_t)(lane >> 4) * 16;
    const uint32_t b_lm = (uint32_t)(wn * 64 + (lane & 7) + ((lane >> 4) << 3)) * ROWB
                        + (uint32_t)((lane >> 3) & 1) * 16;

    float acc[2][8][4];
#pragma unroll
    for (int i = 0; i < 2; i++)
#pragma unroll
        for (int j = 0; j < 8; j++)
#pragma unroll
            for (int q = 0; q < 4; q++) acc[i][j][q] = 0.f;

    const int nch = K >> 5;

    // prologue: chunks 0,1 into stages 0,1
#pragma unroll
    for (int p = 0; p < NSTAGE - 1; p++) {
        const int k0 = p << 5;
        const uint32_t st = sb + p * STAGE_BYTES + s_row;
#pragma unroll
        for (int u = 0; u < 2; u++) {
            const int cc = lc + u * 2;
            CP16(st + OFF_A + cc * 16, A + a_g + k0 + cc * 8);
            CP16(st + OFF_W + cc * 16, W + w_g + k0 + cc * 8);
        }
        CP_COMMIT();
    }

    int stage = 0;
    for (int c = 0; c < nch; c++) {
        CP_WAIT(NSTAGE - 2);
        __syncthreads();

        if (c + NSTAGE - 1 < nch) {
            const int k0 = (c + NSTAGE - 1) << 5;
            int ws = stage + NSTAGE - 1; if (ws >= NSTAGE) ws -= NSTAGE;
            const uint32_t st = sb + ws * STAGE_BYTES + s_row;
#pragma unroll
            for (int u = 0; u < 2; u++) {
                const int cc = lc + u * 2;
                CP16(st + OFF_A + cc * 16, A + a_g + k0 + cc * 8);
                CP16(st + OFF_W + cc * 16, W + w_g + k0 + cc * 8);
            }
        }
        CP_COMMIT();

        const uint32_t base = sb + stage * STAGE_BYTES;
#pragma unroll
        for (int kk = 0; kk < 2; kk++) {
            uint32_t a[2][4], bh[4][4];
#pragma unroll
            for (int i = 0; i < 2; i++) {
                const uint32_t ao = base + OFF_A + a_lm + i * (16 * ROWB) + kk * 32;
                LDSM4(a[i][0], a[i][1], a[i][2], a[i][3], ao);
            }
#pragma unroll
            for (int g = 0; g < 4; g++) {
                const uint32_t bo = base + OFF_W + b_lm + g * (16 * ROWB) + kk * 32;
                LDSM4(bh[g][0], bh[g][1], bh[g][2], bh[g][3], bo);
            }
#pragma unroll
            for (int i = 0; i < 2; i++) {
#pragma unroll
                for (int j = 0; j < 8; j++) {
                    const int g = j >> 1, h = (j & 1) * 2;
                    MMA_F16(acc[i][j], a[i], bh[g][h], bh[g][h + 1]);
                }
            }
        }
        if (++stage == NSTAGE) stage = 0;
    }

    // ---- epilogue ----
#pragma unroll
    for (int i = 0; i < 2; i++) {
        const int row  = m0 + wm * 32 + i * 16 + (lane >> 2);
        const int row2 = row + 8;
#pragma unroll
        for (int j = 0; j < 8; j++) {
            const int col = n0 + wn * 64 + j * 8 + 2 * (lane & 3);
            float a0 = acc[i][j][0], a1 = acc[i][j][1];
            float b0 = acc[i][j][2], b1 = acc[i][j][3];

            if (EPI == 0) {
                if (col < N) {
                    *(float2*)&C[(size_t)row  * N + col] = make_float2(a0, a1);
                    *(float2*)&C[(size_t)row2 * N + col] = make_float2(b0, b1);
                }
            } else if (EPI == 1) {
                const int d = col & 127;
                if (d >= DNn) {
                    const int ir = (d - DNn) >> 1;
                    const int s0 = row & (SEQ - 1), s1 = row2 & (SEQ - 1);
                    float c0 = fcos[s0 * 32 + ir], sn0 = fsin[s0 * 32 + ir];
                    float c1 = fcos[s1 * 32 + ir], sn1 = fsin[s1 * 32 + ir];
                    float t0 = a0 * c0 - a1 * sn0, t1 = a0 * sn0 + a1 * c0;
                    a0 = t0; a1 = t1;
                    t0 = b0 * c1 - b1 * sn1; t1 = b0 * sn1 + b1 * c1;
                    b0 = t0; b1 = t1;
                }
                *(__half2*)&Hq[(size_t)row  * QW + col] = __floats2half2_rn(a0, a1);
                *(__half2*)&Hq[(size_t)row2 * QW + col] = __floats2half2_rn(b0, b1);
            } else {
                const int h = col / (DNn + DVv);
                const int d = col - h * (DNn + DVv);
                if (d < DNn) {
                    const size_t off = (size_t)h * DQK + d;
                    *(__half2*)&Hk[(size_t)row  * QW + off] = __floats2half2_rn(a0, a1);
                    *(__half2*)&Hk[(size_t)row2 * QW + off] = __floats2half2_rn(b0, b1);
                } else {
                    const size_t off = (size_t)h * DVv + (d - DNn);
                    *(__half2*)&Hv[(size_t)row  * OW + off] = __floats2half2_rn(a0, a1);
                    *(__half2*)&Hv[(size_t)row2 * OW + off] = __floats2half2_rn(b0, b1);
                }
            }
        }
    }
}

// ============================================================
// Flash attention — FA2-style, fp16 mma.sync, occupancy 3
// BQ=64, BK=64, 4 warps (each owns 16 rows), block 128.
// Q fragments in registers; K + V in 2-stage cp.async ring; prefetch of
// tile kt+2 into the CURRENT stage strictly after the post-compute sync.
// grid: (SEQ/64, NH, BSZ)
// ============================================================
#define RB 272
#define SK    0
#define SV    17408
#define FSTG  34816                   // per stage: K + V
#define F_TOTAL (2 * FSTG)            // 69632

__global__ void __launch_bounds__(128, 3)
flash_mma(const __half* __restrict__ q16,
          const __half* __restrict__ khi, const __half* __restrict__ vhi)
{
    extern __shared__ char smx[];
    const uint32_t sb = smem_u32(smx);
    const int tid = threadIdx.x, lane = tid & 31, wid = tid >> 5;   // 4 warps
    const int q0 = blockIdx.x * 64;
    const int h  = blockIdx.y;
    const int b  = blockIdx.z;
    const float scale = 0.088388347648318447f;  // 128^-0.5

    const uint32_t a_off  = (uint32_t)(wid * 16 + (lane & 15)) * RB + (uint32_t)(lane >> 4) * 16;
    const uint32_t bK_off = (uint32_t)((lane & 7) + ((lane >> 4) << 3)) * RB
                          + (uint32_t)((lane >> 3) & 1) * 16;
    const uint32_t bV_off = (uint32_t)((lane & 7) + (((lane >> 3) & 1) << 3)) * RB
                          + (uint32_t)(lane >> 4) * 16;

    // ---- stage Q tile (64 x 128) through smem stage-0, hoist fragments
    {
        int r = tid >> 4;
        const int cc = tid & 15;
#pragma unroll
        for (int it = 0; it < 8; it++, r += 8) {
            size_t go = (size_t)(b * SEQ + q0 + r) * QW + h * DQK + cc * 8;
            *(uint4*)(smx + (uint32_t)r * RB + cc * 16) = *(const uint4*)(q16 + go);
        }
    }
    __syncthreads();
    uint32_t aq[8][4];
#pragma unroll
    for (int kk = 0; kk < 8; kk++)
        LDSM4(aq[kk][0], aq[kk][1], aq[kk][2], aq[kk][3], sb + a_off + kk * 32);
    __syncthreads();

    float oacc[16][4];
#pragma unroll
    for (int t = 0; t < 16; t++)
#pragma unroll
        for (int qq = 0; qq < 4; qq++) oacc[t][qq] = 0.f;
    float m0 = -1e30f, m1 = -1e30f, l0 = 0.f, l1 = 0.f;

    const int row0 = q0 + wid * 16 + (lane >> 2);
    const int row1 = row0 + 8;

    const int nkt = blockIdx.x + 1;
    const int ldr_r0 = tid >> 4;        // 8 rows per pass, 8 passes
    const int ldr_c  = tid & 15;

    // prologue: tiles 0,1 into stages 0,1 (empty commit when nkt==1)
#pragma unroll
    for (int p = 0; p < 2; p++) {
        if (p < nkt) {
            const uint32_t stg = sb + p * FSTG;
            int r = ldr_r0;
#pragma unroll
            for (int it = 0; it < 8; it++, r += 8) {
                size_t grow = (size_t)(b * SEQ + p * 64 + r);
                size_t gk = grow * QW + h * DQK + ldr_c * 8;
                size_t gv = grow * OW + h * DVv + ldr_c * 8;
                uint32_t so = (uint32_t)r * RB + ldr_c * 16;
                CP16(stg + SK + so, khi + gk);
                CP16(stg + SV + so, vhi + gv);
            }
        }
        CP_COMMIT();
    }

    int stage = 0;
    for (int kt = 0; kt < nkt; kt++) {
        const int t0 = kt * 64;
        CP_WAIT(1);                    // tile kt resident
        __syncthreads();               // make it visible to all warps

        const uint32_t stg = sb + stage * FSTG;

        // ---- S = Q @ K^T  (warp tile 16 x 64)
        float sacc[8][4];
#pragma unroll
        for (int t = 0; t < 8; t++)
#pragma unroll
            for (int qq = 0; qq < 4; qq++) sacc[t][qq] = 0.f;

#pragma unroll
        for (int kk = 0; kk < 8; kk++) {
#pragma unroll
            for (int g = 0; g < 4; g++) {
                uint32_t bh[4];
                const uint32_t bo = bK_off + g * (16 * RB) + kk * 32;
                LDSM4(bh[0], bh[1], bh[2], bh[3], stg + SK + bo);
                MMA_F16(sacc[2*g],   aq[kk], bh[0], bh[1]);
                MMA_F16(sacc[2*g+1], aq[kk], bh[2], bh[3]);
            }
        }

        // ---- scale + causal mask
        const int cb = t0 + 2 * (lane & 3);
#pragma unroll
        for (int t = 0; t < 8; t++) {
            const int c0 = cb + 8 * t, c1 = c0 + 1;
            sacc[t][0] = sacc[t][0] * scale + ((c0 > row0) ? -1e9f : 0.f);
            sacc[t][1] = sacc[t][1] * scale + ((c1 > row0) ? -1e9f : 0.f);
            sacc[t][2] = sacc[t][2] * scale + ((c0 > row1) ? -1e9f : 0.f);
            sacc[t][3] = sacc[t][3] * scale + ((c1 > row1) ? -1e9f : 0.f);
        }

        // ---- online softmax
        float mx0 = -1e30f, mx1 = -1e30f;
#pragma unroll
        for (int t = 0; t < 8; t++) {
            mx0 = fmaxf(mx0, fmaxf(sacc[t][0], sacc[t][1]));
            mx1 = fmaxf(mx1, fmaxf(sacc[t][2], sacc[t][3]));
        }
        mx0 = fmaxf(mx0, __shfl_xor_sync(0xffffffffu, mx0, 1));
        mx0 = fmaxf(mx0, __shfl_xor_sync(0xffffffffu, mx0, 2));
        mx1 = fmaxf(mx1, __shfl_xor_sync(0xffffffffu, mx1, 1));
        mx1 = fmaxf(mx1, __shfl_xor_sync(0xffffffffu, mx1, 2));

        const float mn0 = fmaxf(m0, mx0), mn1 = fmaxf(m1, mx1);
        const float al0 = __expf(m0 - mn0), al1 = __expf(m1 - mn1);
        m0 = mn0; m1 = mn1;

        float ps0 = 0.f, ps1 = 0.f;
#pragma unroll
        for (int t = 0; t < 8; t++) {
            sacc[t][0] = __expf(sacc[t][0] - mn0);
            sacc[t][1] = __expf(sacc[t][1] - mn0);
            sacc[t][2] = __expf(sacc[t][2] - mn1);
            sacc[t][3] = __expf(sacc[t][3] - mn1);
            ps0 += sacc[t][0] + sacc[t][1];
            ps1 += sacc[t][2] + sacc[t][3];
        }
        ps0 += __shfl_xor_sync(0xffffffffu, ps0, 1);
        ps0 += __shfl_xor_sync(0xffffffffu, ps0, 2);
        ps1 += __shfl_xor_sync(0xffffffffu, ps1, 1);
        ps1 += __shfl_xor_sync(0xffffffffu, ps1, 2);
        l0 = l0 * al0 + ps0;
        l1 = l1 * al1 + ps1;

#pragma unroll
        for (int t = 0; t < 16; t++) {
            oacc[t][0] *= al0; oacc[t][1] *= al0;
            oacc[t][2] *= al1; oacc[t][3] *= al1;
        }

        // ---- O += P @ V
#pragma unroll
        for (int jj = 0; jj < 4; jj++) {
            const int t2 = 2 * jj, t3 = 2 * jj + 1;
            uint32_t phi[4];
            {
                __half2 h0 = __floats2half2_rn(sacc[t2][0], sacc[t2][1]);
                __half2 h1 = __floats2half2_rn(sacc[t2][2], sacc[t2][3]);
                __half2 h2 = __floats2half2_rn(sacc[t3][0], sacc[t3][1]);
                __half2 h3 = __floats2half2_rn(sacc[t3][2], sacc[t3][3]);
                phi[0] = *(uint32_t*)&h0; phi[1] = *(uint32_t*)&h1;
                phi[2] = *(uint32_t*)&h2; phi[3] = *(uint32_t*)&h3;
            }
#pragma unroll
            for (int g = 0; g < 8; g++) {
                uint32_t bv[4];
                const uint32_t bo = bV_off + jj * (16 * RB) + g * 32;
                LDSM4T(bv[0], bv[1], bv[2], bv[3], stg + SV + bo);
                MMA_F16(oacc[2*g],   phi, bv[0], bv[1]);
                MMA_F16(oacc[2*g+1], phi, bv[2], bv[3]);
            }
        }

        // ---- stage fully consumed by ALL warps: now prefetch tile kt+2 into it
        __syncthreads();
        if (kt + 2 < nkt) {
            int r = ldr_r0;
#pragma unroll
            for (int it = 0; it < 8; it++, r += 8) {
                size_t grow = (size_t)(b * SEQ + (kt + 2) * 64 + r);
                size_t gk = grow * QW + h * DQK + ldr_c * 8;
                size_t gv = grow * OW + h * DVv + ldr_c * 8;
                uint32_t so = stg + (uint32_t)r * RB + ldr_c * 16;
                CP16(so + SK, khi + gk);
                CP16(so + SV, vhi + gv);
            }
        }
        CP_COMMIT();
        stage ^= 1;
    }

    // ---- epilogue: write fp16 attn directly (A operand of final GEMM)
    const float inv0 = 1.f / l0, inv1 = 1.f / l1;
    const size_t o0 = (size_t)(b * SEQ + row0) * OW + h * DVv;
    const size_t o1 = (size_t)(b * SEQ + row1) * OW + h * DVv;
#pragma unroll
    for (int t = 0; t < 16; t++) {
        const int d0 = 8 * t + 2 * (lane & 3);
        __half2 v0 = __floats2half2_rn(oacc[t][0] * inv0, oacc[t][1] * inv0);
        __half2 v1 = __floats2half2_rn(oacc[t][2] * inv1, oacc[t][3] * inv1);
        *(__half2*)&g_ath[o0 + d0] = v0;
        *(__half2*)&g_ath[o1 + d0] = v1;
    }
}

// ============================================================
// launch
// ============================================================
static inline void convw(const float* in, __half* out, size_t n)
{
    conv_h4_kernel<<<(int)((n / 4 + 255) / 256), 256>>>(
        (const float4*)in, (uint2*)out, (int)(n / 4));
}

extern "C" void kernel_launch(void* const* d_in, const int* in_sizes, int n_in,
                              void* d_out, int out_size)
{
    const float* x      = (const float*)d_in[0];
    const float* wq_a   = (const float*)d_in[1];
    const float* qnw    = (const float*)d_in[2];
    const float* wq_b   = (const float*)d_in[3];
    const float* wkv_a  = (const float*)d_in[4];
    const float* kvnw   = (const float*)d_in[5];
    const float* wkv_b  = (const float*)d_in[6];
    const float* wo     = (const float*)d_in[7];
    const float* fcos   = (const float*)d_in[9];
    const float* fsin   = (const float*)d_in[10];

    float* out = (float*)d_out;

    float *p_qa, *p_kv;
    cudaGetSymbolAddress((void**)&p_qa,   g_qa);
    cudaGetSymbolAddress((void**)&p_kv,   g_kv);

    __half *xh, *wqa, *wqb, *wka, *wkb, *wo16, *qanh, *ckvnh, *ath, *qh, *khi, *vhi;
    cudaGetSymbolAddress((void**)&xh,   g_xh);
    cudaGetSymbolAddress((void**)&wqa,  g_wqa);
    cudaGetSymbolAddress((void**)&wqb,  g_wqb);
    cudaGetSymbolAddress((void**)&wka,  g_wkva);
    cudaGetSymbolAddress((void**)&wkb,  g_wkvb);
    cudaGetSymbolAddress((void**)&wo16, g_wo16);
    cudaGetSymbolAddress((void**)&qanh, g_qanh);
    cudaGetSymbolAddress((void**)&ckvnh,g_ckvnh);
    cudaGetSymbolAddress((void**)&ath,  g_ath);
    cudaGetSymbolAddress((void**)&qh,   g_qh);
    cudaGetSymbolAddress((void**)&khi,  g_khi);
    cudaGetSymbolAddress((void**)&vhi,  g_vhi);

    cudaFuncSetAttribute(gemm_mma<0>, cudaFuncAttributeMaxDynamicSharedMemorySize, GS_TOTAL);
    cudaFuncSetAttribute(gemm_mma<1>, cudaFuncAttributeMaxDynamicSharedMemorySize, GS_TOTAL);
    cudaFuncSetAttribute(gemm_mma<2>, cudaFuncAttributeMaxDynamicSharedMemorySize, GS_TOTAL);
    cudaFuncSetAttribute(flash_mma,   cudaFuncAttributeMaxDynamicSharedMemorySize, F_TOTAL);

    // operand prep (all single fp16)
    convw(x,     xh,   (size_t)ROWS * DIM);
    convw(wq_a,  wqa,  (size_t)QLR * DIM);
    convw(wq_b,  wqb,  (size_t)QW * QLR);
    convw(wkv_a, wka,  (size_t)KVAW * DIM);
    convw(wkv_b, wkb,  (size_t)KV2W * KVLR);
    convw(wo,    wo16, (size_t)DIM * OW);

    // q path
    gemm_mma<0><<<dim3(QLR / 128, ROWS / 128), 256, GS_TOTAL>>>(
        xh, wqa, p_qa, nullptr, nullptr, nullptr, QLR, DIM, fcos, fsin);
    rmsnorm_h_kernel<<<ROWS, 256>>>(p_qa, qnw, qanh, QLR, QLR);
    gemm_mma<1><<<dim3(QW / 128, ROWS / 128), 256, GS_TOTAL>>>(
        qanh, wqb, nullptr, qh, nullptr, nullptr, QW, QLR, fcos, fsin);

    // kv path
    gemm_mma<0><<<dim3((KVAW + 127) / 128, ROWS / 128), 256, GS_TOTAL>>>(
        xh, wka, p_kv, nullptr, nullptr, nullptr, KVAW, DIM, fcos, fsin);
    rmsnorm_h_kernel<<<ROWS, 256>>>(p_kv, kvnw, ckvnh, KVLR, KVAW);
    gemm_mma<2><<<dim3(KV2W / 128, ROWS / 128), 256, GS_TOTAL>>>(
        ckvnh, wkb, nullptr, nullptr, khi, vhi, KV2W, KVLR, fcos, fsin);
    fill_kpe_kernel<<<ROWS, 256>>>(fcos, fsin);

    // attention (tensor-core flash, occ 3)
    flash_mma<<<dim3(SEQ / 64, NH, BSZ), 128, F_TOTAL>>>(qh, khi, vhi);

    // output projection
    gemm_mma<0><<<dim3(DIM / 128, ROWS / 128), 256, GS_TOTAL>>>(
        ath, wo16, out, nullptr, nullptr, nullptr, DIM, OW, fcos, fsin);
}